// round 5
// baseline (speedup 1.0000x reference)
#include <cuda_runtime.h>
#include <cuda_bf16.h>
#include <stdint.h>
#include <math.h>

#define SLEN 1024
#define DDIM 2048
#define ENUM 8
#define HNUM 6
#define DKC  256
#define DVC  512
#define KDIM 1536   // HNUM*DKC
#define VDIM 3072   // HNUM*DVC
#define QKVN 6144   // KDIM+KDIM+VDIM fused
#define CAP  1024
#define NROW (ENUM*CAP)

// ---------------- scratch (device globals; no allocation in kernel_launch) ----
__device__ int   d_sel[SLEN*2];
__device__ float d_rw [SLEN*2];
__device__ int   d_m  [ENUM];
__device__ int   d_tok[NROW];
__device__ int   d_pos[SLEN*2];
__device__ float d_xg  [NROW*DDIM];
__device__ float d_qkvpre[(size_t)NROW*QKVN];
__device__ float d_qn  [NROW*KDIM];
__device__ float d_kn  [NROW*KDIM];
__device__ float d_vn  [NROW*VDIM];
__device__ float d_beta[NROW*HNUM];
__device__ float d_g   [NROW*HNUM];
__device__ float d_o   [NROW*VDIM];
__device__ float d_gg  [SLEN*VDIM];
__device__ float d_pre [SLEN*VDIM];

// bf16 hi/lo split buffers
__device__ __align__(256) __nv_bfloat16 d_xg_hi[NROW*DDIM];
__device__ __align__(256) __nv_bfloat16 d_xg_lo[NROW*DDIM];
__device__ __align__(256) __nv_bfloat16 d_qkvw_hi[(size_t)ENUM*DDIM*QKVN];
__device__ __align__(256) __nv_bfloat16 d_qkvw_lo[(size_t)ENUM*DDIM*QKVN];
__device__ __align__(256) __nv_bfloat16 d_gw_hi[DDIM*VDIM];
__device__ __align__(256) __nv_bfloat16 d_gw_lo[DDIM*VDIM];
__device__ __align__(256) __nv_bfloat16 d_ow_hi[VDIM*DDIM];
__device__ __align__(256) __nv_bfloat16 d_ow_lo[VDIM*DDIM];
__device__ __align__(256) __nv_bfloat16 d_hid_hi[SLEN*DDIM];
__device__ __align__(256) __nv_bfloat16 d_hid_lo[SLEN*DDIM];
__device__ __align__(256) __nv_bfloat16 d_pre_hi[SLEN*VDIM];
__device__ __align__(256) __nv_bfloat16 d_pre_lo[SLEN*VDIM];

// ---------------- PTX helpers -------------------------------------------------
__device__ __forceinline__ void cpa16(uint32_t d, const void* s) {
    asm volatile("cp.async.cg.shared.global [%0], [%1], 16;" :: "r"(d), "l"(s));
}
__device__ __forceinline__ void ldm_x4(uint32_t* r, uint32_t a) {
    asm volatile("ldmatrix.sync.aligned.m8n8.x4.shared.b16 {%0,%1,%2,%3}, [%4];"
                 : "=r"(r[0]), "=r"(r[1]), "=r"(r[2]), "=r"(r[3]) : "r"(a));
}
__device__ __forceinline__ void ldm_x4t(uint32_t* r, uint32_t a) {
    asm volatile("ldmatrix.sync.aligned.m8n8.x4.trans.shared.b16 {%0,%1,%2,%3}, [%4];"
                 : "=r"(r[0]), "=r"(r[1]), "=r"(r[2]), "=r"(r[3]) : "r"(a));
}
__device__ __forceinline__ void mma_bf16(float* c, const uint32_t* a, const uint32_t* b) {
    asm volatile(
        "mma.sync.aligned.m16n8k16.row.col.f32.bf16.bf16.f32 "
        "{%0,%1,%2,%3},{%4,%5,%6,%7},{%8,%9},{%0,%1,%2,%3};"
        : "+f"(c[0]), "+f"(c[1]), "+f"(c[2]), "+f"(c[3])
        : "r"(a[0]), "r"(a[1]), "r"(a[2]), "r"(a[3]), "r"(b[0]), "r"(b[1]));
}
// packed f32x2 FMA (B300)
__device__ __forceinline__ unsigned long long pk2(float x, float y) {
    unsigned long long r;
    asm("mov.b64 %0, {%1, %2};" : "=l"(r) : "f"(x), "f"(y));
    return r;
}
__device__ __forceinline__ unsigned long long fma2(unsigned long long a,
                                                   unsigned long long b,
                                                   unsigned long long c) {
    unsigned long long d;
    asm("fma.rn.f32x2 %0, %1, %2, %3;" : "=l"(d) : "l"(a), "l"(b), "l"(c));
    return d;
}
__device__ __forceinline__ float2 upk2(unsigned long long u) {
    float2 f;
    asm("mov.b64 {%0, %1}, %2;" : "=f"(f.x), "=f"(f.y) : "l"(u));
    return f;
}

// ---------------- hi/lo split conversion --------------------------------------
__device__ __forceinline__ void split4(float4 v, __nv_bfloat162* hi, __nv_bfloat162* lo) {
    __nv_bfloat16 h0 = __float2bfloat16(v.x), h1 = __float2bfloat16(v.y);
    __nv_bfloat16 h2 = __float2bfloat16(v.z), h3 = __float2bfloat16(v.w);
    __nv_bfloat16 l0 = __float2bfloat16(v.x - __bfloat162float(h0));
    __nv_bfloat16 l1 = __float2bfloat16(v.y - __bfloat162float(h1));
    __nv_bfloat16 l2 = __float2bfloat16(v.z - __bfloat162float(h2));
    __nv_bfloat16 l3 = __float2bfloat16(v.w - __bfloat162float(h3));
    hi[0] = __halves2bfloat162(h0, h1);
    hi[1] = __halves2bfloat162(h2, h3);
    lo[0] = __halves2bfloat162(l0, l1);
    lo[1] = __halves2bfloat162(l2, l3);
}

__global__ void split_kernel(const float4* __restrict__ x, __nv_bfloat162* __restrict__ hi,
                             __nv_bfloat162* __restrict__ lo, int n4) {
    int i = blockIdx.x * 256 + threadIdx.x;
    if (i >= n4) return;
    __nv_bfloat162 h[2], l[2];
    split4(x[i], h, l);
    hi[2 * i] = h[0]; hi[2 * i + 1] = h[1];
    lo[2 * i] = l[0]; lo[2 * i + 1] = l[1];
}

// -------------- one mega-pack: qkv fused weights + gate/out/hidden splits ----
#define QKV_U (ENUM*DDIM*(QKVN/4))
#define GW_U  (DDIM*VDIM/4)
#define OW_U  (VDIM*DDIM/4)
#define HID_U (SLEN*DDIM/4)
#define TOT_U (QKV_U + GW_U + OW_U + HID_U)

__global__ void pack_w_kernel(const float* __restrict__ q_w, const float* __restrict__ k_w,
                              const float* __restrict__ v_w, const float* __restrict__ g_w,
                              const float* __restrict__ o_w, const float* __restrict__ hidden) {
    long long u = (long long)blockIdx.x * 256 + threadIdx.x;
    if (u >= TOT_U) return;
    if (u < QKV_U) {
        long long per_e = (long long)DDIM * (QKVN / 4);
        int e = (int)(u / per_e);
        long long r = u - (long long)e * per_e;
        int d = (int)(r / (QKVN / 4));
        int c4 = (int)(r - (long long)d * (QKVN / 4));
        int n = c4 * 4;
        float4 src;
        if (n < KDIM) {
            src = *(const float4*)(q_w + (size_t)d * KDIM + n);
        } else if (n < 2 * KDIM) {
            src = *(const float4*)(k_w + ((size_t)e * DDIM + d) * KDIM + (n - KDIM));
        } else {
            src = *(const float4*)(v_w + ((size_t)e * DDIM + d) * VDIM + (n - 2 * KDIM));
        }
        size_t dst = ((size_t)e * DDIM + d) * QKVN + n;
        __nv_bfloat162 h[2], l[2];
        split4(src, h, l);
        __nv_bfloat162* hp = (__nv_bfloat162*)(d_qkvw_hi + dst);
        __nv_bfloat162* lp = (__nv_bfloat162*)(d_qkvw_lo + dst);
        hp[0] = h[0]; hp[1] = h[1]; lp[0] = l[0]; lp[1] = l[1];
        return;
    }
    u -= QKV_U;
    if (u < GW_U) {
        float4 src = ((const float4*)g_w)[u];
        __nv_bfloat162 h[2], l[2]; split4(src, h, l);
        ((__nv_bfloat162*)d_gw_hi)[2 * u] = h[0]; ((__nv_bfloat162*)d_gw_hi)[2 * u + 1] = h[1];
        ((__nv_bfloat162*)d_gw_lo)[2 * u] = l[0]; ((__nv_bfloat162*)d_gw_lo)[2 * u + 1] = l[1];
        return;
    }
    u -= GW_U;
    if (u < OW_U) {
        float4 src = ((const float4*)o_w)[u];
        __nv_bfloat162 h[2], l[2]; split4(src, h, l);
        ((__nv_bfloat162*)d_ow_hi)[2 * u] = h[0]; ((__nv_bfloat162*)d_ow_hi)[2 * u + 1] = h[1];
        ((__nv_bfloat162*)d_ow_lo)[2 * u] = l[0]; ((__nv_bfloat162*)d_ow_lo)[2 * u + 1] = l[1];
        return;
    }
    u -= OW_U;
    {
        float4 src = ((const float4*)hidden)[u];
        __nv_bfloat162 h[2], l[2]; split4(src, h, l);
        ((__nv_bfloat162*)d_hid_hi)[2 * u] = h[0]; ((__nv_bfloat162*)d_hid_hi)[2 * u + 1] = h[1];
        ((__nv_bfloat162*)d_hid_lo)[2 * u] = l[0]; ((__nv_bfloat162*)d_hid_lo)[2 * u + 1] = l[1];
    }
}

// ---------------- tensor-core split-bf16 GEMM ---------------------------------
#define LDA 40
#define LDB 136
#define A_SZ (128*LDA)
#define B_SZ (32*LDB)
#define STAGE_H (2*A_SZ + 2*B_SZ)
#define GEMM_SMEM (STAGE_H*2*2)

__global__ __launch_bounds__(256, 2)
void gemm_tc(const __nv_bfloat16* __restrict__ Ahi, const __nv_bfloat16* __restrict__ Alo,
             const __nv_bfloat16* __restrict__ Bhi, const __nv_bfloat16* __restrict__ Blo,
             float* __restrict__ C, int M, int N, int K,
             long long aStride, long long bStride, long long cStride, int useM) {
    extern __shared__ __nv_bfloat16 smbuf[];
    int z = blockIdx.z;
    int mlim = useM ? d_m[z] : M;
    int row0 = blockIdx.y * 128;
    if (row0 >= mlim) return;
    int col0 = blockIdx.x * 128;
    Ahi += (size_t)z * aStride; Alo += (size_t)z * aStride;
    Bhi += (size_t)z * bStride; Blo += (size_t)z * bStride;
    C += (size_t)z * cStride;

    uint32_t sbase = (uint32_t)__cvta_generic_to_shared(smbuf);
    int t = threadIdx.x;

    int arow = t >> 1, akc = (t & 1) * 16;
    int brow = t >> 3, bnc = (t & 7) * 16;
    const __nv_bfloat16* gAh = Ahi + (size_t)(row0 + arow) * K + akc;
    const __nv_bfloat16* gAl = Alo + (size_t)(row0 + arow) * K + akc;
    const __nv_bfloat16* gBh = Bhi + (size_t)brow * N + col0 + bnc;
    const __nv_bfloat16* gBl = Blo + (size_t)brow * N + col0 + bnc;
    uint32_t dAh = sbase + (uint32_t)(arow * LDA + akc) * 2;
    uint32_t dAl = dAh + A_SZ * 2;
    uint32_t dBh = sbase + (uint32_t)(2 * A_SZ + brow * LDB + bnc) * 2;
    uint32_t dBl = dBh + B_SZ * 2;

    int lane = t & 31, wid = t >> 5;
    int wm = (wid >> 2) * 64, wn = (wid & 3) * 32;
    int aR = lane & 15, aC = (lane >> 4) * 8;
    uint32_t aOff = (uint32_t)((wm + aR) * LDA + aC) * 2;
    int bgp = lane >> 3, blr = lane & 7;
    int bR = blr + (bgp & 1) * 8, bC = (bgp >> 1) * 8;
    uint32_t bOff = (uint32_t)(bR * LDB + wn + bC) * 2;

    float acc[4][4][4];
#pragma unroll
    for (int mi = 0; mi < 4; mi++)
#pragma unroll
        for (int ni = 0; ni < 4; ni++)
#pragma unroll
            for (int j = 0; j < 4; j++) acc[mi][ni][j] = 0.f;

    int KT = K / 32;

    cpa16(dAh, gAh);           cpa16(dAh + 16, gAh + 8);
    cpa16(dAl, gAl);           cpa16(dAl + 16, gAl + 8);
    cpa16(dBh, gBh);           cpa16(dBh + 16, gBh + 8);
    cpa16(dBl, gBl);           cpa16(dBl + 16, gBl + 8);
    asm volatile("cp.async.commit_group;");

    for (int kt = 0; kt < KT; kt++) {
        if (kt + 1 < KT) {
            int k0 = (kt + 1) * 32;
            uint32_t so = (uint32_t)(((kt + 1) & 1) * STAGE_H) * 2;
            const __nv_bfloat16* a0 = gAh + k0;
            const __nv_bfloat16* a1 = gAl + k0;
            const __nv_bfloat16* b0 = gBh + (size_t)k0 * N;
            const __nv_bfloat16* b1 = gBl + (size_t)k0 * N;
            cpa16(dAh + so, a0);        cpa16(dAh + so + 16, a0 + 8);
            cpa16(dAl + so, a1);        cpa16(dAl + so + 16, a1 + 8);
            cpa16(dBh + so, b0);        cpa16(dBh + so + 16, b0 + 8);
            cpa16(dBl + so, b1);        cpa16(dBl + so + 16, b1 + 8);
            asm volatile("cp.async.commit_group;");
            asm volatile("cp.async.wait_group 1;");
        } else {
            asm volatile("cp.async.wait_group 0;");
        }
        __syncthreads();

        uint32_t s0 = sbase + (uint32_t)((kt & 1) * STAGE_H) * 2;
        uint32_t sAh = s0 + aOff;
        uint32_t sAl = sAh + (uint32_t)A_SZ * 2;
        uint32_t sBh = s0 + (uint32_t)(2 * A_SZ) * 2 + bOff;
        uint32_t sBl = sBh + (uint32_t)B_SZ * 2;

#pragma unroll
        for (int ks = 0; ks < 2; ks++) {
            uint32_t kao = (uint32_t)(ks * 16) * 2;
            uint32_t kbo = (uint32_t)(ks * 16 * LDB) * 2;
            uint32_t bh[8], bl2[8], af[16];
            ldm_x4t(bh + 0, sBh + kbo);
            ldm_x4t(bh + 4, sBh + kbo + 32);
            ldm_x4t(bl2 + 0, sBl + kbo);
            ldm_x4t(bl2 + 4, sBl + kbo + 32);
#pragma unroll
            for (int mi = 0; mi < 4; mi++)
                ldm_x4(af + mi * 4, sAh + kao + (uint32_t)(mi * 16 * LDA) * 2);
#pragma unroll
            for (int mi = 0; mi < 4; mi++)
#pragma unroll
                for (int ni = 0; ni < 4; ni++)
                    mma_bf16(acc[mi][ni], af + mi * 4, bh + (ni >> 1) * 4 + (ni & 1) * 2);
#pragma unroll
            for (int mi = 0; mi < 4; mi++)
#pragma unroll
                for (int ni = 0; ni < 4; ni++)
                    mma_bf16(acc[mi][ni], af + mi * 4, bl2 + (ni >> 1) * 4 + (ni & 1) * 2);
#pragma unroll
            for (int mi = 0; mi < 4; mi++)
                ldm_x4(af + mi * 4, sAl + kao + (uint32_t)(mi * 16 * LDA) * 2);
#pragma unroll
            for (int mi = 0; mi < 4; mi++)
#pragma unroll
                for (int ni = 0; ni < 4; ni++)
                    mma_bf16(acc[mi][ni], af + mi * 4, bh + (ni >> 1) * 4 + (ni & 1) * 2);
        }
        __syncthreads();
    }

    int gr = lane >> 2, gc = (lane & 3) * 2;
#pragma unroll
    for (int mi = 0; mi < 4; mi++) {
        int r = row0 + wm + mi * 16 + gr;
#pragma unroll
        for (int ni = 0; ni < 4; ni++) {
            float* Cp = C + (size_t)r * N + col0 + wn + ni * 8 + gc;
            if (r < mlim) {
                Cp[0] = acc[mi][ni][0];
                Cp[1] = acc[mi][ni][1];
            }
            if (r + 8 < mlim) {
                float* Cq = Cp + (size_t)8 * N;
                Cq[0] = acc[mi][ni][2];
                Cq[1] = acc[mi][ni][3];
            }
        }
    }
}

// ---------------- router ------------------------------------------------------
__global__ void router_kernel(const float* __restrict__ hidden,
                              const float* __restrict__ gate_w) {
    int s = blockIdx.x;
    int tid = threadIdx.x;
    float acc[ENUM];
#pragma unroll
    for (int e = 0; e < ENUM; e++) acc[e] = 0.f;
    const float* xr = hidden + (size_t)s * DDIM;
    for (int d = tid; d < DDIM; d += 256) {
        float x = xr[d];
        const float* w = gate_w + (size_t)d * ENUM;
#pragma unroll
        for (int e = 0; e < ENUM; e++) acc[e] += x * w[e];
    }
    __shared__ float red[ENUM][256];
#pragma unroll
    for (int e = 0; e < ENUM; e++) red[e][tid] = acc[e];
    __syncthreads();
    for (int st = 128; st > 0; st >>= 1) {
        if (tid < st) {
#pragma unroll
            for (int e = 0; e < ENUM; e++) red[e][tid] += red[e][tid + st];
        }
        __syncthreads();
    }
    if (tid == 0) {
        float l[ENUM], mx = -1e30f;
#pragma unroll
        for (int e = 0; e < ENUM; e++) { l[e] = red[e][0]; mx = fmaxf(mx, l[e]); }
        float p[ENUM], sum = 0.f;
#pragma unroll
        for (int e = 0; e < ENUM; e++) { p[e] = expf(l[e] - mx); sum += p[e]; }
#pragma unroll
        for (int e = 0; e < ENUM; e++) p[e] /= sum;
        int i0 = 0;
#pragma unroll
        for (int e = 1; e < ENUM; e++) if (p[e] > p[i0]) i0 = e;
        int i1 = -1;
#pragma unroll
        for (int e = 0; e < ENUM; e++)
            if (e != i0 && (i1 < 0 || p[e] > p[i1])) i1 = e;
        float r0 = p[i0], r1 = p[i1], rs = r0 + r1;
        d_sel[2 * s] = i0;  d_sel[2 * s + 1] = i1;
        d_rw[2 * s] = r0 / rs;  d_rw[2 * s + 1] = r1 / rs;
    }
}

// -------------- dispatch ------------------------------------------------------
__global__ void dispatch_kernel() {
    int e = threadIdx.x;
    if (e >= ENUM) return;
    int c = 0;
    for (int i = 0; i < SLEN * 2; i++) c += (d_sel[i] == e);
    int drop = c > CAP ? c - CAP : 0;
    d_m[e] = c - drop;
    int r = 0;
    for (int i = 0; i < SLEN * 2; i++) {
        if (d_sel[i] == e) {
            if (r >= drop) {
                int j = r - drop;
                d_tok[e * CAP + j] = i >> 1;
                d_pos[i] = e * CAP + j;
            } else {
                d_pos[i] = -1;
            }
            r++;
        }
    }
}

// -------------- gather + hi/lo split of activations --------------------------
__global__ void gather_split_kernel(const float* __restrict__ hidden) {
    int row = blockIdx.x;
    int e = row >> 10, t = row & 1023;
    if (t >= d_m[e]) return;
    const float4* src = (const float4*)(hidden + (size_t)d_tok[row] * DDIM);
    float4* dst = (float4*)(d_xg + (size_t)row * DDIM);
    __nv_bfloat162* hi = (__nv_bfloat162*)(d_xg_hi + (size_t)row * DDIM);
    __nv_bfloat162* lo = (__nv_bfloat162*)(d_xg_lo + (size_t)row * DDIM);
    for (int i = threadIdx.x; i < DDIM / 4; i += 256) {
        float4 v = src[i];
        dst[i] = v;
        __nv_bfloat162 h[2], l[2];
        split4(v, h, l);
        hi[2 * i] = h[0]; hi[2 * i + 1] = h[1];
        lo[2 * i] = l[0]; lo[2 * i + 1] = l[1];
    }
}

// -------------- beta / g projections -----------------------------------------
__global__ void bg_kernel(const float* __restrict__ b_w, const float* __restrict__ a_w,
                          const float* __restrict__ A_log, const float* __restrict__ dt_bias) {
    int row = blockIdx.x * 8 + (threadIdx.x >> 5);
    int lane = threadIdx.x & 31;
    int e = row >> 10, t = row & 1023;
    if (t >= d_m[e]) return;
    const float* x = d_xg + (size_t)row * DDIM;
    const float* bw = b_w + (size_t)e * DDIM * HNUM;
    const float* aw = a_w + (size_t)e * DDIM * HNUM;
    float ba[HNUM], aa[HNUM];
#pragma unroll
    for (int h = 0; h < HNUM; h++) { ba[h] = 0.f; aa[h] = 0.f; }
    for (int d = lane; d < DDIM; d += 32) {
        float xv = x[d];
        const float* bp = bw + (size_t)d * HNUM;
        const float* ap = aw + (size_t)d * HNUM;
#pragma unroll
        for (int h = 0; h < HNUM; h++) { ba[h] += xv * bp[h]; aa[h] += xv * ap[h]; }
    }
#pragma unroll
    for (int h = 0; h < HNUM; h++) {
#pragma unroll
        for (int o = 16; o; o >>= 1) {
            ba[h] += __shfl_xor_sync(0xffffffffu, ba[h], o);
            aa[h] += __shfl_xor_sync(0xffffffffu, aa[h], o);
        }
    }
    if (lane == 0) {
#pragma unroll
        for (int h = 0; h < HNUM; h++) {
            d_beta[row * HNUM + h] = 1.f / (1.f + expf(-ba[h]));
            float xx = aa[h] + dt_bias[h];
            float sp = xx > 20.f ? xx : log1pf(expf(xx));
            d_g[row * HNUM + h] = -expf(A_log[h]) * sp;
        }
    }
}

// -------------- conv + silu + l2norm (q,k) — reads fused pre buffer ----------
__global__ void convnorm_kernel(const float* __restrict__ pre, const float* __restrict__ cw,
                                float* __restrict__ out, float scale, int preOff) {
    int row = blockIdx.x;
    int h = blockIdx.y;
    int e = row >> 10, t = row & 1023;
    if (t >= d_m[e]) return;
    int tid = threadIdx.x;
    int ch = h * DKC + tid;
    float y = 0.f;
#pragma unroll
    for (int j = 0; j < 4; j++) {
        int tt = t - 3 + j;
        if (tt >= 0) y += cw[ch * 4 + j] * pre[(size_t)(row - 3 + j) * QKVN + preOff + ch];
    }
    y = y / (1.f + expf(-y));
    __shared__ float red[256];
    red[tid] = y * y;
    __syncthreads();
    for (int st = 128; st > 0; st >>= 1) {
        if (tid < st) red[tid] += red[tid + st];
        __syncthreads();
    }
    float inv = rsqrtf(red[0] + 1e-6f) * scale;
    out[(size_t)row * KDIM + ch] = y * inv;
}

// -------------- conv + silu for v — fused pre buffer --------------------------
__global__ void convv_kernel(const float* __restrict__ pre, const float* __restrict__ cw,
                             float* __restrict__ out) {
    int idx = blockIdx.x * 256 + threadIdx.x;
    int row = idx / VDIM;
    int ch = idx - row * VDIM;
    int e = row >> 10, t = row & 1023;
    if (t >= d_m[e]) return;
    float y = 0.f;
#pragma unroll
    for (int j = 0; j < 4; j++) {
        int tt = t - 3 + j;
        if (tt >= 0) y += cw[ch * 4 + j] * pre[(size_t)(row - 3 + j) * QKVN + 2 * KDIM + ch];
    }
    out[(size_t)row * VDIM + ch] = y / (1.f + expf(-y));
}

// -------------- gated delta-rule recurrence (f32x2 packed) --------------------
// lane owns 8 contiguous k-dims; warp owns 4 v-lanes; block = (vc, h, e).
__global__ void recur_kernel() {
    int vc = blockIdx.x;
    int h = blockIdx.y;
    int e = blockIdx.z;
    int m = d_m[e];
    __shared__ __align__(16) float S[32 * 256];
    __shared__ float su[32], sw[32], sd[32];
    int tid = threadIdx.x, warp = tid >> 5, lane = tid & 31;
    int v0 = warp * 4;
    for (int i = lane; i < 4 * 256; i += 32) S[v0 * 256 + i] = 0.f;
    if (lane < 4) { su[v0 + lane] = 0.f; sw[v0 + lane] = 0.f; }
    __syncwarp();
    if (m == 0) return;

    const float* kb = d_kn + (size_t)(e * CAP) * KDIM + h * DKC;
    const float* qb = d_qn + (size_t)(e * CAP) * KDIM + h * DKC;
    const float* vb = d_vn + (size_t)(e * CAP) * VDIM + h * DVC + vc * 32;
    const float* bb = d_beta + (size_t)(e * CAP) * HNUM + h;
    const float* gb = d_g + (size_t)(e * CAP) * HNUM + h;
    float* ob = d_o + (size_t)(e * CAP) * VDIM + h * DVC + vc * 32;

    int k0i = lane * 8;
    const unsigned long long ZP = 0ULL;

    unsigned long long kcp[4], qcp[4];
    {
        float4 a0 = *(const float4*)(kb + k0i), a1 = *(const float4*)(kb + k0i + 4);
        float4 b0 = *(const float4*)(qb + k0i), b1 = *(const float4*)(qb + k0i + 4);
        kcp[0] = pk2(a0.x, a0.y); kcp[1] = pk2(a0.z, a0.w);
        kcp[2] = pk2(a1.x, a1.y); kcp[3] = pk2(a1.z, a1.w);
        qcp[0] = pk2(b0.x, b0.y); qcp[1] = pk2(b0.z, b0.w);
        qcp[2] = pk2(b1.x, b1.y); qcp[3] = pk2(b1.z, b1.w);
    }
    float beta = bb[0];
    float gv = gb[0];
    float vv = (lane < 4) ? vb[v0 + lane] : 0.f;

    for (int t = 0; t < m; t++) {
        float eg = expf(gv);
        // qk dot (packed) + shuffle reduce
        unsigned long long qkp = ZP;
#pragma unroll
        for (int j = 0; j < 4; j++) qkp = fma2(kcp[j], qcp[j], qkp);
        float2 qf = upk2(qkp);
        float qk = qf.x + qf.y;
#pragma unroll
        for (int o = 16; o; o >>= 1) qk += __shfl_xor_sync(0xffffffffu, qk, o);

        if (lane < 4) {
            int v = v0 + lane;
            float dd = beta * (vv - eg * su[v]);
            ob[(size_t)t * VDIM + v] = eg * sw[v] + qk * dd;
            sd[v] = dd;
        }
        __syncwarp();

        // prefetch t+1
        unsigned long long knp[4], qnp[4];
        float beta_n = 0.f, g_n = 0.f, vv_n = 0.f;
        if (t + 1 < m) {
            const float* kr = kb + (size_t)(t + 1) * KDIM;
            const float* qr = qb + (size_t)(t + 1) * KDIM;
            float4 a0 = *(const float4*)(kr + k0i), a1 = *(const float4*)(kr + k0i + 4);
            float4 b0 = *(const float4*)(qr + k0i), b1 = *(const float4*)(qr + k0i + 4);
            knp[0] = pk2(a0.x, a0.y); knp[1] = pk2(a0.z, a0.w);
            knp[2] = pk2(a1.x, a1.y); knp[3] = pk2(a1.z, a1.w);
            qnp[0] = pk2(b0.x, b0.y); qnp[1] = pk2(b0.z, b0.w);
            qnp[2] = pk2(b1.x, b1.y); qnp[3] = pk2(b1.z, b1.w);
            beta_n = bb[(size_t)(t + 1) * HNUM];
            g_n = gb[(size_t)(t + 1) * HNUM];
            if (lane < 4) vv_n = vb[(size_t)(t + 1) * VDIM + v0 + lane];
        } else {
#pragma unroll
            for (int j = 0; j < 4; j++) { knp[j] = ZP; qnp[j] = ZP; }
        }

        unsigned long long egp = pk2(eg, eg);
#pragma unroll
        for (int vi = 0; vi < 4; vi++) {
            int v = v0 + vi;
            unsigned long long ddp;
            { float dd = sd[v]; ddp = pk2(dd, dd); }
            float* Sr = &S[v * 256 + k0i];
            float4 sa = *(float4*)Sr;
            float4 sb = *(float4*)(Sr + 4);
            unsigned long long s0 = pk2(sa.x, sa.y), s1 = pk2(sa.z, sa.w);
            unsigned long long s2 = pk2(sb.x, sb.y), s3 = pk2(sb.z, sb.w);
            s0 = fma2(egp, s0, fma2(kcp[0], ddp, ZP));
            s1 = fma2(egp, s1, fma2(kcp[1], ddp, ZP));
            s2 = fma2(egp, s2, fma2(kcp[2], ddp, ZP));
            s3 = fma2(egp, s3, fma2(kcp[3], ddp, ZP));
            float2 f0 = upk2(s0), f1 = upk2(s1), f2 = upk2(s2), f3 = upk2(s3);
            *(float4*)Sr = make_float4(f0.x, f0.y, f1.x, f1.y);
            *(float4*)(Sr + 4) = make_float4(f2.x, f2.y, f3.x, f3.y);
            unsigned long long up = fma2(knp[0], s0, ZP);
            up = fma2(knp[1], s1, up);
            up = fma2(knp[2], s2, up);
            up = fma2(knp[3], s3, up);
            unsigned long long wp = fma2(qnp[0], s0, ZP);
            wp = fma2(qnp[1], s1, wp);
            wp = fma2(qnp[2], s2, wp);
            wp = fma2(qnp[3], s3, wp);
            float2 uf = upk2(up), wf = upk2(wp);
            float un = uf.x + uf.y, wn = wf.x + wf.y;
#pragma unroll
            for (int o = 16; o; o >>= 1) {
                un += __shfl_xor_sync(0xffffffffu, un, o);
                wn += __shfl_xor_sync(0xffffffffu, wn, o);
            }
            if (lane == 0) { su[v] = un; sw[v] = wn; }
        }
        __syncwarp();
#pragma unroll
        for (int j = 0; j < 4; j++) { kcp[j] = knp[j]; qcp[j] = qnp[j]; }
        beta = beta_n; gv = g_n; vv = vv_n;
    }
}

// -------------- combine + gated RMSNorm ---------------------------------------
__global__ void combine_kernel(const float* __restrict__ norm_w) {
    int s = blockIdx.x, h = blockIdx.y, tid = threadIdx.x;
    int p0 = d_pos[2 * s], p1 = d_pos[2 * s + 1];
    float r0 = d_rw[2 * s], r1 = d_rw[2 * s + 1];
    float acc[2];
    float ss = 0.f;
#pragma unroll
    for (int i = 0; i < 2; i++) {
        int v = tid + i * 256;
        float a = 0.f;
        if (p0 >= 0) a += r0 * d_o[(size_t)p0 * VDIM + h * DVC + v];
        if (p1 >= 0) a += r1 * d_o[(size_t)p1 * VDIM + h * DVC + v];
        acc[i] = a;
        ss += a * a;
    }
    __shared__ float red[256];
    red[tid] = ss;
    __syncthreads();
    for (int st = 128; st > 0; st >>= 1) {
        if (tid < st) red[tid] += red[tid + st];
        __syncthreads();
    }
    float inv = rsqrtf(red[0] / (float)DVC + 1e-5f);
#pragma unroll
    for (int i = 0; i < 2; i++) {
        int v = tid + i * 256;
        float gg = d_gg[(size_t)s * VDIM + h * DVC + v];
        float sg = gg / (1.f + expf(-gg));
        d_pre[(size_t)s * VDIM + h * DVC + v] = acc[i] * inv * norm_w[v] * sg;
    }
}

// ----------------------------- launch -----------------------------------------
extern "C" void kernel_launch(void* const* d_in, const int* in_sizes, int n_in,
                              void* d_out, int out_size) {
    const float* hidden  = (const float*)d_in[0];
    const float* q_w     = (const float*)d_in[1];
    const float* gate_w  = (const float*)d_in[2];
    const float* k_w     = (const float*)d_in[3];
    const float* v_w     = (const float*)d_in[4];
    const float* b_w     = (const float*)d_in[5];
    const float* a_w     = (const float*)d_in[6];
    const float* A_log   = (const float*)d_in[7];
    const float* dt_bias = (const float*)d_in[8];
    const float* qcw     = (const float*)d_in[9];
    const float* kcw     = (const float*)d_in[10];
    const float* vcw     = (const float*)d_in[11];
    const float* g_w     = (const float*)d_in[12];
    const float* norm_w  = (const float*)d_in[13];
    const float* o_w     = (const float*)d_in[14];

    float* qkvpre = 0; float* gg = 0; float* pre = 0;
    cudaGetSymbolAddress((void**)&qkvpre, d_qkvpre);
    cudaGetSymbolAddress((void**)&gg, d_gg);
    cudaGetSymbolAddress((void**)&pre, d_pre);
    float* qn = 0; float* kn = 0; float* vn = 0;
    cudaGetSymbolAddress((void**)&qn, d_qn);
    cudaGetSymbolAddress((void**)&kn, d_kn);
    cudaGetSymbolAddress((void**)&vn, d_vn);

    __nv_bfloat16* xgh = 0; __nv_bfloat16* xgl = 0;
    __nv_bfloat16* qkvh = 0; __nv_bfloat16* qkvl = 0;
    __nv_bfloat16* gwh = 0; __nv_bfloat16* gwl = 0;
    __nv_bfloat16* owh = 0; __nv_bfloat16* owl = 0;
    __nv_bfloat16* hih = 0; __nv_bfloat16* hil = 0;
    __nv_bfloat16* prh = 0; __nv_bfloat16* prl = 0;
    cudaGetSymbolAddress((void**)&xgh, d_xg_hi);
    cudaGetSymbolAddress((void**)&xgl, d_xg_lo);
    cudaGetSymbolAddress((void**)&qkvh, d_qkvw_hi);
    cudaGetSymbolAddress((void**)&qkvl, d_qkvw_lo);
    cudaGetSymbolAddress((void**)&gwh, d_gw_hi);
    cudaGetSymbolAddress((void**)&gwl, d_gw_lo);
    cudaGetSymbolAddress((void**)&owh, d_ow_hi);
    cudaGetSymbolAddress((void**)&owl, d_ow_lo);
    cudaGetSymbolAddress((void**)&hih, d_hid_hi);
    cudaGetSymbolAddress((void**)&hil, d_hid_lo);
    cudaGetSymbolAddress((void**)&prh, d_pre_hi);
    cudaGetSymbolAddress((void**)&prl, d_pre_lo);

    cudaFuncSetAttribute(gemm_tc, cudaFuncAttributeMaxDynamicSharedMemorySize, GEMM_SMEM);

    // 1: pack all weights (+hidden split) — no deps
    pack_w_kernel<<<(int)((TOT_U + 255) / 256), 256>>>(q_w, k_w, v_w, g_w, o_w, hidden);
    // 2-3: routing
    router_kernel<<<SLEN, 256>>>(hidden, gate_w);
    dispatch_kernel<<<1, 32>>>();
    // 4: gate projection (tensor core) — only needs pack
    gemm_tc<<<dim3(VDIM / 128, SLEN / 128, 1), 256, GEMM_SMEM>>>(
        hih, hil, gwh, gwl, gg, SLEN, VDIM, DDIM, 0LL, 0LL, 0LL, 0);
    // 5: gather + activation split
    gather_split_kernel<<<NROW, 256>>>(hidden);
    // 6: fused qkv per-expert projection
    gemm_tc<<<dim3(QKVN / 128, CAP / 128, ENUM), 256, GEMM_SMEM>>>(
        xgh, xgl, qkvh, qkvl, qkvpre, CAP, QKVN, DDIM,
        (long long)CAP * DDIM, (long long)DDIM * QKVN, (long long)CAP * QKVN, 1);

    bg_kernel<<<NROW / 8, 256>>>(b_w, a_w, A_log, dt_bias);

    dim3 gc(NROW, HNUM);
    convnorm_kernel<<<gc, 256>>>(qkvpre, qcw, qn, 0.0625f, 0);      // q at offset 0
    convnorm_kernel<<<gc, 256>>>(qkvpre, kcw, kn, 1.0f, KDIM);      // k at offset 1536
    convv_kernel<<<(NROW * (VDIM / 256)), 256>>>(qkvpre, vcw, vn);  // v at offset 3072

    recur_kernel<<<dim3(DVC / 32, HNUM, ENUM), 256>>>();

    combine_kernel<<<dim3(SLEN, HNUM), 256>>>(norm_w);
    {
        int n4 = SLEN * VDIM / 4;
        split_kernel<<<(n4 + 255) / 256, 256>>>((const float4*)pre,
                                                (__nv_bfloat162*)prh, (__nv_bfloat162*)prl, n4);
    }
    gemm_tc<<<dim3(DDIM / 128, SLEN / 128, 1), 256, GEMM_SMEM>>>(
        prh, prl, owh, owl, (float*)d_out, SLEN, DDIM, VDIM, 0LL, 0LL, 0LL, 0);
}

// round 6
// speedup vs baseline: 1.1493x; 1.1493x over previous
#include <cuda_runtime.h>
#include <cuda_bf16.h>
#include <stdint.h>
#include <math.h>

#define SLEN 1024
#define DDIM 2048
#define ENUM 8
#define HNUM 6
#define DKC  256
#define DVC  512
#define KDIM 1536   // HNUM*DKC
#define VDIM 3072   // HNUM*DVC
#define QKVN 6144   // KDIM+KDIM+VDIM fused
#define CAP  1024
#define NROW (ENUM*CAP)

// ---------------- scratch (device globals; no allocation in kernel_launch) ----
__device__ int   d_sel[SLEN*2];
__device__ float d_rw [SLEN*2];
__device__ int   d_m  [ENUM];
__device__ int   d_tok[NROW];
__device__ int   d_pos[SLEN*2];
__device__ float d_xg  [NROW*DDIM];
__device__ float d_qkvpre[(size_t)NROW*QKVN];
__device__ float d_qn  [NROW*KDIM];
__device__ float d_kn  [NROW*KDIM];
__device__ float d_vn  [NROW*VDIM];
__device__ float d_beta[NROW*HNUM];
__device__ float d_g   [NROW*HNUM];
__device__ float d_o   [NROW*VDIM];
__device__ float d_gg  [SLEN*VDIM];
__device__ float d_pre [SLEN*VDIM];

// bf16 hi/lo split buffers
__device__ __align__(256) __nv_bfloat16 d_xg_hi[NROW*DDIM];
__device__ __align__(256) __nv_bfloat16 d_xg_lo[NROW*DDIM];
__device__ __align__(256) __nv_bfloat16 d_qkvw_hi[(size_t)ENUM*DDIM*QKVN];
__device__ __align__(256) __nv_bfloat16 d_qkvw_lo[(size_t)ENUM*DDIM*QKVN];
__device__ __align__(256) __nv_bfloat16 d_gw_hi[DDIM*VDIM];
__device__ __align__(256) __nv_bfloat16 d_gw_lo[DDIM*VDIM];
__device__ __align__(256) __nv_bfloat16 d_ow_hi[VDIM*DDIM];
__device__ __align__(256) __nv_bfloat16 d_ow_lo[VDIM*DDIM];
__device__ __align__(256) __nv_bfloat16 d_hid_hi[SLEN*DDIM];
__device__ __align__(256) __nv_bfloat16 d_hid_lo[SLEN*DDIM];
__device__ __align__(256) __nv_bfloat16 d_pre_hi[SLEN*VDIM];
__device__ __align__(256) __nv_bfloat16 d_pre_lo[SLEN*VDIM];

// ---------------- PTX helpers -------------------------------------------------
__device__ __forceinline__ void cpa16(uint32_t d, const void* s) {
    asm volatile("cp.async.cg.shared.global [%0], [%1], 16;" :: "r"(d), "l"(s));
}
__device__ __forceinline__ void ldm_x4(uint32_t* r, uint32_t a) {
    asm volatile("ldmatrix.sync.aligned.m8n8.x4.shared.b16 {%0,%1,%2,%3}, [%4];"
                 : "=r"(r[0]), "=r"(r[1]), "=r"(r[2]), "=r"(r[3]) : "r"(a));
}
__device__ __forceinline__ void ldm_x4t(uint32_t* r, uint32_t a) {
    asm volatile("ldmatrix.sync.aligned.m8n8.x4.trans.shared.b16 {%0,%1,%2,%3}, [%4];"
                 : "=r"(r[0]), "=r"(r[1]), "=r"(r[2]), "=r"(r[3]) : "r"(a));
}
__device__ __forceinline__ void mma_bf16(float* c, const uint32_t* a, const uint32_t* b) {
    asm volatile(
        "mma.sync.aligned.m16n8k16.row.col.f32.bf16.bf16.f32 "
        "{%0,%1,%2,%3},{%4,%5,%6,%7},{%8,%9},{%0,%1,%2,%3};"
        : "+f"(c[0]), "+f"(c[1]), "+f"(c[2]), "+f"(c[3])
        : "r"(a[0]), "r"(a[1]), "r"(a[2]), "r"(a[3]), "r"(b[0]), "r"(b[1]));
}

// ---------------- hi/lo split conversion --------------------------------------
__device__ __forceinline__ void split4(float4 v, __nv_bfloat162* hi, __nv_bfloat162* lo) {
    __nv_bfloat16 h0 = __float2bfloat16(v.x), h1 = __float2bfloat16(v.y);
    __nv_bfloat16 h2 = __float2bfloat16(v.z), h3 = __float2bfloat16(v.w);
    __nv_bfloat16 l0 = __float2bfloat16(v.x - __bfloat162float(h0));
    __nv_bfloat16 l1 = __float2bfloat16(v.y - __bfloat162float(h1));
    __nv_bfloat16 l2 = __float2bfloat16(v.z - __bfloat162float(h2));
    __nv_bfloat16 l3 = __float2bfloat16(v.w - __bfloat162float(h3));
    hi[0] = __halves2bfloat162(h0, h1);
    hi[1] = __halves2bfloat162(h2, h3);
    lo[0] = __halves2bfloat162(l0, l1);
    lo[1] = __halves2bfloat162(l2, l3);
}

__global__ void split_kernel(const float4* __restrict__ x, __nv_bfloat162* __restrict__ hi,
                             __nv_bfloat162* __restrict__ lo, int n4) {
    int i = blockIdx.x * 256 + threadIdx.x;
    if (i >= n4) return;
    __nv_bfloat162 h[2], l[2];
    split4(x[i], h, l);
    hi[2 * i] = h[0]; hi[2 * i + 1] = h[1];
    lo[2 * i] = l[0]; lo[2 * i + 1] = l[1];
}

// -------------- one mega-pack: qkv fused weights + gate/out/hidden splits ----
#define QKV_U (ENUM*DDIM*(QKVN/4))
#define GW_U  (DDIM*VDIM/4)
#define OW_U  (VDIM*DDIM/4)
#define HID_U (SLEN*DDIM/4)
#define TOT_U (QKV_U + GW_U + OW_U + HID_U)

__global__ void pack_w_kernel(const float* __restrict__ q_w, const float* __restrict__ k_w,
                              const float* __restrict__ v_w, const float* __restrict__ g_w,
                              const float* __restrict__ o_w, const float* __restrict__ hidden) {
    long long u = (long long)blockIdx.x * 256 + threadIdx.x;
    if (u >= TOT_U) return;
    if (u < QKV_U) {
        long long per_e = (long long)DDIM * (QKVN / 4);
        int e = (int)(u / per_e);
        long long r = u - (long long)e * per_e;
        int d = (int)(r / (QKVN / 4));
        int c4 = (int)(r - (long long)d * (QKVN / 4));
        int n = c4 * 4;
        float4 src;
        if (n < KDIM) {
            src = *(const float4*)(q_w + (size_t)d * KDIM + n);
        } else if (n < 2 * KDIM) {
            src = *(const float4*)(k_w + ((size_t)e * DDIM + d) * KDIM + (n - KDIM));
        } else {
            src = *(const float4*)(v_w + ((size_t)e * DDIM + d) * VDIM + (n - 2 * KDIM));
        }
        size_t dst = ((size_t)e * DDIM + d) * QKVN + n;
        __nv_bfloat162 h[2], l[2];
        split4(src, h, l);
        __nv_bfloat162* hp = (__nv_bfloat162*)(d_qkvw_hi + dst);
        __nv_bfloat162* lp = (__nv_bfloat162*)(d_qkvw_lo + dst);
        hp[0] = h[0]; hp[1] = h[1]; lp[0] = l[0]; lp[1] = l[1];
        return;
    }
    u -= QKV_U;
    if (u < GW_U) {
        float4 src = ((const float4*)g_w)[u];
        __nv_bfloat162 h[2], l[2]; split4(src, h, l);
        ((__nv_bfloat162*)d_gw_hi)[2 * u] = h[0]; ((__nv_bfloat162*)d_gw_hi)[2 * u + 1] = h[1];
        ((__nv_bfloat162*)d_gw_lo)[2 * u] = l[0]; ((__nv_bfloat162*)d_gw_lo)[2 * u + 1] = l[1];
        return;
    }
    u -= GW_U;
    if (u < OW_U) {
        float4 src = ((const float4*)o_w)[u];
        __nv_bfloat162 h[2], l[2]; split4(src, h, l);
        ((__nv_bfloat162*)d_ow_hi)[2 * u] = h[0]; ((__nv_bfloat162*)d_ow_hi)[2 * u + 1] = h[1];
        ((__nv_bfloat162*)d_ow_lo)[2 * u] = l[0]; ((__nv_bfloat162*)d_ow_lo)[2 * u + 1] = l[1];
        return;
    }
    u -= OW_U;
    {
        float4 src = ((const float4*)hidden)[u];
        __nv_bfloat162 h[2], l[2]; split4(src, h, l);
        ((__nv_bfloat162*)d_hid_hi)[2 * u] = h[0]; ((__nv_bfloat162*)d_hid_hi)[2 * u + 1] = h[1];
        ((__nv_bfloat162*)d_hid_lo)[2 * u] = l[0]; ((__nv_bfloat162*)d_hid_lo)[2 * u + 1] = l[1];
    }
}

// ---------------- tensor-core split-bf16 GEMM ---------------------------------
#define LDA 40
#define LDB 136
#define A_SZ (128*LDA)
#define B_SZ (32*LDB)
#define STAGE_H (2*A_SZ + 2*B_SZ)
#define GEMM_SMEM (STAGE_H*2*2)

__global__ __launch_bounds__(256, 2)
void gemm_tc(const __nv_bfloat16* __restrict__ Ahi, const __nv_bfloat16* __restrict__ Alo,
             const __nv_bfloat16* __restrict__ Bhi, const __nv_bfloat16* __restrict__ Blo,
             float* __restrict__ C, int M, int N, int K,
             long long aStride, long long bStride, long long cStride, int useM) {
    extern __shared__ __nv_bfloat16 smbuf[];
    int z = blockIdx.z;
    int mlim = useM ? d_m[z] : M;
    int row0 = blockIdx.y * 128;
    if (row0 >= mlim) return;
    int col0 = blockIdx.x * 128;
    Ahi += (size_t)z * aStride; Alo += (size_t)z * aStride;
    Bhi += (size_t)z * bStride; Blo += (size_t)z * bStride;
    C += (size_t)z * cStride;

    uint32_t sbase = (uint32_t)__cvta_generic_to_shared(smbuf);
    int t = threadIdx.x;

    int arow = t >> 1, akc = (t & 1) * 16;
    int brow = t >> 3, bnc = (t & 7) * 16;
    const __nv_bfloat16* gAh = Ahi + (size_t)(row0 + arow) * K + akc;
    const __nv_bfloat16* gAl = Alo + (size_t)(row0 + arow) * K + akc;
    const __nv_bfloat16* gBh = Bhi + (size_t)brow * N + col0 + bnc;
    const __nv_bfloat16* gBl = Blo + (size_t)brow * N + col0 + bnc;
    uint32_t dAh = sbase + (uint32_t)(arow * LDA + akc) * 2;
    uint32_t dAl = dAh + A_SZ * 2;
    uint32_t dBh = sbase + (uint32_t)(2 * A_SZ + brow * LDB + bnc) * 2;
    uint32_t dBl = dBh + B_SZ * 2;

    int lane = t & 31, wid = t >> 5;
    int wm = (wid >> 2) * 64, wn = (wid & 3) * 32;
    int aR = lane & 15, aC = (lane >> 4) * 8;
    uint32_t aOff = (uint32_t)((wm + aR) * LDA + aC) * 2;
    int bgp = lane >> 3, blr = lane & 7;
    int bR = blr + (bgp & 1) * 8, bC = (bgp >> 1) * 8;
    uint32_t bOff = (uint32_t)(bR * LDB + wn + bC) * 2;

    float acc[4][4][4];
#pragma unroll
    for (int mi = 0; mi < 4; mi++)
#pragma unroll
        for (int ni = 0; ni < 4; ni++)
#pragma unroll
            for (int j = 0; j < 4; j++) acc[mi][ni][j] = 0.f;

    int KT = K / 32;

    cpa16(dAh, gAh);           cpa16(dAh + 16, gAh + 8);
    cpa16(dAl, gAl);           cpa16(dAl + 16, gAl + 8);
    cpa16(dBh, gBh);           cpa16(dBh + 16, gBh + 8);
    cpa16(dBl, gBl);           cpa16(dBl + 16, gBl + 8);
    asm volatile("cp.async.commit_group;");

    for (int kt = 0; kt < KT; kt++) {
        if (kt + 1 < KT) {
            int k0 = (kt + 1) * 32;
            uint32_t so = (uint32_t)(((kt + 1) & 1) * STAGE_H) * 2;
            const __nv_bfloat16* a0 = gAh + k0;
            const __nv_bfloat16* a1 = gAl + k0;
            const __nv_bfloat16* b0 = gBh + (size_t)k0 * N;
            const __nv_bfloat16* b1 = gBl + (size_t)k0 * N;
            cpa16(dAh + so, a0);        cpa16(dAh + so + 16, a0 + 8);
            cpa16(dAl + so, a1);        cpa16(dAl + so + 16, a1 + 8);
            cpa16(dBh + so, b0);        cpa16(dBh + so + 16, b0 + 8);
            cpa16(dBl + so, b1);        cpa16(dBl + so + 16, b1 + 8);
            asm volatile("cp.async.commit_group;");
            asm volatile("cp.async.wait_group 1;");
        } else {
            asm volatile("cp.async.wait_group 0;");
        }
        __syncthreads();

        uint32_t s0 = sbase + (uint32_t)((kt & 1) * STAGE_H) * 2;
        uint32_t sAh = s0 + aOff;
        uint32_t sAl = sAh + (uint32_t)A_SZ * 2;
        uint32_t sBh = s0 + (uint32_t)(2 * A_SZ) * 2 + bOff;
        uint32_t sBl = sBh + (uint32_t)B_SZ * 2;

#pragma unroll
        for (int ks = 0; ks < 2; ks++) {
            uint32_t kao = (uint32_t)(ks * 16) * 2;
            uint32_t kbo = (uint32_t)(ks * 16 * LDB) * 2;
            uint32_t bh[8], bl2[8], af[16];
            ldm_x4t(bh + 0, sBh + kbo);
            ldm_x4t(bh + 4, sBh + kbo + 32);
            ldm_x4t(bl2 + 0, sBl + kbo);
            ldm_x4t(bl2 + 4, sBl + kbo + 32);
#pragma unroll
            for (int mi = 0; mi < 4; mi++)
                ldm_x4(af + mi * 4, sAh + kao + (uint32_t)(mi * 16 * LDA) * 2);
#pragma unroll
            for (int mi = 0; mi < 4; mi++)
#pragma unroll
                for (int ni = 0; ni < 4; ni++)
                    mma_bf16(acc[mi][ni], af + mi * 4, bh + (ni >> 1) * 4 + (ni & 1) * 2);
#pragma unroll
            for (int mi = 0; mi < 4; mi++)
#pragma unroll
                for (int ni = 0; ni < 4; ni++)
                    mma_bf16(acc[mi][ni], af + mi * 4, bl2 + (ni >> 1) * 4 + (ni & 1) * 2);
#pragma unroll
            for (int mi = 0; mi < 4; mi++)
                ldm_x4(af + mi * 4, sAl + kao + (uint32_t)(mi * 16 * LDA) * 2);
#pragma unroll
            for (int mi = 0; mi < 4; mi++)
#pragma unroll
                for (int ni = 0; ni < 4; ni++)
                    mma_bf16(acc[mi][ni], af + mi * 4, bh + (ni >> 1) * 4 + (ni & 1) * 2);
        }
        __syncthreads();
    }

    int gr = lane >> 2, gc = (lane & 3) * 2;
#pragma unroll
    for (int mi = 0; mi < 4; mi++) {
        int r = row0 + wm + mi * 16 + gr;
#pragma unroll
        for (int ni = 0; ni < 4; ni++) {
            float* Cp = C + (size_t)r * N + col0 + wn + ni * 8 + gc;
            if (r < mlim) {
                Cp[0] = acc[mi][ni][0];
                Cp[1] = acc[mi][ni][1];
            }
            if (r + 8 < mlim) {
                float* Cq = Cp + (size_t)8 * N;
                Cq[0] = acc[mi][ni][2];
                Cq[1] = acc[mi][ni][3];
            }
        }
    }
}

// ---------------- router ------------------------------------------------------
__global__ void router_kernel(const float* __restrict__ hidden,
                              const float* __restrict__ gate_w) {
    int s = blockIdx.x;
    int tid = threadIdx.x;
    float acc[ENUM];
#pragma unroll
    for (int e = 0; e < ENUM; e++) acc[e] = 0.f;
    const float* xr = hidden + (size_t)s * DDIM;
    for (int d = tid; d < DDIM; d += 256) {
        float x = xr[d];
        const float* w = gate_w + (size_t)d * ENUM;
#pragma unroll
        for (int e = 0; e < ENUM; e++) acc[e] += x * w[e];
    }
    __shared__ float red[ENUM][256];
#pragma unroll
    for (int e = 0; e < ENUM; e++) red[e][tid] = acc[e];
    __syncthreads();
    for (int st = 128; st > 0; st >>= 1) {
        if (tid < st) {
#pragma unroll
            for (int e = 0; e < ENUM; e++) red[e][tid] += red[e][tid + st];
        }
        __syncthreads();
    }
    if (tid == 0) {
        float l[ENUM], mx = -1e30f;
#pragma unroll
        for (int e = 0; e < ENUM; e++) { l[e] = red[e][0]; mx = fmaxf(mx, l[e]); }
        float p[ENUM], sum = 0.f;
#pragma unroll
        for (int e = 0; e < ENUM; e++) { p[e] = expf(l[e] - mx); sum += p[e]; }
#pragma unroll
        for (int e = 0; e < ENUM; e++) p[e] /= sum;
        int i0 = 0;
#pragma unroll
        for (int e = 1; e < ENUM; e++) if (p[e] > p[i0]) i0 = e;
        int i1 = -1;
#pragma unroll
        for (int e = 0; e < ENUM; e++)
            if (e != i0 && (i1 < 0 || p[e] > p[i1])) i1 = e;
        float r0 = p[i0], r1 = p[i1], rs = r0 + r1;
        d_sel[2 * s] = i0;  d_sel[2 * s + 1] = i1;
        d_rw[2 * s] = r0 / rs;  d_rw[2 * s + 1] = r1 / rs;
    }
}

// -------------- dispatch ------------------------------------------------------
__global__ void dispatch_kernel() {
    int e = threadIdx.x;
    if (e >= ENUM) return;
    int c = 0;
    for (int i = 0; i < SLEN * 2; i++) c += (d_sel[i] == e);
    int drop = c > CAP ? c - CAP : 0;
    d_m[e] = c - drop;
    int r = 0;
    for (int i = 0; i < SLEN * 2; i++) {
        if (d_sel[i] == e) {
            if (r >= drop) {
                int j = r - drop;
                d_tok[e * CAP + j] = i >> 1;
                d_pos[i] = e * CAP + j;
            } else {
                d_pos[i] = -1;
            }
            r++;
        }
    }
}

// -------------- gather + hi/lo split of activations --------------------------
__global__ void gather_split_kernel(const float* __restrict__ hidden) {
    int row = blockIdx.x;
    int e = row >> 10, t = row & 1023;
    if (t >= d_m[e]) return;
    const float4* src = (const float4*)(hidden + (size_t)d_tok[row] * DDIM);
    float4* dst = (float4*)(d_xg + (size_t)row * DDIM);
    __nv_bfloat162* hi = (__nv_bfloat162*)(d_xg_hi + (size_t)row * DDIM);
    __nv_bfloat162* lo = (__nv_bfloat162*)(d_xg_lo + (size_t)row * DDIM);
    for (int i = threadIdx.x; i < DDIM / 4; i += 256) {
        float4 v = src[i];
        dst[i] = v;
        __nv_bfloat162 h[2], l[2];
        split4(v, h, l);
        hi[2 * i] = h[0]; hi[2 * i + 1] = h[1];
        lo[2 * i] = l[0]; lo[2 * i + 1] = l[1];
    }
}

// -------------- beta / g projections -----------------------------------------
__global__ void bg_kernel(const float* __restrict__ b_w, const float* __restrict__ a_w,
                          const float* __restrict__ A_log, const float* __restrict__ dt_bias) {
    int row = blockIdx.x * 8 + (threadIdx.x >> 5);
    int lane = threadIdx.x & 31;
    int e = row >> 10, t = row & 1023;
    if (t >= d_m[e]) return;
    const float* x = d_xg + (size_t)row * DDIM;
    const float* bw = b_w + (size_t)e * DDIM * HNUM;
    const float* aw = a_w + (size_t)e * DDIM * HNUM;
    float ba[HNUM], aa[HNUM];
#pragma unroll
    for (int h = 0; h < HNUM; h++) { ba[h] = 0.f; aa[h] = 0.f; }
    for (int d = lane; d < DDIM; d += 32) {
        float xv = x[d];
        const float* bp = bw + (size_t)d * HNUM;
        const float* ap = aw + (size_t)d * HNUM;
#pragma unroll
        for (int h = 0; h < HNUM; h++) { ba[h] += xv * bp[h]; aa[h] += xv * ap[h]; }
    }
#pragma unroll
    for (int h = 0; h < HNUM; h++) {
#pragma unroll
        for (int o = 16; o; o >>= 1) {
            ba[h] += __shfl_xor_sync(0xffffffffu, ba[h], o);
            aa[h] += __shfl_xor_sync(0xffffffffu, aa[h], o);
        }
    }
    if (lane == 0) {
#pragma unroll
        for (int h = 0; h < HNUM; h++) {
            d_beta[row * HNUM + h] = 1.f / (1.f + expf(-ba[h]));
            float xx = aa[h] + dt_bias[h];
            float sp = xx > 20.f ? xx : log1pf(expf(xx));
            d_g[row * HNUM + h] = -expf(A_log[h]) * sp;
        }
    }
}

// -------------- conv + silu + l2norm (q,k) — reads fused pre buffer ----------
__global__ void convnorm_kernel(const float* __restrict__ pre, const float* __restrict__ cw,
                                float* __restrict__ out, float scale, int preOff) {
    int row = blockIdx.x;
    int h = blockIdx.y;
    int e = row >> 10, t = row & 1023;
    if (t >= d_m[e]) return;
    int tid = threadIdx.x;
    int ch = h * DKC + tid;
    float y = 0.f;
#pragma unroll
    for (int j = 0; j < 4; j++) {
        int tt = t - 3 + j;
        if (tt >= 0) y += cw[ch * 4 + j] * pre[(size_t)(row - 3 + j) * QKVN + preOff + ch];
    }
    y = y / (1.f + expf(-y));
    __shared__ float red[256];
    red[tid] = y * y;
    __syncthreads();
    for (int st = 128; st > 0; st >>= 1) {
        if (tid < st) red[tid] += red[tid + st];
        __syncthreads();
    }
    float inv = rsqrtf(red[0] + 1e-6f) * scale;
    out[(size_t)row * KDIM + ch] = y * inv;
}

// -------------- conv + silu for v — fused pre buffer --------------------------
__global__ void convv_kernel(const float* __restrict__ pre, const float* __restrict__ cw,
                             float* __restrict__ out) {
    int idx = blockIdx.x * 256 + threadIdx.x;
    int row = idx / VDIM;
    int ch = idx - row * VDIM;
    int e = row >> 10, t = row & 1023;
    if (t >= d_m[e]) return;
    float y = 0.f;
#pragma unroll
    for (int j = 0; j < 4; j++) {
        int tt = t - 3 + j;
        if (tt >= 0) y += cw[ch * 4 + j] * pre[(size_t)(row - 3 + j) * QKVN + 2 * KDIM + ch];
    }
    out[(size_t)row * VDIM + ch] = y / (1.f + expf(-y));
}

// -------------- gated delta-rule recurrence (R4 version: conflict-free) -------
// block = (vc, h, e). State S[32][256] smem, lane stride 32 (bank-conflict-free).
__global__ void recur_kernel() {
    int vc = blockIdx.x;
    int h = blockIdx.y;
    int e = blockIdx.z;
    int m = d_m[e];
    __shared__ float S[32 * 256];
    __shared__ float su[32], sw[32], sd[32];
    int tid = threadIdx.x, warp = tid >> 5, lane = tid & 31;
    int v0 = warp * 4;
    for (int i = lane; i < 4 * 256; i += 32) S[v0 * 256 + i] = 0.f;
    if (lane < 4) { su[v0 + lane] = 0.f; sw[v0 + lane] = 0.f; }
    __syncwarp();
    if (m == 0) return;

    const float* kb = d_kn + (size_t)(e * CAP) * KDIM + h * DKC;
    const float* qb = d_qn + (size_t)(e * CAP) * KDIM + h * DKC;
    const float* vb = d_vn + (size_t)(e * CAP) * VDIM + h * DVC + vc * 32;
    const float* bb = d_beta + (size_t)(e * CAP) * HNUM + h;
    const float* gb = d_g + (size_t)(e * CAP) * HNUM + h;
    float* ob = d_o + (size_t)(e * CAP) * VDIM + h * DVC + vc * 32;

    float kc[8], qc[8];
#pragma unroll
    for (int j = 0; j < 8; j++) { kc[j] = kb[lane + 32 * j]; qc[j] = qb[lane + 32 * j]; }
    float beta = bb[0];
    float gv = gb[0];
    float vv = (lane < 4) ? vb[v0 + lane] : 0.f;

    for (int t = 0; t < m; t++) {
        float eg = expf(gv);
        float qk = 0.f;
#pragma unroll
        for (int j = 0; j < 8; j++) qk += kc[j] * qc[j];
#pragma unroll
        for (int o = 16; o; o >>= 1) qk += __shfl_xor_sync(0xffffffffu, qk, o);

        if (lane < 4) {
            int v = v0 + lane;
            float dd = beta * (vv - eg * su[v]);
            ob[(size_t)t * VDIM + v] = eg * sw[v] + qk * dd;
            sd[v] = dd;
        }
        __syncwarp();

        float kn2[8], qn2[8];
        float beta_n = 0.f, g_n = 0.f, vv_n = 0.f;
        if (t + 1 < m) {
            const float* kr = kb + (size_t)(t + 1) * KDIM;
            const float* qr = qb + (size_t)(t + 1) * KDIM;
#pragma unroll
            for (int j = 0; j < 8; j++) { kn2[j] = kr[lane + 32 * j]; qn2[j] = qr[lane + 32 * j]; }
            beta_n = bb[(size_t)(t + 1) * HNUM];
            g_n = gb[(size_t)(t + 1) * HNUM];
            if (lane < 4) vv_n = vb[(size_t)(t + 1) * VDIM + v0 + lane];
        } else {
#pragma unroll
            for (int j = 0; j < 8; j++) { kn2[j] = 0.f; qn2[j] = 0.f; }
        }

#pragma unroll
        for (int vi = 0; vi < 4; vi++) {
            int v = v0 + vi;
            float dd = sd[v];
            float un = 0.f, wn = 0.f;
            float* Sr = &S[v * 256];
#pragma unroll
            for (int j = 0; j < 8; j++) {
                float s2 = Sr[lane + 32 * j];
                s2 = eg * s2 + kc[j] * dd;
                Sr[lane + 32 * j] = s2;
                un += kn2[j] * s2;
                wn += qn2[j] * s2;
            }
#pragma unroll
            for (int o = 16; o; o >>= 1) {
                un += __shfl_xor_sync(0xffffffffu, un, o);
                wn += __shfl_xor_sync(0xffffffffu, wn, o);
            }
            if (lane == 0) { su[v] = un; sw[v] = wn; }
        }
        __syncwarp();
#pragma unroll
        for (int j = 0; j < 8; j++) { kc[j] = kn2[j]; qc[j] = qn2[j]; }
        beta = beta_n; gv = g_n; vv = vv_n;
    }
}

// -------------- combine + gated RMSNorm ---------------------------------------
__global__ void combine_kernel(const float* __restrict__ norm_w) {
    int s = blockIdx.x, h = blockIdx.y, tid = threadIdx.x;
    int p0 = d_pos[2 * s], p1 = d_pos[2 * s + 1];
    float r0 = d_rw[2 * s], r1 = d_rw[2 * s + 1];
    float acc[2];
    float ss = 0.f;
#pragma unroll
    for (int i = 0; i < 2; i++) {
        int v = tid + i * 256;
        float a = 0.f;
        if (p0 >= 0) a += r0 * d_o[(size_t)p0 * VDIM + h * DVC + v];
        if (p1 >= 0) a += r1 * d_o[(size_t)p1 * VDIM + h * DVC + v];
        acc[i] = a;
        ss += a * a;
    }
    __shared__ float red[256];
    red[tid] = ss;
    __syncthreads();
    for (int st = 128; st > 0; st >>= 1) {
        if (tid < st) red[tid] += red[tid + st];
        __syncthreads();
    }
    float inv = rsqrtf(red[0] / (float)DVC + 1e-5f);
#pragma unroll
    for (int i = 0; i < 2; i++) {
        int v = tid + i * 256;
        float gg = d_gg[(size_t)s * VDIM + h * DVC + v];
        float sg = gg / (1.f + expf(-gg));
        d_pre[(size_t)s * VDIM + h * DVC + v] = acc[i] * inv * norm_w[v] * sg;
    }
}

// ----------------------------- launch -----------------------------------------
extern "C" void kernel_launch(void* const* d_in, const int* in_sizes, int n_in,
                              void* d_out, int out_size) {
    const float* hidden  = (const float*)d_in[0];
    const float* q_w     = (const float*)d_in[1];
    const float* gate_w  = (const float*)d_in[2];
    const float* k_w     = (const float*)d_in[3];
    const float* v_w     = (const float*)d_in[4];
    const float* b_w     = (const float*)d_in[5];
    const float* a_w     = (const float*)d_in[6];
    const float* A_log   = (const float*)d_in[7];
    const float* dt_bias = (const float*)d_in[8];
    const float* qcw     = (const float*)d_in[9];
    const float* kcw     = (const float*)d_in[10];
    const float* vcw     = (const float*)d_in[11];
    const float* g_w     = (const float*)d_in[12];
    const float* norm_w  = (const float*)d_in[13];
    const float* o_w     = (const float*)d_in[14];

    float* qkvpre = 0; float* gg = 0; float* pre = 0;
    cudaGetSymbolAddress((void**)&qkvpre, d_qkvpre);
    cudaGetSymbolAddress((void**)&gg, d_gg);
    cudaGetSymbolAddress((void**)&pre, d_pre);
    float* qn = 0; float* kn = 0; float* vn = 0;
    cudaGetSymbolAddress((void**)&qn, d_qn);
    cudaGetSymbolAddress((void**)&kn, d_kn);
    cudaGetSymbolAddress((void**)&vn, d_vn);

    __nv_bfloat16* xgh = 0; __nv_bfloat16* xgl = 0;
    __nv_bfloat16* qkvh = 0; __nv_bfloat16* qkvl = 0;
    __nv_bfloat16* gwh = 0; __nv_bfloat16* gwl = 0;
    __nv_bfloat16* owh = 0; __nv_bfloat16* owl = 0;
    __nv_bfloat16* hih = 0; __nv_bfloat16* hil = 0;
    __nv_bfloat16* prh = 0; __nv_bfloat16* prl = 0;
    cudaGetSymbolAddress((void**)&xgh, d_xg_hi);
    cudaGetSymbolAddress((void**)&xgl, d_xg_lo);
    cudaGetSymbolAddress((void**)&qkvh, d_qkvw_hi);
    cudaGetSymbolAddress((void**)&qkvl, d_qkvw_lo);
    cudaGetSymbolAddress((void**)&gwh, d_gw_hi);
    cudaGetSymbolAddress((void**)&gwl, d_gw_lo);
    cudaGetSymbolAddress((void**)&owh, d_ow_hi);
    cudaGetSymbolAddress((void**)&owl, d_ow_lo);
    cudaGetSymbolAddress((void**)&hih, d_hid_hi);
    cudaGetSymbolAddress((void**)&hil, d_hid_lo);
    cudaGetSymbolAddress((void**)&prh, d_pre_hi);
    cudaGetSymbolAddress((void**)&prl, d_pre_lo);

    cudaFuncSetAttribute(gemm_tc, cudaFuncAttributeMaxDynamicSharedMemorySize, GEMM_SMEM);

    // 1: pack all weights (+hidden split) — no deps
    pack_w_kernel<<<(int)((TOT_U + 255) / 256), 256>>>(q_w, k_w, v_w, g_w, o_w, hidden);
    // 2-3: routing
    router_kernel<<<SLEN, 256>>>(hidden, gate_w);
    dispatch_kernel<<<1, 32>>>();
    // 4: gate projection (tensor core)
    gemm_tc<<<dim3(VDIM / 128, SLEN / 128, 1), 256, GEMM_SMEM>>>(
        hih, hil, gwh, gwl, gg, SLEN, VDIM, DDIM, 0LL, 0LL, 0LL, 0);
    // 5: gather + activation split
    gather_split_kernel<<<NROW, 256>>>(hidden);
    // 6: fused qkv per-expert projection
    gemm_tc<<<dim3(QKVN / 128, CAP / 128, ENUM), 256, GEMM_SMEM>>>(
        xgh, xgl, qkvh, qkvl, qkvpre, CAP, QKVN, DDIM,
        (long long)CAP * DDIM, (long long)DDIM * QKVN, (long long)CAP * QKVN, 1);

    bg_kernel<<<NROW / 8, 256>>>(b_w, a_w, A_log, dt_bias);

    dim3 gc(NROW, HNUM);
    convnorm_kernel<<<gc, 256>>>(qkvpre, qcw, qn, 0.0625f, 0);      // q at offset 0
    convnorm_kernel<<<gc, 256>>>(qkvpre, kcw, kn, 1.0f, KDIM);      // k at offset 1536
    convv_kernel<<<(NROW * (VDIM / 256)), 256>>>(qkvpre, vcw, vn);  // v at offset 3072

    recur_kernel<<<dim3(DVC / 32, HNUM, ENUM), 256>>>();

    combine_kernel<<<dim3(SLEN, HNUM), 256>>>(norm_w);
    {
        int n4 = SLEN * VDIM / 4;
        split_kernel<<<(n4 + 255) / 256, 256>>>((const float4*)pre,
                                                (__nv_bfloat162*)prh, (__nv_bfloat162*)prl, n4);
    }
    gemm_tc<<<dim3(DDIM / 128, SLEN / 128, 1), 256, GEMM_SMEM>>>(
        prh, prl, owh, owl, (float*)d_out, SLEN, DDIM, VDIM, 0LL, 0LL, 0LL, 0);
}

// round 7
// speedup vs baseline: 1.2063x; 1.0496x over previous
#include <cuda_runtime.h>
#include <cuda_bf16.h>
#include <stdint.h>
#include <math.h>

#define SLEN 1024
#define DDIM 2048
#define ENUM 8
#define HNUM 6
#define DKC  256
#define DVC  512
#define KDIM 1536   // HNUM*DKC
#define VDIM 3072   // HNUM*DVC
#define QKVO 6144   // q+k+v data cols
#define QKVP 6272   // padded: + 12 beta/g cols + zero pad (49*128)
#define CAP  1024
#define NROW (ENUM*CAP)

// ---------------- scratch (device globals; no allocation in kernel_launch) ----
__device__ int   d_sel[SLEN*2];
__device__ float d_rw [SLEN*2];
__device__ int   d_m  [ENUM];
__device__ int   d_tok[NROW];
__device__ int   d_pos[SLEN*2];
__device__ float d_qkvpre[(size_t)NROW*QKVP];
__device__ float d_qn  [NROW*KDIM];
__device__ float d_kn  [NROW*KDIM];
__device__ float d_vn  [NROW*VDIM];
__device__ float d_beta[NROW*HNUM];
__device__ float d_g   [NROW*HNUM];
__device__ float d_o   [NROW*VDIM];
__device__ float d_gg  [SLEN*VDIM];
__device__ float d_pre [SLEN*VDIM];

// bf16 hi/lo split buffers
__device__ __align__(256) __nv_bfloat16 d_xg_hi[NROW*DDIM];
__device__ __align__(256) __nv_bfloat16 d_xg_lo[NROW*DDIM];
__device__ __align__(256) __nv_bfloat16 d_qkvw_hi[(size_t)ENUM*DDIM*QKVP];
__device__ __align__(256) __nv_bfloat16 d_qkvw_lo[(size_t)ENUM*DDIM*QKVP];
__device__ __align__(256) __nv_bfloat16 d_gw_hi[DDIM*VDIM];
__device__ __align__(256) __nv_bfloat16 d_gw_lo[DDIM*VDIM];
__device__ __align__(256) __nv_bfloat16 d_ow_hi[VDIM*DDIM];
__device__ __align__(256) __nv_bfloat16 d_ow_lo[VDIM*DDIM];
__device__ __align__(256) __nv_bfloat16 d_hid_hi[SLEN*DDIM];
__device__ __align__(256) __nv_bfloat16 d_hid_lo[SLEN*DDIM];
__device__ __align__(256) __nv_bfloat16 d_pre_hi[SLEN*VDIM];
__device__ __align__(256) __nv_bfloat16 d_pre_lo[SLEN*VDIM];

// ---------------- PTX helpers -------------------------------------------------
__device__ __forceinline__ void cpa16(uint32_t d, const void* s) {
    asm volatile("cp.async.cg.shared.global [%0], [%1], 16;" :: "r"(d), "l"(s));
}
__device__ __forceinline__ void ldm_x4(uint32_t* r, uint32_t a) {
    asm volatile("ldmatrix.sync.aligned.m8n8.x4.shared.b16 {%0,%1,%2,%3}, [%4];"
                 : "=r"(r[0]), "=r"(r[1]), "=r"(r[2]), "=r"(r[3]) : "r"(a));
}
__device__ __forceinline__ void ldm_x4t(uint32_t* r, uint32_t a) {
    asm volatile("ldmatrix.sync.aligned.m8n8.x4.trans.shared.b16 {%0,%1,%2,%3}, [%4];"
                 : "=r"(r[0]), "=r"(r[1]), "=r"(r[2]), "=r"(r[3]) : "r"(a));
}
__device__ __forceinline__ void mma_bf16(float* c, const uint32_t* a, const uint32_t* b) {
    asm volatile(
        "mma.sync.aligned.m16n8k16.row.col.f32.bf16.bf16.f32 "
        "{%0,%1,%2,%3},{%4,%5,%6,%7},{%8,%9},{%0,%1,%2,%3};"
        : "+f"(c[0]), "+f"(c[1]), "+f"(c[2]), "+f"(c[3])
        : "r"(a[0]), "r"(a[1]), "r"(a[2]), "r"(a[3]), "r"(b[0]), "r"(b[1]));
}

// ---------------- hi/lo split conversion --------------------------------------
__device__ __forceinline__ void split4(float4 v, __nv_bfloat162* hi, __nv_bfloat162* lo) {
    __nv_bfloat16 h0 = __float2bfloat16(v.x), h1 = __float2bfloat16(v.y);
    __nv_bfloat16 h2 = __float2bfloat16(v.z), h3 = __float2bfloat16(v.w);
    __nv_bfloat16 l0 = __float2bfloat16(v.x - __bfloat162float(h0));
    __nv_bfloat16 l1 = __float2bfloat16(v.y - __bfloat162float(h1));
    __nv_bfloat16 l2 = __float2bfloat16(v.z - __bfloat162float(h2));
    __nv_bfloat16 l3 = __float2bfloat16(v.w - __bfloat162float(h3));
    hi[0] = __halves2bfloat162(h0, h1);
    hi[1] = __halves2bfloat162(h2, h3);
    lo[0] = __halves2bfloat162(l0, l1);
    lo[1] = __halves2bfloat162(l2, l3);
}

__global__ void split_kernel(const float4* __restrict__ x, __nv_bfloat162* __restrict__ hi,
                             __nv_bfloat162* __restrict__ lo, int n4) {
    int i = blockIdx.x * 256 + threadIdx.x;
    if (i >= n4) return;
    __nv_bfloat162 h[2], l[2];
    split4(x[i], h, l);
    hi[2 * i] = h[0]; hi[2 * i + 1] = h[1];
    lo[2 * i] = l[0]; lo[2 * i + 1] = l[1];
}

// -------------- mega-pack: qkv+bg fused weights + gate/out/hidden splits -----
#define QKV_U (ENUM*DDIM*(QKVP/4))
#define GW_U  (DDIM*VDIM/4)
#define OW_U  (VDIM*DDIM/4)
#define HID_U (SLEN*DDIM/4)
#define TOT_U (QKV_U + GW_U + OW_U + HID_U)

__global__ void pack_w_kernel(const float* __restrict__ q_w, const float* __restrict__ k_w,
                              const float* __restrict__ v_w, const float* __restrict__ b_w,
                              const float* __restrict__ a_w, const float* __restrict__ g_w,
                              const float* __restrict__ o_w, const float* __restrict__ hidden) {
    long long u = (long long)blockIdx.x * 256 + threadIdx.x;
    if (u >= TOT_U) return;
    if (u < QKV_U) {
        long long per_e = (long long)DDIM * (QKVP / 4);
        int e = (int)(u / per_e);
        long long r = u - (long long)e * per_e;
        int d = (int)(r / (QKVP / 4));
        int c4 = (int)(r - (long long)d * (QKVP / 4));
        int n = c4 * 4;
        float4 src;
        if (n < KDIM) {
            src = *(const float4*)(q_w + (size_t)d * KDIM + n);
        } else if (n < 2 * KDIM) {
            src = *(const float4*)(k_w + ((size_t)e * DDIM + d) * KDIM + (n - KDIM));
        } else if (n < QKVO) {
            src = *(const float4*)(v_w + ((size_t)e * DDIM + d) * VDIM + (n - 2 * KDIM));
        } else {
            // beta cols [6144,6150), a cols [6150,6156), zeros beyond
            float vals[4];
#pragma unroll
            for (int j = 0; j < 4; j++) {
                int c = n + j;
                if (c < QKVO + HNUM)
                    vals[j] = b_w[((size_t)e * DDIM + d) * HNUM + (c - QKVO)];
                else if (c < QKVO + 2 * HNUM)
                    vals[j] = a_w[((size_t)e * DDIM + d) * HNUM + (c - QKVO - HNUM)];
                else
                    vals[j] = 0.f;
            }
            src = make_float4(vals[0], vals[1], vals[2], vals[3]);
        }
        size_t dst = ((size_t)e * DDIM + d) * QKVP + n;
        __nv_bfloat162 h[2], l[2];
        split4(src, h, l);
        __nv_bfloat162* hp = (__nv_bfloat162*)(d_qkvw_hi + dst);
        __nv_bfloat162* lp = (__nv_bfloat162*)(d_qkvw_lo + dst);
        hp[0] = h[0]; hp[1] = h[1]; lp[0] = l[0]; lp[1] = l[1];
        return;
    }
    u -= QKV_U;
    if (u < GW_U) {
        float4 src = ((const float4*)g_w)[u];
        __nv_bfloat162 h[2], l[2]; split4(src, h, l);
        ((__nv_bfloat162*)d_gw_hi)[2 * u] = h[0]; ((__nv_bfloat162*)d_gw_hi)[2 * u + 1] = h[1];
        ((__nv_bfloat162*)d_gw_lo)[2 * u] = l[0]; ((__nv_bfloat162*)d_gw_lo)[2 * u + 1] = l[1];
        return;
    }
    u -= GW_U;
    if (u < OW_U) {
        float4 src = ((const float4*)o_w)[u];
        __nv_bfloat162 h[2], l[2]; split4(src, h, l);
        ((__nv_bfloat162*)d_ow_hi)[2 * u] = h[0]; ((__nv_bfloat162*)d_ow_hi)[2 * u + 1] = h[1];
        ((__nv_bfloat162*)d_ow_lo)[2 * u] = l[0]; ((__nv_bfloat162*)d_ow_lo)[2 * u + 1] = l[1];
        return;
    }
    u -= OW_U;
    {
        float4 src = ((const float4*)hidden)[u];
        __nv_bfloat162 h[2], l[2]; split4(src, h, l);
        ((__nv_bfloat162*)d_hid_hi)[2 * u] = h[0]; ((__nv_bfloat162*)d_hid_hi)[2 * u + 1] = h[1];
        ((__nv_bfloat162*)d_hid_lo)[2 * u] = l[0]; ((__nv_bfloat162*)d_hid_lo)[2 * u + 1] = l[1];
    }
}

// ---------------- tensor-core split-bf16 GEMM ---------------------------------
#define LDA 40
#define LDB 136
#define A_SZ (128*LDA)
#define B_SZ (32*LDB)
#define STAGE_H (2*A_SZ + 2*B_SZ)
#define GEMM_SMEM (STAGE_H*2*2)

__global__ __launch_bounds__(256, 2)
void gemm_tc(const __nv_bfloat16* __restrict__ Ahi, const __nv_bfloat16* __restrict__ Alo,
             const __nv_bfloat16* __restrict__ Bhi, const __nv_bfloat16* __restrict__ Blo,
             float* __restrict__ C, int M, int N, int K,
             long long aStride, long long bStride, long long cStride, int useM) {
    extern __shared__ __nv_bfloat16 smbuf[];
    int z = blockIdx.z;
    int mlim = useM ? d_m[z] : M;
    int row0 = blockIdx.y * 128;
    if (row0 >= mlim) return;
    int col0 = blockIdx.x * 128;
    Ahi += (size_t)z * aStride; Alo += (size_t)z * aStride;
    Bhi += (size_t)z * bStride; Blo += (size_t)z * bStride;
    C += (size_t)z * cStride;

    uint32_t sbase = (uint32_t)__cvta_generic_to_shared(smbuf);
    int t = threadIdx.x;

    int arow = t >> 1, akc = (t & 1) * 16;
    int brow = t >> 3, bnc = (t & 7) * 16;
    const __nv_bfloat16* gAh = Ahi + (size_t)(row0 + arow) * K + akc;
    const __nv_bfloat16* gAl = Alo + (size_t)(row0 + arow) * K + akc;
    const __nv_bfloat16* gBh = Bhi + (size_t)brow * N + col0 + bnc;
    const __nv_bfloat16* gBl = Blo + (size_t)brow * N + col0 + bnc;
    uint32_t dAh = sbase + (uint32_t)(arow * LDA + akc) * 2;
    uint32_t dAl = dAh + A_SZ * 2;
    uint32_t dBh = sbase + (uint32_t)(2 * A_SZ + brow * LDB + bnc) * 2;
    uint32_t dBl = dBh + B_SZ * 2;

    int lane = t & 31, wid = t >> 5;
    int wm = (wid >> 2) * 64, wn = (wid & 3) * 32;
    int aR = lane & 15, aC = (lane >> 4) * 8;
    uint32_t aOff = (uint32_t)((wm + aR) * LDA + aC) * 2;
    int bgp = lane >> 3, blr = lane & 7;
    int bR = blr + (bgp & 1) * 8, bC = (bgp >> 1) * 8;
    uint32_t bOff = (uint32_t)(bR * LDB + wn + bC) * 2;

    float acc[4][4][4];
#pragma unroll
    for (int mi = 0; mi < 4; mi++)
#pragma unroll
        for (int ni = 0; ni < 4; ni++)
#pragma unroll
            for (int j = 0; j < 4; j++) acc[mi][ni][j] = 0.f;

    int KT = K / 32;

    cpa16(dAh, gAh);           cpa16(dAh + 16, gAh + 8);
    cpa16(dAl, gAl);           cpa16(dAl + 16, gAl + 8);
    cpa16(dBh, gBh);           cpa16(dBh + 16, gBh + 8);
    cpa16(dBl, gBl);           cpa16(dBl + 16, gBl + 8);
    asm volatile("cp.async.commit_group;");

    for (int kt = 0; kt < KT; kt++) {
        if (kt + 1 < KT) {
            int k0 = (kt + 1) * 32;
            uint32_t so = (uint32_t)(((kt + 1) & 1) * STAGE_H) * 2;
            const __nv_bfloat16* a0 = gAh + k0;
            const __nv_bfloat16* a1 = gAl + k0;
            const __nv_bfloat16* b0 = gBh + (size_t)k0 * N;
            const __nv_bfloat16* b1 = gBl + (size_t)k0 * N;
            cpa16(dAh + so, a0);        cpa16(dAh + so + 16, a0 + 8);
            cpa16(dAl + so, a1);        cpa16(dAl + so + 16, a1 + 8);
            cpa16(dBh + so, b0);        cpa16(dBh + so + 16, b0 + 8);
            cpa16(dBl + so, b1);        cpa16(dBl + so + 16, b1 + 8);
            asm volatile("cp.async.commit_group;");
            asm volatile("cp.async.wait_group 1;");
        } else {
            asm volatile("cp.async.wait_group 0;");
        }
        __syncthreads();

        uint32_t s0 = sbase + (uint32_t)((kt & 1) * STAGE_H) * 2;
        uint32_t sAh = s0 + aOff;
        uint32_t sAl = sAh + (uint32_t)A_SZ * 2;
        uint32_t sBh = s0 + (uint32_t)(2 * A_SZ) * 2 + bOff;
        uint32_t sBl = sBh + (uint32_t)B_SZ * 2;

#pragma unroll
        for (int ks = 0; ks < 2; ks++) {
            uint32_t kao = (uint32_t)(ks * 16) * 2;
            uint32_t kbo = (uint32_t)(ks * 16 * LDB) * 2;
            uint32_t bh[8], bl2[8], af[16];
            ldm_x4t(bh + 0, sBh + kbo);
            ldm_x4t(bh + 4, sBh + kbo + 32);
            ldm_x4t(bl2 + 0, sBl + kbo);
            ldm_x4t(bl2 + 4, sBl + kbo + 32);
#pragma unroll
            for (int mi = 0; mi < 4; mi++)
                ldm_x4(af + mi * 4, sAh + kao + (uint32_t)(mi * 16 * LDA) * 2);
#pragma unroll
            for (int mi = 0; mi < 4; mi++)
#pragma unroll
                for (int ni = 0; ni < 4; ni++)
                    mma_bf16(acc[mi][ni], af + mi * 4, bh + (ni >> 1) * 4 + (ni & 1) * 2);
#pragma unroll
            for (int mi = 0; mi < 4; mi++)
#pragma unroll
                for (int ni = 0; ni < 4; ni++)
                    mma_bf16(acc[mi][ni], af + mi * 4, bl2 + (ni >> 1) * 4 + (ni & 1) * 2);
#pragma unroll
            for (int mi = 0; mi < 4; mi++)
                ldm_x4(af + mi * 4, sAl + kao + (uint32_t)(mi * 16 * LDA) * 2);
#pragma unroll
            for (int mi = 0; mi < 4; mi++)
#pragma unroll
                for (int ni = 0; ni < 4; ni++)
                    mma_bf16(acc[mi][ni], af + mi * 4, bh + (ni >> 1) * 4 + (ni & 1) * 2);
        }
        __syncthreads();
    }

    int gr = lane >> 2, gc = (lane & 3) * 2;
#pragma unroll
    for (int mi = 0; mi < 4; mi++) {
        int r = row0 + wm + mi * 16 + gr;
#pragma unroll
        for (int ni = 0; ni < 4; ni++) {
            float* Cp = C + (size_t)r * N + col0 + wn + ni * 8 + gc;
            if (r < mlim) {
                Cp[0] = acc[mi][ni][0];
                Cp[1] = acc[mi][ni][1];
            }
            if (r + 8 < mlim) {
                float* Cq = Cp + (size_t)8 * N;
                Cq[0] = acc[mi][ni][2];
                Cq[1] = acc[mi][ni][3];
            }
        }
    }
}

// ---------------- router ------------------------------------------------------
__global__ void router_kernel(const float* __restrict__ hidden,
                              const float* __restrict__ gate_w) {
    int s = blockIdx.x;
    int tid = threadIdx.x;
    float acc[ENUM];
#pragma unroll
    for (int e = 0; e < ENUM; e++) acc[e] = 0.f;
    const float* xr = hidden + (size_t)s * DDIM;
    for (int d = tid; d < DDIM; d += 256) {
        float x = xr[d];
        const float* w = gate_w + (size_t)d * ENUM;
#pragma unroll
        for (int e = 0; e < ENUM; e++) acc[e] += x * w[e];
    }
    __shared__ float red[ENUM][256];
#pragma unroll
    for (int e = 0; e < ENUM; e++) red[e][tid] = acc[e];
    __syncthreads();
    for (int st = 128; st > 0; st >>= 1) {
        if (tid < st) {
#pragma unroll
            for (int e = 0; e < ENUM; e++) red[e][tid] += red[e][tid + st];
        }
        __syncthreads();
    }
    if (tid == 0) {
        float l[ENUM], mx = -1e30f;
#pragma unroll
        for (int e = 0; e < ENUM; e++) { l[e] = red[e][0]; mx = fmaxf(mx, l[e]); }
        float p[ENUM], sum = 0.f;
#pragma unroll
        for (int e = 0; e < ENUM; e++) { p[e] = expf(l[e] - mx); sum += p[e]; }
#pragma unroll
        for (int e = 0; e < ENUM; e++) p[e] /= sum;
        int i0 = 0;
#pragma unroll
        for (int e = 1; e < ENUM; e++) if (p[e] > p[i0]) i0 = e;
        int i1 = -1;
#pragma unroll
        for (int e = 0; e < ENUM; e++)
            if (e != i0 && (i1 < 0 || p[e] > p[i1])) i1 = e;
        float r0 = p[i0], r1 = p[i1], rs = r0 + r1;
        d_sel[2 * s] = i0;  d_sel[2 * s + 1] = i1;
        d_rw[2 * s] = r0 / rs;  d_rw[2 * s + 1] = r1 / rs;
    }
}

// -------------- dispatch: parallel warp-per-expert ballot scan ----------------
__global__ void dispatch_kernel() {
    int e = threadIdx.x >> 5;      // warp = expert
    int lane = threadIdx.x & 31;
    // pass 1: count
    int cnt = 0;
    for (int i = lane; i < SLEN * 2; i += 32) cnt += (d_sel[i] == e);
#pragma unroll
    for (int o = 16; o; o >>= 1) cnt += __shfl_xor_sync(0xffffffffu, cnt, o);
    int drop = cnt > CAP ? cnt - CAP : 0;
    if (lane == 0) d_m[e] = cnt - drop;
    // pass 2: stable rank assignment
    int base = 0;
    for (int i0 = 0; i0 < SLEN * 2; i0 += 32) {
        int i = i0 + lane;
        bool hit = (d_sel[i] == e);
        unsigned mask = __ballot_sync(0xffffffffu, hit);
        if (hit) {
            int r = base + __popc(mask & ((1u << lane) - 1u));
            if (r >= drop) {
                int j = r - drop;
                d_tok[e * CAP + j] = i >> 1;
                d_pos[i] = e * CAP + j;
            } else {
                d_pos[i] = -1;
            }
        }
        base += __popc(mask);
    }
}

// -------------- gather + hi/lo split of activations --------------------------
__global__ void gather_split_kernel(const float* __restrict__ hidden) {
    int row = blockIdx.x;
    int e = row >> 10, t = row & 1023;
    if (t >= d_m[e]) return;
    const float4* src = (const float4*)(hidden + (size_t)d_tok[row] * DDIM);
    __nv_bfloat162* hi = (__nv_bfloat162*)(d_xg_hi + (size_t)row * DDIM);
    __nv_bfloat162* lo = (__nv_bfloat162*)(d_xg_lo + (size_t)row * DDIM);
    for (int i = threadIdx.x; i < DDIM / 4; i += 256) {
        float4 v = src[i];
        __nv_bfloat162 h[2], l[2];
        split4(v, h, l);
        hi[2 * i] = h[0]; hi[2 * i + 1] = h[1];
        lo[2 * i] = l[0]; lo[2 * i + 1] = l[1];
    }
}

// -------------- beta/g epilogue: read projected logits from qkvpre ------------
__global__ void bg_finish_kernel(const float* __restrict__ A_log,
                                 const float* __restrict__ dt_bias) {
    int idx = blockIdx.x * 256 + threadIdx.x;
    if (idx >= NROW * HNUM) return;
    int row = idx / HNUM, h = idx - row * HNUM;
    int e = row >> 10, t = row & 1023;
    if (t >= d_m[e]) return;
    float bl = d_qkvpre[(size_t)row * QKVP + QKVO + h];
    float al = d_qkvpre[(size_t)row * QKVP + QKVO + HNUM + h];
    d_beta[idx] = 1.f / (1.f + expf(-bl));
    float xx = al + dt_bias[h];
    float sp = xx > 20.f ? xx : log1pf(expf(xx));
    d_g[idx] = -expf(A_log[h]) * sp;
}

// -------------- conv + silu + l2norm (q,k) — reads fused pre buffer ----------
__global__ void convnorm_kernel(const float* __restrict__ pre, const float* __restrict__ cw,
                                float* __restrict__ out, float scale, int preOff) {
    int row = blockIdx.x;
    int h = blockIdx.y;
    int e = row >> 10, t = row & 1023;
    if (t >= d_m[e]) return;
    int tid = threadIdx.x;
    int ch = h * DKC + tid;
    float y = 0.f;
#pragma unroll
    for (int j = 0; j < 4; j++) {
        int tt = t - 3 + j;
        if (tt >= 0) y += cw[ch * 4 + j] * pre[(size_t)(row - 3 + j) * QKVP + preOff + ch];
    }
    y = y / (1.f + expf(-y));
    __shared__ float red[256];
    red[tid] = y * y;
    __syncthreads();
    for (int st = 128; st > 0; st >>= 1) {
        if (tid < st) red[tid] += red[tid + st];
        __syncthreads();
    }
    float inv = rsqrtf(red[0] + 1e-6f) * scale;
    out[(size_t)row * KDIM + ch] = y * inv;
}

// -------------- conv + silu for v — fused pre buffer --------------------------
__global__ void convv_kernel(const float* __restrict__ pre, const float* __restrict__ cw,
                             float* __restrict__ out) {
    int idx = blockIdx.x * 256 + threadIdx.x;
    int row = idx / VDIM;
    int ch = idx - row * VDIM;
    int e = row >> 10, t = row & 1023;
    if (t >= d_m[e]) return;
    float y = 0.f;
#pragma unroll
    for (int j = 0; j < 4; j++) {
        int tt = t - 3 + j;
        if (tt >= 0) y += cw[ch * 4 + j] * pre[(size_t)(row - 3 + j) * QKVP + 2 * KDIM + ch];
    }
    out[(size_t)row * VDIM + ch] = y / (1.f + expf(-y));
}

// -------------- gated delta-rule recurrence (conflict-free strided) -----------
__global__ void recur_kernel() {
    int vc = blockIdx.x;
    int h = blockIdx.y;
    int e = blockIdx.z;
    int m = d_m[e];
    __shared__ float S[32 * 256];
    __shared__ float su[32], sw[32], sd[32];
    int tid = threadIdx.x, warp = tid >> 5, lane = tid & 31;
    int v0 = warp * 4;
    for (int i = lane; i < 4 * 256; i += 32) S[v0 * 256 + i] = 0.f;
    if (lane < 4) { su[v0 + lane] = 0.f; sw[v0 + lane] = 0.f; }
    __syncwarp();
    if (m == 0) return;

    const float* kb = d_kn + (size_t)(e * CAP) * KDIM + h * DKC;
    const float* qb = d_qn + (size_t)(e * CAP) * KDIM + h * DKC;
    const float* vb = d_vn + (size_t)(e * CAP) * VDIM + h * DVC + vc * 32;
    const float* bb = d_beta + (size_t)(e * CAP) * HNUM + h;
    const float* gb = d_g + (size_t)(e * CAP) * HNUM + h;
    float* ob = d_o + (size_t)(e * CAP) * VDIM + h * DVC + vc * 32;

    float kc[8], qc[8];
#pragma unroll
    for (int j = 0; j < 8; j++) { kc[j] = kb[lane + 32 * j]; qc[j] = qb[lane + 32 * j]; }
    float beta = bb[0];
    float gv = gb[0];
    float vv = (lane < 4) ? vb[v0 + lane] : 0.f;

    for (int t = 0; t < m; t++) {
        float eg = expf(gv);
        float qk = 0.f;
#pragma unroll
        for (int j = 0; j < 8; j++) qk += kc[j] * qc[j];
#pragma unroll
        for (int o = 16; o; o >>= 1) qk += __shfl_xor_sync(0xffffffffu, qk, o);

        if (lane < 4) {
            int v = v0 + lane;
            float dd = beta * (vv - eg * su[v]);
            ob[(size_t)t * VDIM + v] = eg * sw[v] + qk * dd;
            sd[v] = dd;
        }
        __syncwarp();

        float kn2[8], qn2[8];
        float beta_n = 0.f, g_n = 0.f, vv_n = 0.f;
        if (t + 1 < m) {
            const float* kr = kb + (size_t)(t + 1) * KDIM;
            const float* qr = qb + (size_t)(t + 1) * KDIM;
#pragma unroll
            for (int j = 0; j < 8; j++) { kn2[j] = kr[lane + 32 * j]; qn2[j] = qr[lane + 32 * j]; }
            beta_n = bb[(size_t)(t + 1) * HNUM];
            g_n = gb[(size_t)(t + 1) * HNUM];
            if (lane < 4) vv_n = vb[(size_t)(t + 1) * VDIM + v0 + lane];
        } else {
#pragma unroll
            for (int j = 0; j < 8; j++) { kn2[j] = 0.f; qn2[j] = 0.f; }
        }

#pragma unroll
        for (int vi = 0; vi < 4; vi++) {
            int v = v0 + vi;
            float dd = sd[v];
            float un = 0.f, wn = 0.f;
            float* Sr = &S[v * 256];
#pragma unroll
            for (int j = 0; j < 8; j++) {
                float s2 = Sr[lane + 32 * j];
                s2 = eg * s2 + kc[j] * dd;
                Sr[lane + 32 * j] = s2;
                un += kn2[j] * s2;
                wn += qn2[j] * s2;
            }
#pragma unroll
            for (int o = 16; o; o >>= 1) {
                un += __shfl_xor_sync(0xffffffffu, un, o);
                wn += __shfl_xor_sync(0xffffffffu, wn, o);
            }
            if (lane == 0) { su[v] = un; sw[v] = wn; }
        }
        __syncwarp();
#pragma unroll
        for (int j = 0; j < 8; j++) { kc[j] = kn2[j]; qc[j] = qn2[j]; }
        beta = beta_n; gv = g_n; vv = vv_n;
    }
}

// -------------- combine + gated RMSNorm ---------------------------------------
__global__ void combine_kernel(const float* __restrict__ norm_w) {
    int s = blockIdx.x, h = blockIdx.y, tid = threadIdx.x;
    int p0 = d_pos[2 * s], p1 = d_pos[2 * s + 1];
    float r0 = d_rw[2 * s], r1 = d_rw[2 * s + 1];
    float acc[2];
    float ss = 0.f;
#pragma unroll
    for (int i = 0; i < 2; i++) {
        int v = tid + i * 256;
        float a = 0.f;
        if (p0 >= 0) a += r0 * d_o[(size_t)p0 * VDIM + h * DVC + v];
        if (p1 >= 0) a += r1 * d_o[(size_t)p1 * VDIM + h * DVC + v];
        acc[i] = a;
        ss += a * a;
    }
    __shared__ float red[256];
    red[tid] = ss;
    __syncthreads();
    for (int st = 128; st > 0; st >>= 1) {
        if (tid < st) red[tid] += red[tid + st];
        __syncthreads();
    }
    float inv = rsqrtf(red[0] / (float)DVC + 1e-5f);
#pragma unroll
    for (int i = 0; i < 2; i++) {
        int v = tid + i * 256;
        float gg = d_gg[(size_t)s * VDIM + h * DVC + v];
        float sg = gg / (1.f + expf(-gg));
        d_pre[(size_t)s * VDIM + h * DVC + v] = acc[i] * inv * norm_w[v] * sg;
    }
}

// ----------------------------- launch -----------------------------------------
extern "C" void kernel_launch(void* const* d_in, const int* in_sizes, int n_in,
                              void* d_out, int out_size) {
    const float* hidden  = (const float*)d_in[0];
    const float* q_w     = (const float*)d_in[1];
    const float* gate_w  = (const float*)d_in[2];
    const float* k_w     = (const float*)d_in[3];
    const float* v_w     = (const float*)d_in[4];
    const float* b_w     = (const float*)d_in[5];
    const float* a_w     = (const float*)d_in[6];
    const float* A_log   = (const float*)d_in[7];
    const float* dt_bias = (const float*)d_in[8];
    const float* qcw     = (const float*)d_in[9];
    const float* kcw     = (const float*)d_in[10];
    const float* vcw     = (const float*)d_in[11];
    const float* g_w     = (const float*)d_in[12];
    const float* norm_w  = (const float*)d_in[13];
    const float* o_w     = (const float*)d_in[14];

    float* qkvpre = 0; float* gg = 0; float* pre = 0;
    cudaGetSymbolAddress((void**)&qkvpre, d_qkvpre);
    cudaGetSymbolAddress((void**)&gg, d_gg);
    cudaGetSymbolAddress((void**)&pre, d_pre);
    float* qn = 0; float* kn = 0; float* vn = 0;
    cudaGetSymbolAddress((void**)&qn, d_qn);
    cudaGetSymbolAddress((void**)&kn, d_kn);
    cudaGetSymbolAddress((void**)&vn, d_vn);

    __nv_bfloat16* xgh = 0; __nv_bfloat16* xgl = 0;
    __nv_bfloat16* qkvh = 0; __nv_bfloat16* qkvl = 0;
    __nv_bfloat16* gwh = 0; __nv_bfloat16* gwl = 0;
    __nv_bfloat16* owh = 0; __nv_bfloat16* owl = 0;
    __nv_bfloat16* hih = 0; __nv_bfloat16* hil = 0;
    __nv_bfloat16* prh = 0; __nv_bfloat16* prl = 0;
    cudaGetSymbolAddress((void**)&xgh, d_xg_hi);
    cudaGetSymbolAddress((void**)&xgl, d_xg_lo);
    cudaGetSymbolAddress((void**)&qkvh, d_qkvw_hi);
    cudaGetSymbolAddress((void**)&qkvl, d_qkvw_lo);
    cudaGetSymbolAddress((void**)&gwh, d_gw_hi);
    cudaGetSymbolAddress((void**)&gwl, d_gw_lo);
    cudaGetSymbolAddress((void**)&owh, d_ow_hi);
    cudaGetSymbolAddress((void**)&owl, d_ow_lo);
    cudaGetSymbolAddress((void**)&hih, d_hid_hi);
    cudaGetSymbolAddress((void**)&hil, d_hid_lo);
    cudaGetSymbolAddress((void**)&prh, d_pre_hi);
    cudaGetSymbolAddress((void**)&prl, d_pre_lo);

    cudaFuncSetAttribute(gemm_tc, cudaFuncAttributeMaxDynamicSharedMemorySize, GEMM_SMEM);

    // 1: pack all weights (+bg cols, +hidden split) — no deps
    pack_w_kernel<<<(int)((TOT_U + 255) / 256), 256>>>(q_w, k_w, v_w, b_w, a_w, g_w, o_w, hidden);
    // 2-3: routing
    router_kernel<<<SLEN, 256>>>(hidden, gate_w);
    dispatch_kernel<<<1, 256>>>();
    // 4: gate projection
    gemm_tc<<<dim3(VDIM / 128, SLEN / 128, 1), 256, GEMM_SMEM>>>(
        hih, hil, gwh, gwl, gg, SLEN, VDIM, DDIM, 0LL, 0LL, 0LL, 0);
    // 5: gather + activation split
    gather_split_kernel<<<NROW, 256>>>(hidden);
    // 6: fused qkv+bg per-expert projection
    gemm_tc<<<dim3(QKVP / 128, CAP / 128, ENUM), 256, GEMM_SMEM>>>(
        xgh, xgl, qkvh, qkvl, qkvpre, CAP, QKVP, DDIM,
        (long long)CAP * DDIM, (long long)DDIM * QKVP, (long long)CAP * QKVP, 1);

    bg_finish_kernel<<<(NROW * HNUM + 255) / 256, 256>>>(A_log, dt_bias);

    dim3 gc(NROW, HNUM);
    convnorm_kernel<<<gc, 256>>>(qkvpre, qcw, qn, 0.0625f, 0);      // q at offset 0
    convnorm_kernel<<<gc, 256>>>(qkvpre, kcw, kn, 1.0f, KDIM);      // k at offset 1536
    convv_kernel<<<(NROW * (VDIM / 256)), 256>>>(qkvpre, vcw, vn);  // v at offset 3072

    recur_kernel<<<dim3(DVC / 32, HNUM, ENUM), 256>>>();

    combine_kernel<<<dim3(SLEN, HNUM), 256>>>(norm_w);
    {
        int n4 = SLEN * VDIM / 4;
        split_kernel<<<(n4 + 255) / 256, 256>>>((const float4*)pre,
                                                (__nv_bfloat162*)prh, (__nv_bfloat162*)prl, n4);
    }
    gemm_tc<<<dim3(DDIM / 128, SLEN / 128, 1), 256, GEMM_SMEM>>>(
        prh, prl, owh, owl, (float*)d_out, SLEN, DDIM, VDIM, 0LL, 0LL, 0LL, 0);
}

// round 8
// speedup vs baseline: 1.2281x; 1.0181x over previous
#include <cuda_runtime.h>
#include <cuda_bf16.h>
#include <stdint.h>
#include <math.h>

#define SLEN 1024
#define DDIM 2048
#define ENUM 8
#define HNUM 6
#define DKC  256
#define DVC  512
#define KDIM 1536   // HNUM*DKC
#define VDIM 3072   // HNUM*DVC
#define QKVO 6144   // q+k+v data cols
#define QKVP 6272   // padded: + 12 beta/g cols + zero pad (49*128)
#define CAP  1024
#define NROW (ENUM*CAP)

// ---------------- scratch (device globals; no allocation in kernel_launch) ----
__device__ int   d_sel[SLEN*2];
__device__ float d_rw [SLEN*2];
__device__ int   d_m  [ENUM];
__device__ int   d_tok[NROW];
__device__ int   d_pos[SLEN*2];
__device__ float d_qkvpre[(size_t)NROW*QKVP];
__device__ float d_qn  [NROW*KDIM];
__device__ float d_kn  [NROW*KDIM];
__device__ float d_vn  [NROW*VDIM];
__device__ float d_beta[NROW*HNUM];
__device__ float d_g   [NROW*HNUM];
__device__ float d_o   [NROW*VDIM];
__device__ float d_gg  [SLEN*VDIM];

// bf16 hi/lo split buffers
__device__ __align__(256) __nv_bfloat16 d_xg_hi[NROW*DDIM];
__device__ __align__(256) __nv_bfloat16 d_xg_lo[NROW*DDIM];
__device__ __align__(256) __nv_bfloat16 d_qkvw_hi[(size_t)ENUM*DDIM*QKVP];
__device__ __align__(256) __nv_bfloat16 d_qkvw_lo[(size_t)ENUM*DDIM*QKVP];
__device__ __align__(256) __nv_bfloat16 d_gw_hi[DDIM*VDIM];
__device__ __align__(256) __nv_bfloat16 d_gw_lo[DDIM*VDIM];
__device__ __align__(256) __nv_bfloat16 d_ow_hi[VDIM*DDIM];
__device__ __align__(256) __nv_bfloat16 d_ow_lo[VDIM*DDIM];
__device__ __align__(256) __nv_bfloat16 d_hid_hi[SLEN*DDIM];
__device__ __align__(256) __nv_bfloat16 d_hid_lo[SLEN*DDIM];
__device__ __align__(256) __nv_bfloat16 d_pre_hi[SLEN*VDIM];
__device__ __align__(256) __nv_bfloat16 d_pre_lo[SLEN*VDIM];

// ---------------- PTX helpers -------------------------------------------------
__device__ __forceinline__ void cpa16(uint32_t d, const void* s) {
    asm volatile("cp.async.cg.shared.global [%0], [%1], 16;" :: "r"(d), "l"(s));
}
__device__ __forceinline__ void ldm_x4(uint32_t* r, uint32_t a) {
    asm volatile("ldmatrix.sync.aligned.m8n8.x4.shared.b16 {%0,%1,%2,%3}, [%4];"
                 : "=r"(r[0]), "=r"(r[1]), "=r"(r[2]), "=r"(r[3]) : "r"(a));
}
__device__ __forceinline__ void ldm_x4t(uint32_t* r, uint32_t a) {
    asm volatile("ldmatrix.sync.aligned.m8n8.x4.trans.shared.b16 {%0,%1,%2,%3}, [%4];"
                 : "=r"(r[0]), "=r"(r[1]), "=r"(r[2]), "=r"(r[3]) : "r"(a));
}
__device__ __forceinline__ void mma_bf16(float* c, const uint32_t* a, const uint32_t* b) {
    asm volatile(
        "mma.sync.aligned.m16n8k16.row.col.f32.bf16.bf16.f32 "
        "{%0,%1,%2,%3},{%4,%5,%6,%7},{%8,%9},{%0,%1,%2,%3};"
        : "+f"(c[0]), "+f"(c[1]), "+f"(c[2]), "+f"(c[3])
        : "r"(a[0]), "r"(a[1]), "r"(a[2]), "r"(a[3]), "r"(b[0]), "r"(b[1]));
}

// ---------------- hi/lo split conversion --------------------------------------
__device__ __forceinline__ void split4(float4 v, __nv_bfloat162* hi, __nv_bfloat162* lo) {
    __nv_bfloat16 h0 = __float2bfloat16(v.x), h1 = __float2bfloat16(v.y);
    __nv_bfloat16 h2 = __float2bfloat16(v.z), h3 = __float2bfloat16(v.w);
    __nv_bfloat16 l0 = __float2bfloat16(v.x - __bfloat162float(h0));
    __nv_bfloat16 l1 = __float2bfloat16(v.y - __bfloat162float(h1));
    __nv_bfloat16 l2 = __float2bfloat16(v.z - __bfloat162float(h2));
    __nv_bfloat16 l3 = __float2bfloat16(v.w - __bfloat162float(h3));
    hi[0] = __halves2bfloat162(h0, h1);
    hi[1] = __halves2bfloat162(h2, h3);
    lo[0] = __halves2bfloat162(l0, l1);
    lo[1] = __halves2bfloat162(l2, l3);
}

// -------------- mega-pack: qkv+bg fused weights + gate/out/hidden splits -----
#define QKV_U (ENUM*DDIM*(QKVP/4))
#define GW_U  (DDIM*VDIM/4)
#define OW_U  (VDIM*DDIM/4)
#define HID_U (SLEN*DDIM/4)
#define TOT_U (QKV_U + GW_U + OW_U + HID_U)

__global__ void pack_w_kernel(const float* __restrict__ q_w, const float* __restrict__ k_w,
                              const float* __restrict__ v_w, const float* __restrict__ b_w,
                              const float* __restrict__ a_w, const float* __restrict__ g_w,
                              const float* __restrict__ o_w, const float* __restrict__ hidden) {
    long long u = (long long)blockIdx.x * 256 + threadIdx.x;
    if (u >= TOT_U) return;
    if (u < QKV_U) {
        long long per_e = (long long)DDIM * (QKVP / 4);
        int e = (int)(u / per_e);
        long long r = u - (long long)e * per_e;
        int d = (int)(r / (QKVP / 4));
        int c4 = (int)(r - (long long)d * (QKVP / 4));
        int n = c4 * 4;
        float4 src;
        if (n < KDIM) {
            src = *(const float4*)(q_w + (size_t)d * KDIM + n);
        } else if (n < 2 * KDIM) {
            src = *(const float4*)(k_w + ((size_t)e * DDIM + d) * KDIM + (n - KDIM));
        } else if (n < QKVO) {
            src = *(const float4*)(v_w + ((size_t)e * DDIM + d) * VDIM + (n - 2 * KDIM));
        } else {
            float vals[4];
#pragma unroll
            for (int j = 0; j < 4; j++) {
                int c = n + j;
                if (c < QKVO + HNUM)
                    vals[j] = b_w[((size_t)e * DDIM + d) * HNUM + (c - QKVO)];
                else if (c < QKVO + 2 * HNUM)
                    vals[j] = a_w[((size_t)e * DDIM + d) * HNUM + (c - QKVO - HNUM)];
                else
                    vals[j] = 0.f;
            }
            src = make_float4(vals[0], vals[1], vals[2], vals[3]);
        }
        size_t dst = ((size_t)e * DDIM + d) * QKVP + n;
        __nv_bfloat162 h[2], l[2];
        split4(src, h, l);
        __nv_bfloat162* hp = (__nv_bfloat162*)(d_qkvw_hi + dst);
        __nv_bfloat162* lp = (__nv_bfloat162*)(d_qkvw_lo + dst);
        hp[0] = h[0]; hp[1] = h[1]; lp[0] = l[0]; lp[1] = l[1];
        return;
    }
    u -= QKV_U;
    if (u < GW_U) {
        float4 src = ((const float4*)g_w)[u];
        __nv_bfloat162 h[2], l[2]; split4(src, h, l);
        ((__nv_bfloat162*)d_gw_hi)[2 * u] = h[0]; ((__nv_bfloat162*)d_gw_hi)[2 * u + 1] = h[1];
        ((__nv_bfloat162*)d_gw_lo)[2 * u] = l[0]; ((__nv_bfloat162*)d_gw_lo)[2 * u + 1] = l[1];
        return;
    }
    u -= GW_U;
    if (u < OW_U) {
        float4 src = ((const float4*)o_w)[u];
        __nv_bfloat162 h[2], l[2]; split4(src, h, l);
        ((__nv_bfloat162*)d_ow_hi)[2 * u] = h[0]; ((__nv_bfloat162*)d_ow_hi)[2 * u + 1] = h[1];
        ((__nv_bfloat162*)d_ow_lo)[2 * u] = l[0]; ((__nv_bfloat162*)d_ow_lo)[2 * u + 1] = l[1];
        return;
    }
    u -= OW_U;
    {
        float4 src = ((const float4*)hidden)[u];
        __nv_bfloat162 h[2], l[2]; split4(src, h, l);
        ((__nv_bfloat162*)d_hid_hi)[2 * u] = h[0]; ((__nv_bfloat162*)d_hid_hi)[2 * u + 1] = h[1];
        ((__nv_bfloat162*)d_hid_lo)[2 * u] = l[0]; ((__nv_bfloat162*)d_hid_lo)[2 * u + 1] = l[1];
    }
}

// ---------------- tensor-core split-bf16 GEMM (3-stage cp.async) --------------
#define LDA 40
#define LDB 136
#define A_SZ (128*LDA)
#define B_SZ (32*LDB)
#define STAGE_H (2*A_SZ + 2*B_SZ)
#define NSTAGE 3
#define GEMM_SMEM (STAGE_H*2*NSTAGE)

__global__ __launch_bounds__(256, 2)
void gemm_tc(const __nv_bfloat16* __restrict__ Ahi, const __nv_bfloat16* __restrict__ Alo,
             const __nv_bfloat16* __restrict__ Bhi, const __nv_bfloat16* __restrict__ Blo,
             float* __restrict__ C, int M, int N, int K,
             long long aStride, long long bStride, long long cStride, int useM) {
    extern __shared__ __nv_bfloat16 smbuf[];
    int z = blockIdx.z;
    int mlim = useM ? d_m[z] : M;
    int row0 = blockIdx.y * 128;
    if (row0 >= mlim) return;
    int col0 = blockIdx.x * 128;
    Ahi += (size_t)z * aStride; Alo += (size_t)z * aStride;
    Bhi += (size_t)z * bStride; Blo += (size_t)z * bStride;
    C += (size_t)z * cStride;

    uint32_t sbase = (uint32_t)__cvta_generic_to_shared(smbuf);
    int t = threadIdx.x;

    int arow = t >> 1, akc = (t & 1) * 16;
    int brow = t >> 3, bnc = (t & 7) * 16;
    const __nv_bfloat16* gAh = Ahi + (size_t)(row0 + arow) * K + akc;
    const __nv_bfloat16* gAl = Alo + (size_t)(row0 + arow) * K + akc;
    const __nv_bfloat16* gBh = Bhi + (size_t)brow * N + col0 + bnc;
    const __nv_bfloat16* gBl = Blo + (size_t)brow * N + col0 + bnc;
    uint32_t dAh = sbase + (uint32_t)(arow * LDA + akc) * 2;
    uint32_t dAl = dAh + A_SZ * 2;
    uint32_t dBh = sbase + (uint32_t)(2 * A_SZ + brow * LDB + bnc) * 2;
    uint32_t dBl = dBh + B_SZ * 2;

    int lane = t & 31, wid = t >> 5;
    int wm = (wid >> 2) * 64, wn = (wid & 3) * 32;
    int aR = lane & 15, aC = (lane >> 4) * 8;
    uint32_t aOff = (uint32_t)((wm + aR) * LDA + aC) * 2;
    int bgp = lane >> 3, blr = lane & 7;
    int bR = blr + (bgp & 1) * 8, bC = (bgp >> 1) * 8;
    uint32_t bOff = (uint32_t)(bR * LDB + wn + bC) * 2;

    float acc[4][4][4];
#pragma unroll
    for (int mi = 0; mi < 4; mi++)
#pragma unroll
        for (int ni = 0; ni < 4; ni++)
#pragma unroll
            for (int j = 0; j < 4; j++) acc[mi][ni][j] = 0.f;

    int KT = K / 32;

    auto load_stage = [&](int ktl) {
        int k0 = ktl * 32;
        uint32_t so = (uint32_t)((ktl % NSTAGE) * STAGE_H) * 2;
        const __nv_bfloat16* a0 = gAh + k0;
        const __nv_bfloat16* a1 = gAl + k0;
        const __nv_bfloat16* b0 = gBh + (size_t)k0 * N;
        const __nv_bfloat16* b1 = gBl + (size_t)k0 * N;
        cpa16(dAh + so, a0);        cpa16(dAh + so + 16, a0 + 8);
        cpa16(dAl + so, a1);        cpa16(dAl + so + 16, a1 + 8);
        cpa16(dBh + so, b0);        cpa16(dBh + so + 16, b0 + 8);
        cpa16(dBl + so, b1);        cpa16(dBl + so + 16, b1 + 8);
        asm volatile("cp.async.commit_group;");
    };

    // prologue: stages 0 and 1 in flight
    load_stage(0);
    if (KT > 1) load_stage(1);

    for (int kt = 0; kt < KT; kt++) {
        // ensure group kt complete (leave at most 1 newer group outstanding)
        if (kt + 1 < KT) {
            asm volatile("cp.async.wait_group 1;");
        } else {
            asm volatile("cp.async.wait_group 0;");
        }
        __syncthreads();                 // single barrier per k-tile
        if (kt + 2 < KT) load_stage(kt + 2);

        uint32_t s0 = sbase + (uint32_t)((kt % NSTAGE) * STAGE_H) * 2;
        uint32_t sAh = s0 + aOff;
        uint32_t sAl = sAh + (uint32_t)A_SZ * 2;
        uint32_t sBh = s0 + (uint32_t)(2 * A_SZ) * 2 + bOff;
        uint32_t sBl = sBh + (uint32_t)B_SZ * 2;

#pragma unroll
        for (int ks = 0; ks < 2; ks++) {
            uint32_t kao = (uint32_t)(ks * 16) * 2;
            uint32_t kbo = (uint32_t)(ks * 16 * LDB) * 2;
            uint32_t bh[8], bl2[8], af[16];
            ldm_x4t(bh + 0, sBh + kbo);
            ldm_x4t(bh + 4, sBh + kbo + 32);
            ldm_x4t(bl2 + 0, sBl + kbo);
            ldm_x4t(bl2 + 4, sBl + kbo + 32);
#pragma unroll
            for (int mi = 0; mi < 4; mi++)
                ldm_x4(af + mi * 4, sAh + kao + (uint32_t)(mi * 16 * LDA) * 2);
#pragma unroll
            for (int mi = 0; mi < 4; mi++)
#pragma unroll
                for (int ni = 0; ni < 4; ni++)
                    mma_bf16(acc[mi][ni], af + mi * 4, bh + (ni >> 1) * 4 + (ni & 1) * 2);
#pragma unroll
            for (int mi = 0; mi < 4; mi++)
#pragma unroll
                for (int ni = 0; ni < 4; ni++)
                    mma_bf16(acc[mi][ni], af + mi * 4, bl2 + (ni >> 1) * 4 + (ni & 1) * 2);
#pragma unroll
            for (int mi = 0; mi < 4; mi++)
                ldm_x4(af + mi * 4, sAl + kao + (uint32_t)(mi * 16 * LDA) * 2);
#pragma unroll
            for (int mi = 0; mi < 4; mi++)
#pragma unroll
                for (int ni = 0; ni < 4; ni++)
                    mma_bf16(acc[mi][ni], af + mi * 4, bh + (ni >> 1) * 4 + (ni & 1) * 2);
        }
    }

    int gr = lane >> 2, gc = (lane & 3) * 2;
#pragma unroll
    for (int mi = 0; mi < 4; mi++) {
        int r = row0 + wm + mi * 16 + gr;
#pragma unroll
        for (int ni = 0; ni < 4; ni++) {
            float* Cp = C + (size_t)r * N + col0 + wn + ni * 8 + gc;
            if (r < mlim) {
                Cp[0] = acc[mi][ni][0];
                Cp[1] = acc[mi][ni][1];
            }
            if (r + 8 < mlim) {
                float* Cq = Cp + (size_t)8 * N;
                Cq[0] = acc[mi][ni][2];
                Cq[1] = acc[mi][ni][3];
            }
        }
    }
}

// ---------------- router ------------------------------------------------------
__global__ void router_kernel(const float* __restrict__ hidden,
                              const float* __restrict__ gate_w) {
    int s = blockIdx.x;
    int tid = threadIdx.x;
    float acc[ENUM];
#pragma unroll
    for (int e = 0; e < ENUM; e++) acc[e] = 0.f;
    const float* xr = hidden + (size_t)s * DDIM;
    for (int d = tid; d < DDIM; d += 256) {
        float x = xr[d];
        const float* w = gate_w + (size_t)d * ENUM;
#pragma unroll
        for (int e = 0; e < ENUM; e++) acc[e] += x * w[e];
    }
    __shared__ float red[ENUM][256];
#pragma unroll
    for (int e = 0; e < ENUM; e++) red[e][tid] = acc[e];
    __syncthreads();
    for (int st = 128; st > 0; st >>= 1) {
        if (tid < st) {
#pragma unroll
            for (int e = 0; e < ENUM; e++) red[e][tid] += red[e][tid + st];
        }
        __syncthreads();
    }
    if (tid == 0) {
        float l[ENUM], mx = -1e30f;
#pragma unroll
        for (int e = 0; e < ENUM; e++) { l[e] = red[e][0]; mx = fmaxf(mx, l[e]); }
        float p[ENUM], sum = 0.f;
#pragma unroll
        for (int e = 0; e < ENUM; e++) { p[e] = expf(l[e] - mx); sum += p[e]; }
#pragma unroll
        for (int e = 0; e < ENUM; e++) p[e] /= sum;
        int i0 = 0;
#pragma unroll
        for (int e = 1; e < ENUM; e++) if (p[e] > p[i0]) i0 = e;
        int i1 = -1;
#pragma unroll
        for (int e = 0; e < ENUM; e++)
            if (e != i0 && (i1 < 0 || p[e] > p[i1])) i1 = e;
        float r0 = p[i0], r1 = p[i1], rs = r0 + r1;
        d_sel[2 * s] = i0;  d_sel[2 * s + 1] = i1;
        d_rw[2 * s] = r0 / rs;  d_rw[2 * s + 1] = r1 / rs;
    }
}

// -------------- dispatch: parallel warp-per-expert ballot scan ----------------
__global__ void dispatch_kernel() {
    int e = threadIdx.x >> 5;
    int lane = threadIdx.x & 31;
    int cnt = 0;
    for (int i = lane; i < SLEN * 2; i += 32) cnt += (d_sel[i] == e);
#pragma unroll
    for (int o = 16; o; o >>= 1) cnt += __shfl_xor_sync(0xffffffffu, cnt, o);
    int drop = cnt > CAP ? cnt - CAP : 0;
    if (lane == 0) d_m[e] = cnt - drop;
    int base = 0;
    for (int i0 = 0; i0 < SLEN * 2; i0 += 32) {
        int i = i0 + lane;
        bool hit = (d_sel[i] == e);
        unsigned mask = __ballot_sync(0xffffffffu, hit);
        if (hit) {
            int r = base + __popc(mask & ((1u << lane) - 1u));
            if (r >= drop) {
                int j = r - drop;
                d_tok[e * CAP + j] = i >> 1;
                d_pos[i] = e * CAP + j;
            } else {
                d_pos[i] = -1;
            }
        }
        base += __popc(mask);
    }
}

// -------------- gather + hi/lo split of activations --------------------------
__global__ void gather_split_kernel(const float* __restrict__ hidden) {
    int row = blockIdx.x;
    int e = row >> 10, t = row & 1023;
    if (t >= d_m[e]) return;
    const float4* src = (const float4*)(hidden + (size_t)d_tok[row] * DDIM);
    __nv_bfloat162* hi = (__nv_bfloat162*)(d_xg_hi + (size_t)row * DDIM);
    __nv_bfloat162* lo = (__nv_bfloat162*)(d_xg_lo + (size_t)row * DDIM);
    for (int i = threadIdx.x; i < DDIM / 4; i += 256) {
        float4 v = src[i];
        __nv_bfloat162 h[2], l[2];
        split4(v, h, l);
        hi[2 * i] = h[0]; hi[2 * i + 1] = h[1];
        lo[2 * i] = l[0]; lo[2 * i + 1] = l[1];
    }
}

// -------------- beta/g epilogue: read projected logits from qkvpre ------------
__global__ void bg_finish_kernel(const float* __restrict__ A_log,
                                 const float* __restrict__ dt_bias) {
    int idx = blockIdx.x * 256 + threadIdx.x;
    if (idx >= NROW * HNUM) return;
    int row = idx / HNUM, h = idx - row * HNUM;
    int e = row >> 10, t = row & 1023;
    if (t >= d_m[e]) return;
    float bl = d_qkvpre[(size_t)row * QKVP + QKVO + h];
    float al = d_qkvpre[(size_t)row * QKVP + QKVO + HNUM + h];
    d_beta[idx] = 1.f / (1.f + expf(-bl));
    float xx = al + dt_bias[h];
    float sp = xx > 20.f ? xx : log1pf(expf(xx));
    d_g[idx] = -expf(A_log[h]) * sp;
}

// -------------- conv + silu + l2norm (q,k) — reads fused pre buffer ----------
__global__ void convnorm_kernel(const float* __restrict__ pre, const float* __restrict__ cw,
                                float* __restrict__ out, float scale, int preOff) {
    int row = blockIdx.x;
    int h = blockIdx.y;
    int e = row >> 10, t = row & 1023;
    if (t >= d_m[e]) return;
    int tid = threadIdx.x;
    int ch = h * DKC + tid;
    float y = 0.f;
#pragma unroll
    for (int j = 0; j < 4; j++) {
        int tt = t - 3 + j;
        if (tt >= 0) y += cw[ch * 4 + j] * pre[(size_t)(row - 3 + j) * QKVP + preOff + ch];
    }
    y = y / (1.f + expf(-y));
    __shared__ float red[256];
    red[tid] = y * y;
    __syncthreads();
    for (int st = 128; st > 0; st >>= 1) {
        if (tid < st) red[tid] += red[tid + st];
        __syncthreads();
    }
    float inv = rsqrtf(red[0] + 1e-6f) * scale;
    out[(size_t)row * KDIM + ch] = y * inv;
}

// -------------- conv + silu for v — fused pre buffer --------------------------
__global__ void convv_kernel(const float* __restrict__ pre, const float* __restrict__ cw,
                             float* __restrict__ out) {
    int idx = blockIdx.x * 256 + threadIdx.x;
    int row = idx / VDIM;
    int ch = idx - row * VDIM;
    int e = row >> 10, t = row & 1023;
    if (t >= d_m[e]) return;
    float y = 0.f;
#pragma unroll
    for (int j = 0; j < 4; j++) {
        int tt = t - 3 + j;
        if (tt >= 0) y += cw[ch * 4 + j] * pre[(size_t)(row - 3 + j) * QKVP + 2 * KDIM + ch];
    }
    out[(size_t)row * VDIM + ch] = y / (1.f + expf(-y));
}

// -------------- gated delta-rule recurrence (conflict-free strided) -----------
__global__ void recur_kernel() {
    int vc = blockIdx.x;
    int h = blockIdx.y;
    int e = blockIdx.z;
    int m = d_m[e];
    __shared__ float S[32 * 256];
    __shared__ float su[32], sw[32], sd[32];
    int tid = threadIdx.x, warp = tid >> 5, lane = tid & 31;
    int v0 = warp * 4;
    for (int i = lane; i < 4 * 256; i += 32) S[v0 * 256 + i] = 0.f;
    if (lane < 4) { su[v0 + lane] = 0.f; sw[v0 + lane] = 0.f; }
    __syncwarp();
    if (m == 0) return;

    const float* kb = d_kn + (size_t)(e * CAP) * KDIM + h * DKC;
    const float* qb = d_qn + (size_t)(e * CAP) * KDIM + h * DKC;
    const float* vb = d_vn + (size_t)(e * CAP) * VDIM + h * DVC + vc * 32;
    const float* bb = d_beta + (size_t)(e * CAP) * HNUM + h;
    const float* gb = d_g + (size_t)(e * CAP) * HNUM + h;
    float* ob = d_o + (size_t)(e * CAP) * VDIM + h * DVC + vc * 32;

    float kc[8], qc[8];
#pragma unroll
    for (int j = 0; j < 8; j++) { kc[j] = kb[lane + 32 * j]; qc[j] = qb[lane + 32 * j]; }
    float beta = bb[0];
    float gv = gb[0];
    float vv = (lane < 4) ? vb[v0 + lane] : 0.f;

    for (int t = 0; t < m; t++) {
        float eg = expf(gv);
        float qk = 0.f;
#pragma unroll
        for (int j = 0; j < 8; j++) qk += kc[j] * qc[j];
#pragma unroll
        for (int o = 16; o; o >>= 1) qk += __shfl_xor_sync(0xffffffffu, qk, o);

        if (lane < 4) {
            int v = v0 + lane;
            float dd = beta * (vv - eg * su[v]);
            ob[(size_t)t * VDIM + v] = eg * sw[v] + qk * dd;
            sd[v] = dd;
        }
        __syncwarp();

        float kn2[8], qn2[8];
        float beta_n = 0.f, g_n = 0.f, vv_n = 0.f;
        if (t + 1 < m) {
            const float* kr = kb + (size_t)(t + 1) * KDIM;
            const float* qr = qb + (size_t)(t + 1) * KDIM;
#pragma unroll
            for (int j = 0; j < 8; j++) { kn2[j] = kr[lane + 32 * j]; qn2[j] = qr[lane + 32 * j]; }
            beta_n = bb[(size_t)(t + 1) * HNUM];
            g_n = gb[(size_t)(t + 1) * HNUM];
            if (lane < 4) vv_n = vb[(size_t)(t + 1) * VDIM + v0 + lane];
        } else {
#pragma unroll
            for (int j = 0; j < 8; j++) { kn2[j] = 0.f; qn2[j] = 0.f; }
        }

#pragma unroll
        for (int vi = 0; vi < 4; vi++) {
            int v = v0 + vi;
            float dd = sd[v];
            float un = 0.f, wn = 0.f;
            float* Sr = &S[v * 256];
#pragma unroll
            for (int j = 0; j < 8; j++) {
                float s2 = Sr[lane + 32 * j];
                s2 = eg * s2 + kc[j] * dd;
                Sr[lane + 32 * j] = s2;
                un += kn2[j] * s2;
                wn += qn2[j] * s2;
            }
#pragma unroll
            for (int o = 16; o; o >>= 1) {
                un += __shfl_xor_sync(0xffffffffu, un, o);
                wn += __shfl_xor_sync(0xffffffffu, wn, o);
            }
            if (lane == 0) { su[v] = un; sw[v] = wn; }
        }
        __syncwarp();
#pragma unroll
        for (int j = 0; j < 8; j++) { kc[j] = kn2[j]; qc[j] = qn2[j]; }
        beta = beta_n; gv = g_n; vv = vv_n;
    }
}

// -------------- combine + gated RMSNorm + bf16 hi/lo (fused) ------------------
__global__ void combine_kernel(const float* __restrict__ norm_w) {
    int s = blockIdx.x, h = blockIdx.y, tid = threadIdx.x;
    int p0 = d_pos[2 * s], p1 = d_pos[2 * s + 1];
    float r0 = d_rw[2 * s], r1 = d_rw[2 * s + 1];
    float acc[2];
    float ss = 0.f;
#pragma unroll
    for (int i = 0; i < 2; i++) {
        int v = tid + i * 256;
        float a = 0.f;
        if (p0 >= 0) a += r0 * d_o[(size_t)p0 * VDIM + h * DVC + v];
        if (p1 >= 0) a += r1 * d_o[(size_t)p1 * VDIM + h * DVC + v];
        acc[i] = a;
        ss += a * a;
    }
    __shared__ float red[256];
    red[tid] = ss;
    __syncthreads();
    for (int st = 128; st > 0; st >>= 1) {
        if (tid < st) red[tid] += red[tid + st];
        __syncthreads();
    }
    float inv = rsqrtf(red[0] / (float)DVC + 1e-5f);
#pragma unroll
    for (int i = 0; i < 2; i++) {
        int v = tid + i * 256;
        float gg = d_gg[(size_t)s * VDIM + h * DVC + v];
        float sg = gg / (1.f + expf(-gg));
        float val = acc[i] * inv * norm_w[v] * sg;
        __nv_bfloat16 hb = __float2bfloat16(val);
        __nv_bfloat16 lb = __float2bfloat16(val - __bfloat162float(hb));
        size_t idx = (size_t)s * VDIM + h * DVC + v;
        d_pre_hi[idx] = hb;
        d_pre_lo[idx] = lb;
    }
}

// ----------------------------- launch -----------------------------------------
extern "C" void kernel_launch(void* const* d_in, const int* in_sizes, int n_in,
                              void* d_out, int out_size) {
    const float* hidden  = (const float*)d_in[0];
    const float* q_w     = (const float*)d_in[1];
    const float* gate_w  = (const float*)d_in[2];
    const float* k_w     = (const float*)d_in[3];
    const float* v_w     = (const float*)d_in[4];
    const float* b_w     = (const float*)d_in[5];
    const float* a_w     = (const float*)d_in[6];
    const float* A_log   = (const float*)d_in[7];
    const float* dt_bias = (const float*)d_in[8];
    const float* qcw     = (const float*)d_in[9];
    const float* kcw     = (const float*)d_in[10];
    const float* vcw     = (const float*)d_in[11];
    const float* g_w     = (const float*)d_in[12];
    const float* norm_w  = (const float*)d_in[13];
    const float* o_w     = (const float*)d_in[14];

    float* qkvpre = 0; float* gg = 0;
    cudaGetSymbolAddress((void**)&qkvpre, d_qkvpre);
    cudaGetSymbolAddress((void**)&gg, d_gg);
    float* qn = 0; float* kn = 0; float* vn = 0;
    cudaGetSymbolAddress((void**)&qn, d_qn);
    cudaGetSymbolAddress((void**)&kn, d_kn);
    cudaGetSymbolAddress((void**)&vn, d_vn);

    __nv_bfloat16* xgh = 0; __nv_bfloat16* xgl = 0;
    __nv_bfloat16* qkvh = 0; __nv_bfloat16* qkvl = 0;
    __nv_bfloat16* gwh = 0; __nv_bfloat16* gwl = 0;
    __nv_bfloat16* owh = 0; __nv_bfloat16* owl = 0;
    __nv_bfloat16* hih = 0; __nv_bfloat16* hil = 0;
    __nv_bfloat16* prh = 0; __nv_bfloat16* prl = 0;
    cudaGetSymbolAddress((void**)&xgh, d_xg_hi);
    cudaGetSymbolAddress((void**)&xgl, d_xg_lo);
    cudaGetSymbolAddress((void**)&qkvh, d_qkvw_hi);
    cudaGetSymbolAddress((void**)&qkvl, d_qkvw_lo);
    cudaGetSymbolAddress((void**)&gwh, d_gw_hi);
    cudaGetSymbolAddress((void**)&gwl, d_gw_lo);
    cudaGetSymbolAddress((void**)&owh, d_ow_hi);
    cudaGetSymbolAddress((void**)&owl, d_ow_lo);
    cudaGetSymbolAddress((void**)&hih, d_hid_hi);
    cudaGetSymbolAddress((void**)&hil, d_hid_lo);
    cudaGetSymbolAddress((void**)&prh, d_pre_hi);
    cudaGetSymbolAddress((void**)&prl, d_pre_lo);

    cudaFuncSetAttribute(gemm_tc, cudaFuncAttributeMaxDynamicSharedMemorySize, GEMM_SMEM);

    // 1: pack all weights (+bg cols, +hidden split)
    pack_w_kernel<<<(int)((TOT_U + 255) / 256), 256>>>(q_w, k_w, v_w, b_w, a_w, g_w, o_w, hidden);
    // 2-3: routing
    router_kernel<<<SLEN, 256>>>(hidden, gate_w);
    dispatch_kernel<<<1, 256>>>();
    // 4: gate projection
    gemm_tc<<<dim3(VDIM / 128, SLEN / 128, 1), 256, GEMM_SMEM>>>(
        hih, hil, gwh, gwl, gg, SLEN, VDIM, DDIM, 0LL, 0LL, 0LL, 0);
    // 5: gather + activation split
    gather_split_kernel<<<NROW, 256>>>(hidden);
    // 6: fused qkv+bg per-expert projection
    gemm_tc<<<dim3(QKVP / 128, CAP / 128, ENUM), 256, GEMM_SMEM>>>(
        xgh, xgl, qkvh, qkvl, qkvpre, CAP, QKVP, DDIM,
        (long long)CAP * DDIM, (long long)DDIM * QKVP, (long long)CAP * QKVP, 1);

    bg_finish_kernel<<<(NROW * HNUM + 255) / 256, 256>>>(A_log, dt_bias);

    dim3 gc(NROW, HNUM);
    convnorm_kernel<<<gc, 256>>>(qkvpre, qcw, qn, 0.0625f, 0);
    convnorm_kernel<<<gc, 256>>>(qkvpre, kcw, kn, 1.0f, KDIM);
    convv_kernel<<<(NROW * (VDIM / 256)), 256>>>(qkvpre, vcw, vn);

    recur_kernel<<<dim3(DVC / 32, HNUM, ENUM), 256>>>();

    combine_kernel<<<dim3(SLEN, HNUM), 256>>>(norm_w);
    gemm_tc<<<dim3(DDIM / 128, SLEN / 128, 1), 256, GEMM_SMEM>>>(
        prh, prl, owh, owl, (float*)d_out, SLEN, DDIM, VDIM, 0LL, 0LL, 0LL, 0);
}

// round 10
// speedup vs baseline: 1.2740x; 1.0374x over previous
#include <cuda_runtime.h>
#include <cuda_bf16.h>
#include <stdint.h>
#include <math.h>

#define SLEN 1024
#define DDIM 2048
#define ENUM 8
#define HNUM 6
#define DKC  256
#define DVC  512
#define KDIM 1536   // HNUM*DKC
#define VDIM 3072   // HNUM*DVC
#define QKVO 6144   // q+k+v data cols
#define QKVP 6272   // padded: + 12 beta/g cols + zero pad (49*128)
#define CAP  1024
#define NROW (ENUM*CAP)

// ---------------- scratch (device globals; no allocation in kernel_launch) ----
__device__ int   d_sel[SLEN*2];
__device__ float d_rw [SLEN*2];
__device__ int   d_m  [ENUM];
__device__ int   d_tok[NROW];
__device__ int   d_pos[SLEN*2];
__device__ float d_qkvpre[(size_t)NROW*QKVP];
__device__ float d_qn  [NROW*KDIM];
__device__ float d_kn  [NROW*KDIM];
__device__ float d_vn  [NROW*VDIM];
__device__ float d_beta[NROW*HNUM];
__device__ float d_g   [NROW*HNUM];
__device__ float d_o   [NROW*VDIM];
__device__ float d_gg  [SLEN*VDIM];

// bf16 hi/lo split buffers
__device__ __align__(256) __nv_bfloat16 d_xg_hi[NROW*DDIM];
__device__ __align__(256) __nv_bfloat16 d_xg_lo[NROW*DDIM];
__device__ __align__(256) __nv_bfloat16 d_qkvw_hi[(size_t)ENUM*DDIM*QKVP];
__device__ __align__(256) __nv_bfloat16 d_qkvw_lo[(size_t)ENUM*DDIM*QKVP];
__device__ __align__(256) __nv_bfloat16 d_gw_hi[DDIM*VDIM];
__device__ __align__(256) __nv_bfloat16 d_gw_lo[DDIM*VDIM];
__device__ __align__(256) __nv_bfloat16 d_ow_hi[VDIM*DDIM];
__device__ __align__(256) __nv_bfloat16 d_ow_lo[VDIM*DDIM];
__device__ __align__(256) __nv_bfloat16 d_hid_hi[SLEN*DDIM];
__device__ __align__(256) __nv_bfloat16 d_hid_lo[SLEN*DDIM];
__device__ __align__(256) __nv_bfloat16 d_pre_hi[SLEN*VDIM];
__device__ __align__(256) __nv_bfloat16 d_pre_lo[SLEN*VDIM];

// ---------------- PTX helpers -------------------------------------------------
__device__ __forceinline__ void cpa16(uint32_t d, const void* s) {
    asm volatile("cp.async.cg.shared.global [%0], [%1], 16;" :: "r"(d), "l"(s));
}
__device__ __forceinline__ void ldm_x4(uint32_t* r, uint32_t a) {
    asm volatile("ldmatrix.sync.aligned.m8n8.x4.shared.b16 {%0,%1,%2,%3}, [%4];"
                 : "=r"(r[0]), "=r"(r[1]), "=r"(r[2]), "=r"(r[3]) : "r"(a));
}
__device__ __forceinline__ void ldm_x4t(uint32_t* r, uint32_t a) {
    asm volatile("ldmatrix.sync.aligned.m8n8.x4.trans.shared.b16 {%0,%1,%2,%3}, [%4];"
                 : "=r"(r[0]), "=r"(r[1]), "=r"(r[2]), "=r"(r[3]) : "r"(a));
}
__device__ __forceinline__ void mma_bf16(float* c, const uint32_t* a, const uint32_t* b) {
    asm volatile(
        "mma.sync.aligned.m16n8k16.row.col.f32.bf16.bf16.f32 "
        "{%0,%1,%2,%3},{%4,%5,%6,%7},{%8,%9},{%0,%1,%2,%3};"
        : "+f"(c[0]), "+f"(c[1]), "+f"(c[2]), "+f"(c[3])
        : "r"(a[0]), "r"(a[1]), "r"(a[2]), "r"(a[3]), "r"(b[0]), "r"(b[1]));
}

// ---------------- hi/lo split conversion --------------------------------------
__device__ __forceinline__ void split4(float4 v, __nv_bfloat162* hi, __nv_bfloat162* lo) {
    __nv_bfloat16 h0 = __float2bfloat16(v.x), h1 = __float2bfloat16(v.y);
    __nv_bfloat16 h2 = __float2bfloat16(v.z), h3 = __float2bfloat16(v.w);
    __nv_bfloat16 l0 = __float2bfloat16(v.x - __bfloat162float(h0));
    __nv_bfloat16 l1 = __float2bfloat16(v.y - __bfloat162float(h1));
    __nv_bfloat16 l2 = __float2bfloat16(v.z - __bfloat162float(h2));
    __nv_bfloat16 l3 = __float2bfloat16(v.w - __bfloat162float(h3));
    hi[0] = __halves2bfloat162(h0, h1);
    hi[1] = __halves2bfloat162(h2, h3);
    lo[0] = __halves2bfloat162(l0, l1);
    lo[1] = __halves2bfloat162(l2, l3);
}

// -------------- mega-pack: qkv+bg fused weights + gate/out/hidden splits -----
#define QKV_U (ENUM*DDIM*(QKVP/4))
#define GW_U  (DDIM*VDIM/4)
#define OW_U  (VDIM*DDIM/4)
#define HID_U (SLEN*DDIM/4)
#define TOT_U (QKV_U + GW_U + OW_U + HID_U)

__global__ void pack_w_kernel(const float* __restrict__ q_w, const float* __restrict__ k_w,
                              const float* __restrict__ v_w, const float* __restrict__ b_w,
                              const float* __restrict__ a_w, const float* __restrict__ g_w,
                              const float* __restrict__ o_w, const float* __restrict__ hidden) {
    long long u = (long long)blockIdx.x * 256 + threadIdx.x;
    if (u >= TOT_U) return;
    if (u < QKV_U) {
        long long per_e = (long long)DDIM * (QKVP / 4);
        int e = (int)(u / per_e);
        long long r = u - (long long)e * per_e;
        int d = (int)(r / (QKVP / 4));
        int c4 = (int)(r - (long long)d * (QKVP / 4));
        int n = c4 * 4;
        float4 src;
        if (n < KDIM) {
            src = *(const float4*)(q_w + (size_t)d * KDIM + n);
        } else if (n < 2 * KDIM) {
            src = *(const float4*)(k_w + ((size_t)e * DDIM + d) * KDIM + (n - KDIM));
        } else if (n < QKVO) {
            src = *(const float4*)(v_w + ((size_t)e * DDIM + d) * VDIM + (n - 2 * KDIM));
        } else {
            float vals[4];
#pragma unroll
            for (int j = 0; j < 4; j++) {
                int c = n + j;
                if (c < QKVO + HNUM)
                    vals[j] = b_w[((size_t)e * DDIM + d) * HNUM + (c - QKVO)];
                else if (c < QKVO + 2 * HNUM)
                    vals[j] = a_w[((size_t)e * DDIM + d) * HNUM + (c - QKVO - HNUM)];
                else
                    vals[j] = 0.f;
            }
            src = make_float4(vals[0], vals[1], vals[2], vals[3]);
        }
        size_t dst = ((size_t)e * DDIM + d) * QKVP + n;
        __nv_bfloat162 h[2], l[2];
        split4(src, h, l);
        __nv_bfloat162* hp = (__nv_bfloat162*)(d_qkvw_hi + dst);
        __nv_bfloat162* lp = (__nv_bfloat162*)(d_qkvw_lo + dst);
        hp[0] = h[0]; hp[1] = h[1]; lp[0] = l[0]; lp[1] = l[1];
        return;
    }
    u -= QKV_U;
    if (u < GW_U) {
        float4 src = ((const float4*)g_w)[u];
        __nv_bfloat162 h[2], l[2]; split4(src, h, l);
        ((__nv_bfloat162*)d_gw_hi)[2 * u] = h[0]; ((__nv_bfloat162*)d_gw_hi)[2 * u + 1] = h[1];
        ((__nv_bfloat162*)d_gw_lo)[2 * u] = l[0]; ((__nv_bfloat162*)d_gw_lo)[2 * u + 1] = l[1];
        return;
    }
    u -= GW_U;
    if (u < OW_U) {
        float4 src = ((const float4*)o_w)[u];
        __nv_bfloat162 h[2], l[2]; split4(src, h, l);
        ((__nv_bfloat162*)d_ow_hi)[2 * u] = h[0]; ((__nv_bfloat162*)d_ow_hi)[2 * u + 1] = h[1];
        ((__nv_bfloat162*)d_ow_lo)[2 * u] = l[0]; ((__nv_bfloat162*)d_ow_lo)[2 * u + 1] = l[1];
        return;
    }
    u -= OW_U;
    {
        float4 src = ((const float4*)hidden)[u];
        __nv_bfloat162 h[2], l[2]; split4(src, h, l);
        ((__nv_bfloat162*)d_hid_hi)[2 * u] = h[0]; ((__nv_bfloat162*)d_hid_hi)[2 * u + 1] = h[1];
        ((__nv_bfloat162*)d_hid_lo)[2 * u] = l[0]; ((__nv_bfloat162*)d_hid_lo)[2 * u + 1] = l[1];
    }
}

// ---------------- tensor-core split-bf16 GEMM core (3-stage cp.async) ---------
// lda = A row stride in elements (may differ from K for split-K slices)
#define LDA 40
#define LDB 136
#define A_SZ (128*LDA)
#define B_SZ (32*LDB)
#define STAGE_H (2*A_SZ + 2*B_SZ)
#define NSTAGE 3
#define GEMM_SMEM (STAGE_H*2*NSTAGE)

template<bool ATOMIC>
__device__ __forceinline__ void gemm_core(
    const __nv_bfloat16* __restrict__ Ahi, const __nv_bfloat16* __restrict__ Alo,
    const __nv_bfloat16* __restrict__ Bhi, const __nv_bfloat16* __restrict__ Blo,
    float* __restrict__ C, int mlim, int N, int K, int lda, int row0, int col0,
    __nv_bfloat16* smbuf) {
    uint32_t sbase = (uint32_t)__cvta_generic_to_shared(smbuf);
    int t = threadIdx.x;

    int arow = t >> 1, akc = (t & 1) * 16;
    int brow = t >> 3, bnc = (t & 7) * 16;
    const __nv_bfloat16* gAh = Ahi + (size_t)(row0 + arow) * lda + akc;
    const __nv_bfloat16* gAl = Alo + (size_t)(row0 + arow) * lda + akc;
    const __nv_bfloat16* gBh = Bhi + (size_t)brow * N + col0 + bnc;
    const __nv_bfloat16* gBl = Blo + (size_t)brow * N + col0 + bnc;
    uint32_t dAh = sbase + (uint32_t)(arow * LDA + akc) * 2;
    uint32_t dAl = dAh + A_SZ * 2;
    uint32_t dBh = sbase + (uint32_t)(2 * A_SZ + brow * LDB + bnc) * 2;
    uint32_t dBl = dBh + B_SZ * 2;

    int lane = t & 31, wid = t >> 5;
    int wm = (wid >> 2) * 64, wn = (wid & 3) * 32;
    int aR = lane & 15, aC = (lane >> 4) * 8;
    uint32_t aOff = (uint32_t)((wm + aR) * LDA + aC) * 2;
    int bgp = lane >> 3, blr = lane & 7;
    int bR = blr + (bgp & 1) * 8, bC = (bgp >> 1) * 8;
    uint32_t bOff = (uint32_t)(bR * LDB + wn + bC) * 2;

    float acc[4][4][4];
#pragma unroll
    for (int mi = 0; mi < 4; mi++)
#pragma unroll
        for (int ni = 0; ni < 4; ni++)
#pragma unroll
            for (int j = 0; j < 4; j++) acc[mi][ni][j] = 0.f;

    int KT = K / 32;

    auto load_stage = [&](int ktl) {
        int k0 = ktl * 32;
        uint32_t so = (uint32_t)((ktl % NSTAGE) * STAGE_H) * 2;
        const __nv_bfloat16* a0 = gAh + k0;
        const __nv_bfloat16* a1 = gAl + k0;
        const __nv_bfloat16* b0 = gBh + (size_t)k0 * N;
        const __nv_bfloat16* b1 = gBl + (size_t)k0 * N;
        cpa16(dAh + so, a0);        cpa16(dAh + so + 16, a0 + 8);
        cpa16(dAl + so, a1);        cpa16(dAl + so + 16, a1 + 8);
        cpa16(dBh + so, b0);        cpa16(dBh + so + 16, b0 + 8);
        cpa16(dBl + so, b1);        cpa16(dBl + so + 16, b1 + 8);
        asm volatile("cp.async.commit_group;");
    };

    load_stage(0);
    if (KT > 1) load_stage(1);

    for (int kt = 0; kt < KT; kt++) {
        if (kt + 1 < KT) {
            asm volatile("cp.async.wait_group 1;");
        } else {
            asm volatile("cp.async.wait_group 0;");
        }
        __syncthreads();
        if (kt + 2 < KT) load_stage(kt + 2);

        uint32_t s0 = sbase + (uint32_t)((kt % NSTAGE) * STAGE_H) * 2;
        uint32_t sAh = s0 + aOff;
        uint32_t sAl = sAh + (uint32_t)A_SZ * 2;
        uint32_t sBh = s0 + (uint32_t)(2 * A_SZ) * 2 + bOff;
        uint32_t sBl = sBh + (uint32_t)B_SZ * 2;

#pragma unroll
        for (int ks = 0; ks < 2; ks++) {
            uint32_t kao = (uint32_t)(ks * 16) * 2;
            uint32_t kbo = (uint32_t)(ks * 16 * LDB) * 2;
            uint32_t bh[8], bl2[8], af[16];
            ldm_x4t(bh + 0, sBh + kbo);
            ldm_x4t(bh + 4, sBh + kbo + 32);
            ldm_x4t(bl2 + 0, sBl + kbo);
            ldm_x4t(bl2 + 4, sBl + kbo + 32);
#pragma unroll
            for (int mi = 0; mi < 4; mi++)
                ldm_x4(af + mi * 4, sAh + kao + (uint32_t)(mi * 16 * LDA) * 2);
#pragma unroll
            for (int mi = 0; mi < 4; mi++)
#pragma unroll
                for (int ni = 0; ni < 4; ni++)
                    mma_bf16(acc[mi][ni], af + mi * 4, bh + (ni >> 1) * 4 + (ni & 1) * 2);
#pragma unroll
            for (int mi = 0; mi < 4; mi++)
#pragma unroll
                for (int ni = 0; ni < 4; ni++)
                    mma_bf16(acc[mi][ni], af + mi * 4, bl2 + (ni >> 1) * 4 + (ni & 1) * 2);
#pragma unroll
            for (int mi = 0; mi < 4; mi++)
                ldm_x4(af + mi * 4, sAl + kao + (uint32_t)(mi * 16 * LDA) * 2);
#pragma unroll
            for (int mi = 0; mi < 4; mi++)
#pragma unroll
                for (int ni = 0; ni < 4; ni++)
                    mma_bf16(acc[mi][ni], af + mi * 4, bh + (ni >> 1) * 4 + (ni & 1) * 2);
        }
    }

    int gr = lane >> 2, gc = (lane & 3) * 2;
#pragma unroll
    for (int mi = 0; mi < 4; mi++) {
        int r = row0 + wm + mi * 16 + gr;
#pragma unroll
        for (int ni = 0; ni < 4; ni++) {
            float* Cp = C + (size_t)r * N + col0 + wn + ni * 8 + gc;
            if (r < mlim) {
                if (ATOMIC) { atomicAdd(Cp, acc[mi][ni][0]); atomicAdd(Cp + 1, acc[mi][ni][1]); }
                else { Cp[0] = acc[mi][ni][0]; Cp[1] = acc[mi][ni][1]; }
            }
            if (r + 8 < mlim) {
                float* Cq = Cp + (size_t)8 * N;
                if (ATOMIC) { atomicAdd(Cq, acc[mi][ni][2]); atomicAdd(Cq + 1, acc[mi][ni][3]); }
                else { Cq[0] = acc[mi][ni][2]; Cq[1] = acc[mi][ni][3]; }
            }
        }
    }
}

// merged qkv (z=0..7) + gate (z=8) GEMM launch
__global__ __launch_bounds__(256, 2)
void gemm_qkv_gate(const __nv_bfloat16* __restrict__ xgh, const __nv_bfloat16* __restrict__ xgl,
                   const __nv_bfloat16* __restrict__ qkvh, const __nv_bfloat16* __restrict__ qkvl,
                   float* __restrict__ qkvpre,
                   const __nv_bfloat16* __restrict__ hih, const __nv_bfloat16* __restrict__ hil,
                   const __nv_bfloat16* __restrict__ gwh, const __nv_bfloat16* __restrict__ gwl,
                   float* __restrict__ gg) {
    extern __shared__ __nv_bfloat16 smbuf[];
    int z = blockIdx.z;
    int row0 = blockIdx.y * 128;
    int col0 = blockIdx.x * 128;
    if (z < ENUM) {
        int mlim = d_m[z];
        if (row0 >= mlim) return;
        gemm_core<false>(xgh + (size_t)z * CAP * DDIM, xgl + (size_t)z * CAP * DDIM,
                         qkvh + (size_t)z * DDIM * QKVP, qkvl + (size_t)z * DDIM * QKVP,
                         qkvpre + (size_t)z * CAP * QKVP, mlim, QKVP, DDIM, DDIM,
                         row0, col0, smbuf);
    } else {
        if (col0 >= VDIM) return;
        gemm_core<false>(hih, hil, gwh, gwl, gg, SLEN, VDIM, DDIM, DDIM, row0, col0, smbuf);
    }
}

// split-K output GEMM: z selects K-half, accumulates via atomics.
// A (pre) rows are VDIM wide; pass lda=VDIM with base offset z*kHalf.
__global__ __launch_bounds__(256, 2)
void gemm_out_splitk(const __nv_bfloat16* __restrict__ Ahi, const __nv_bfloat16* __restrict__ Alo,
                     const __nv_bfloat16* __restrict__ Bhi, const __nv_bfloat16* __restrict__ Blo,
                     float* __restrict__ C) {
    extern __shared__ __nv_bfloat16 smbuf[];
    int z = blockIdx.z;            // 0,1
    int row0 = blockIdx.y * 128;
    int col0 = blockIdx.x * 128;
    int kHalf = VDIM / 2;          // 1536
    gemm_core<true>(Ahi + (size_t)z * kHalf, Alo + (size_t)z * kHalf,
                    Bhi + (size_t)z * kHalf * DDIM, Blo + (size_t)z * kHalf * DDIM,
                    C, SLEN, DDIM, kHalf, VDIM, row0, col0, smbuf);
}

__global__ void zero_out_kernel(float4* __restrict__ p, int n4) {
    int i = blockIdx.x * 256 + threadIdx.x;
    if (i < n4) p[i] = make_float4(0.f, 0.f, 0.f, 0.f);
}

// ---------------- router ------------------------------------------------------
__global__ void router_kernel(const float* __restrict__ hidden,
                              const float* __restrict__ gate_w) {
    int s = blockIdx.x;
    int tid = threadIdx.x;
    float acc[ENUM];
#pragma unroll
    for (int e = 0; e < ENUM; e++) acc[e] = 0.f;
    const float* xr = hidden + (size_t)s * DDIM;
    for (int d = tid; d < DDIM; d += 256) {
        float x = xr[d];
        const float* w = gate_w + (size_t)d * ENUM;
#pragma unroll
        for (int e = 0; e < ENUM; e++) acc[e] += x * w[e];
    }
    __shared__ float red[ENUM][256];
#pragma unroll
    for (int e = 0; e < ENUM; e++) red[e][tid] = acc[e];
    __syncthreads();
    for (int st = 128; st > 0; st >>= 1) {
        if (tid < st) {
#pragma unroll
            for (int e = 0; e < ENUM; e++) red[e][tid] += red[e][tid + st];
        }
        __syncthreads();
    }
    if (tid == 0) {
        float l[ENUM], mx = -1e30f;
#pragma unroll
        for (int e = 0; e < ENUM; e++) { l[e] = red[e][0]; mx = fmaxf(mx, l[e]); }
        float p[ENUM], sum = 0.f;
#pragma unroll
        for (int e = 0; e < ENUM; e++) { p[e] = expf(l[e] - mx); sum += p[e]; }
#pragma unroll
        for (int e = 0; e < ENUM; e++) p[e] /= sum;
        int i0 = 0;
#pragma unroll
        for (int e = 1; e < ENUM; e++) if (p[e] > p[i0]) i0 = e;
        int i1 = -1;
#pragma unroll
        for (int e = 0; e < ENUM; e++)
            if (e != i0 && (i1 < 0 || p[e] > p[i1])) i1 = e;
        float r0 = p[i0], r1 = p[i1], rs = r0 + r1;
        d_sel[2 * s] = i0;  d_sel[2 * s + 1] = i1;
        d_rw[2 * s] = r0 / rs;  d_rw[2 * s + 1] = r1 / rs;
    }
}

// -------------- dispatch: parallel warp-per-expert ballot scan ----------------
__global__ void dispatch_kernel() {
    int e = threadIdx.x >> 5;
    int lane = threadIdx.x & 31;
    int cnt = 0;
    for (int i = lane; i < SLEN * 2; i += 32) cnt += (d_sel[i] == e);
#pragma unroll
    for (int o = 16; o; o >>= 1) cnt += __shfl_xor_sync(0xffffffffu, cnt, o);
    int drop = cnt > CAP ? cnt - CAP : 0;
    if (lane == 0) d_m[e] = cnt - drop;
    int base = 0;
    for (int i0 = 0; i0 < SLEN * 2; i0 += 32) {
        int i = i0 + lane;
        bool hit = (d_sel[i] == e);
        unsigned mask = __ballot_sync(0xffffffffu, hit);
        if (hit) {
            int r = base + __popc(mask & ((1u << lane) - 1u));
            if (r >= drop) {
                int j = r - drop;
                d_tok[e * CAP + j] = i >> 1;
                d_pos[i] = e * CAP + j;
            } else {
                d_pos[i] = -1;
            }
        }
        base += __popc(mask);
    }
}

// -------------- gather + hi/lo split of activations --------------------------
__global__ void gather_split_kernel(const float* __restrict__ hidden) {
    int row = blockIdx.x;
    int e = row >> 10, t = row & 1023;
    if (t >= d_m[e]) return;
    const float4* src = (const float4*)(hidden + (size_t)d_tok[row] * DDIM);
    __nv_bfloat162* hi = (__nv_bfloat162*)(d_xg_hi + (size_t)row * DDIM);
    __nv_bfloat162* lo = (__nv_bfloat162*)(d_xg_lo + (size_t)row * DDIM);
    for (int i = threadIdx.x; i < DDIM / 4; i += 256) {
        float4 v = src[i];
        __nv_bfloat162 h[2], l[2];
        split4(v, h, l);
        hi[2 * i] = h[0]; hi[2 * i + 1] = h[1];
        lo[2 * i] = l[0]; lo[2 * i + 1] = l[1];
    }
}

// -------------- beta/g epilogue -----------------------------------------------
__global__ void bg_finish_kernel(const float* __restrict__ A_log,
                                 const float* __restrict__ dt_bias) {
    int idx = blockIdx.x * 256 + threadIdx.x;
    if (idx >= NROW * HNUM) return;
    int row = idx / HNUM, h = idx - row * HNUM;
    int e = row >> 10, t = row & 1023;
    if (t >= d_m[e]) return;
    float bl = d_qkvpre[(size_t)row * QKVP + QKVO + h];
    float al = d_qkvpre[(size_t)row * QKVP + QKVO + HNUM + h];
    d_beta[idx] = 1.f / (1.f + expf(-bl));
    float xx = al + dt_bias[h];
    float sp = xx > 20.f ? xx : log1pf(expf(xx));
    d_g[idx] = -expf(A_log[h]) * sp;
}

// -------------- merged conv launch: y<6 q-norm, y<12 k-norm, else v -----------
__global__ void conv_all_kernel(const float* __restrict__ pre,
                                const float* __restrict__ qcw,
                                const float* __restrict__ kcw,
                                const float* __restrict__ vcw) {
    int row = blockIdx.x;
    int y = blockIdx.y;
    int e = row >> 10, t = row & 1023;
    if (t >= d_m[e]) return;
    int tid = threadIdx.x;

    if (y < 12) {
        int h = (y < 6) ? y : (y - 6);
        int preOff = (y < 6) ? 0 : KDIM;
        float scale = (y < 6) ? 0.0625f : 1.0f;
        const float* cw = (y < 6) ? qcw : kcw;
        float* out = (y < 6) ? d_qn : d_kn;
        int ch = h * DKC + tid;
        float yv = 0.f;
#pragma unroll
        for (int j = 0; j < 4; j++) {
            int tt = t - 3 + j;
            if (tt >= 0) yv += cw[ch * 4 + j] * pre[(size_t)(row - 3 + j) * QKVP + preOff + ch];
        }
        yv = yv / (1.f + expf(-yv));
        __shared__ float red[256];
        red[tid] = yv * yv;
        __syncthreads();
        for (int st = 128; st > 0; st >>= 1) {
            if (tid < st) red[tid] += red[tid + st];
            __syncthreads();
        }
        float inv = rsqrtf(red[0] + 1e-6f) * scale;
        out[(size_t)row * KDIM + ch] = yv * inv;
    } else {
        int ch = (y - 12) * 256 + tid;
        float yv = 0.f;
#pragma unroll
        for (int j = 0; j < 4; j++) {
            int tt = t - 3 + j;
            if (tt >= 0) yv += vcw[ch * 4 + j] * pre[(size_t)(row - 3 + j) * QKVP + 2 * KDIM + ch];
        }
        d_vn[(size_t)row * VDIM + ch] = yv / (1.f + expf(-yv));
    }
}

// -------------- gated delta-rule recurrence (conflict-free strided) -----------
__global__ void recur_kernel() {
    int vc = blockIdx.x;
    int h = blockIdx.y;
    int e = blockIdx.z;
    int m = d_m[e];
    __shared__ float S[32 * 256];
    __shared__ float su[32], sw[32], sd[32];
    int tid = threadIdx.x, warp = tid >> 5, lane = tid & 31;
    int v0 = warp * 4;
    for (int i = lane; i < 4 * 256; i += 32) S[v0 * 256 + i] = 0.f;
    if (lane < 4) { su[v0 + lane] = 0.f; sw[v0 + lane] = 0.f; }
    __syncwarp();
    if (m == 0) return;

    const float* kb = d_kn + (size_t)(e * CAP) * KDIM + h * DKC;
    const float* qb = d_qn + (size_t)(e * CAP) * KDIM + h * DKC;
    const float* vb = d_vn + (size_t)(e * CAP) * VDIM + h * DVC + vc * 32;
    const float* bb = d_beta + (size_t)(e * CAP) * HNUM + h;
    const float* gb = d_g + (size_t)(e * CAP) * HNUM + h;
    float* ob = d_o + (size_t)(e * CAP) * VDIM + h * DVC + vc * 32;

    float kc[8], qc[8];
#pragma unroll
    for (int j = 0; j < 8; j++) { kc[j] = kb[lane + 32 * j]; qc[j] = qb[lane + 32 * j]; }
    float beta = bb[0];
    float gv = gb[0];
    float vv = (lane < 4) ? vb[v0 + lane] : 0.f;

    for (int t = 0; t < m; t++) {
        float eg = expf(gv);
        float qk = 0.f;
#pragma unroll
        for (int j = 0; j < 8; j++) qk += kc[j] * qc[j];
#pragma unroll
        for (int o = 16; o; o >>= 1) qk += __shfl_xor_sync(0xffffffffu, qk, o);

        if (lane < 4) {
            int v = v0 + lane;
            float dd = beta * (vv - eg * su[v]);
            ob[(size_t)t * VDIM + v] = eg * sw[v] + qk * dd;
            sd[v] = dd;
        }
        __syncwarp();

        float kn2[8], qn2[8];
        float beta_n = 0.f, g_n = 0.f, vv_n = 0.f;
        if (t + 1 < m) {
            const float* kr = kb + (size_t)(t + 1) * KDIM;
            const float* qr = qb + (size_t)(t + 1) * KDIM;
#pragma unroll
            for (int j = 0; j < 8; j++) { kn2[j] = kr[lane + 32 * j]; qn2[j] = qr[lane + 32 * j]; }
            beta_n = bb[(size_t)(t + 1) * HNUM];
            g_n = gb[(size_t)(t + 1) * HNUM];
            if (lane < 4) vv_n = vb[(size_t)(t + 1) * VDIM + v0 + lane];
        } else {
#pragma unroll
            for (int j = 0; j < 8; j++) { kn2[j] = 0.f; qn2[j] = 0.f; }
        }

#pragma unroll
        for (int vi = 0; vi < 4; vi++) {
            int v = v0 + vi;
            float dd = sd[v];
            float un = 0.f, wn = 0.f;
            float* Sr = &S[v * 256];
#pragma unroll
            for (int j = 0; j < 8; j++) {
                float s2 = Sr[lane + 32 * j];
                s2 = eg * s2 + kc[j] * dd;
                Sr[lane + 32 * j] = s2;
                un += kn2[j] * s2;
                wn += qn2[j] * s2;
            }
#pragma unroll
            for (int o = 16; o; o >>= 1) {
                un += __shfl_xor_sync(0xffffffffu, un, o);
                wn += __shfl_xor_sync(0xffffffffu, wn, o);
            }
            if (lane == 0) { su[v] = un; sw[v] = wn; }
        }
        __syncwarp();
#pragma unroll
        for (int j = 0; j < 8; j++) { kc[j] = kn2[j]; qc[j] = qn2[j]; }
        beta = beta_n; gv = g_n; vv = vv_n;
    }
}

// -------------- combine + gated RMSNorm + bf16 hi/lo (fused) ------------------
__global__ void combine_kernel(const float* __restrict__ norm_w) {
    int s = blockIdx.x, h = blockIdx.y, tid = threadIdx.x;
    int p0 = d_pos[2 * s], p1 = d_pos[2 * s + 1];
    float r0 = d_rw[2 * s], r1 = d_rw[2 * s + 1];
    float acc[2];
    float ss = 0.f;
#pragma unroll
    for (int i = 0; i < 2; i++) {
        int v = tid + i * 256;
        float a = 0.f;
        if (p0 >= 0) a += r0 * d_o[(size_t)p0 * VDIM + h * DVC + v];
        if (p1 >= 0) a += r1 * d_o[(size_t)p1 * VDIM + h * DVC + v];
        acc[i] = a;
        ss += a * a;
    }
    __shared__ float red[256];
    red[tid] = ss;
    __syncthreads();
    for (int st = 128; st > 0; st >>= 1) {
        if (tid < st) red[tid] += red[tid + st];
        __syncthreads();
    }
    float inv = rsqrtf(red[0] / (float)DVC + 1e-5f);
#pragma unroll
    for (int i = 0; i < 2; i++) {
        int v = tid + i * 256;
        float gg = d_gg[(size_t)s * VDIM + h * DVC + v];
        float sg = gg / (1.f + expf(-gg));
        float val = acc[i] * inv * norm_w[v] * sg;
        __nv_bfloat16 hb = __float2bfloat16(val);
        __nv_bfloat16 lb = __float2bfloat16(val - __bfloat162float(hb));
        size_t idx = (size_t)s * VDIM + h * DVC + v;
        d_pre_hi[idx] = hb;
        d_pre_lo[idx] = lb;
    }
}

// ----------------------------- launch -----------------------------------------
extern "C" void kernel_launch(void* const* d_in, const int* in_sizes, int n_in,
                              void* d_out, int out_size) {
    const float* hidden  = (const float*)d_in[0];
    const float* q_w     = (const float*)d_in[1];
    const float* gate_w  = (const float*)d_in[2];
    const float* k_w     = (const float*)d_in[3];
    const float* v_w     = (const float*)d_in[4];
    const float* b_w     = (const float*)d_in[5];
    const float* a_w     = (const float*)d_in[6];
    const float* A_log   = (const float*)d_in[7];
    const float* dt_bias = (const float*)d_in[8];
    const float* qcw     = (const float*)d_in[9];
    const float* kcw     = (const float*)d_in[10];
    const float* vcw     = (const float*)d_in[11];
    const float* g_w     = (const float*)d_in[12];
    const float* norm_w  = (const float*)d_in[13];
    const float* o_w     = (const float*)d_in[14];

    float* qkvpre = 0; float* gg = 0;
    cudaGetSymbolAddress((void**)&qkvpre, d_qkvpre);
    cudaGetSymbolAddress((void**)&gg, d_gg);

    __nv_bfloat16* xgh = 0; __nv_bfloat16* xgl = 0;
    __nv_bfloat16* qkvh = 0; __nv_bfloat16* qkvl = 0;
    __nv_bfloat16* gwh = 0; __nv_bfloat16* gwl = 0;
    __nv_bfloat16* owh = 0; __nv_bfloat16* owl = 0;
    __nv_bfloat16* hih = 0; __nv_bfloat16* hil = 0;
    __nv_bfloat16* prh = 0; __nv_bfloat16* prl = 0;
    cudaGetSymbolAddress((void**)&xgh, d_xg_hi);
    cudaGetSymbolAddress((void**)&xgl, d_xg_lo);
    cudaGetSymbolAddress((void**)&qkvh, d_qkvw_hi);
    cudaGetSymbolAddress((void**)&qkvl, d_qkvw_lo);
    cudaGetSymbolAddress((void**)&gwh, d_gw_hi);
    cudaGetSymbolAddress((void**)&gwl, d_gw_lo);
    cudaGetSymbolAddress((void**)&owh, d_ow_hi);
    cudaGetSymbolAddress((void**)&owl, d_ow_lo);
    cudaGetSymbolAddress((void**)&hih, d_hid_hi);
    cudaGetSymbolAddress((void**)&hil, d_hid_lo);
    cudaGetSymbolAddress((void**)&prh, d_pre_hi);
    cudaGetSymbolAddress((void**)&prl, d_pre_lo);

    cudaFuncSetAttribute(gemm_qkv_gate, cudaFuncAttributeMaxDynamicSharedMemorySize, GEMM_SMEM);
    cudaFuncSetAttribute(gemm_out_splitk, cudaFuncAttributeMaxDynamicSharedMemorySize, GEMM_SMEM);

    // 1: pack all weights
    pack_w_kernel<<<(int)((TOT_U + 255) / 256), 256>>>(q_w, k_w, v_w, b_w, a_w, g_w, o_w, hidden);
    // 2: zero output (early; independent)
    zero_out_kernel<<<(SLEN * DDIM / 4 + 255) / 256, 256>>>((float4*)d_out, SLEN * DDIM / 4);
    // 3-4: routing
    router_kernel<<<SLEN, 256>>>(hidden, gate_w);
    dispatch_kernel<<<1, 256>>>();
    // 5: gather + activation split
    gather_split_kernel<<<NROW, 256>>>(hidden);
    // 6: merged qkv (z<8) + gate (z=8) projections
    gemm_qkv_gate<<<dim3(QKVP / 128, CAP / 128, ENUM + 1), 256, GEMM_SMEM>>>(
        xgh, xgl, qkvh, qkvl, qkvpre, hih, hil, gwh, gwl, gg);

    bg_finish_kernel<<<(NROW * HNUM + 255) / 256, 256>>>(A_log, dt_bias);

    // 7: merged convs (q norm / k norm / v)
    conv_all_kernel<<<dim3(NROW, 24), 256>>>(qkvpre, qcw, kcw, vcw);

    recur_kernel<<<dim3(DVC / 32, HNUM, ENUM), 256>>>();

    combine_kernel<<<dim3(SLEN, HNUM), 256>>>(norm_w);
    // 8: split-K output GEMM (atomic accumulate into zeroed d_out)
    gemm_out_splitk<<<dim3(DDIM / 128, SLEN / 128, 2), 256, GEMM_SMEM>>>(
        prh, prl, owh, owl, (float*)d_out);
}

// round 11
// speedup vs baseline: 1.2751x; 1.0008x over previous
#include <cuda_runtime.h>
#include <cuda_bf16.h>
#include <stdint.h>
#include <math.h>

#define SLEN 1024
#define DDIM 2048
#define ENUM 8
#define HNUM 6
#define DKC  256
#define DVC  512
#define KDIM 1536   // HNUM*DKC
#define VDIM 3072   // HNUM*DVC
#define QKVO 6144   // q+k+v data cols
#define QKVP 6272   // padded: + 12 beta/g cols + zero pad (49*128)
#define CAP  1024
#define NROW (ENUM*CAP)

// ---------------- scratch (device globals; no allocation in kernel_launch) ----
__device__ int   d_sel[SLEN*2];
__device__ float d_rw [SLEN*2];
__device__ int   d_m  [ENUM];
__device__ int   d_tok[NROW];
__device__ int   d_pos[SLEN*2];
__device__ float d_qkvpre[(size_t)NROW*QKVP];
__device__ float d_qn  [NROW*KDIM];
__device__ float d_kn  [NROW*KDIM];
__device__ float d_vn  [NROW*VDIM];
__device__ float d_beta[NROW*HNUM];
__device__ float d_g   [NROW*HNUM];
__device__ float d_o   [NROW*VDIM];
__device__ float d_gg  [SLEN*VDIM];

// bf16 hi/lo split buffers
__device__ __align__(256) __nv_bfloat16 d_xg_hi[NROW*DDIM];
__device__ __align__(256) __nv_bfloat16 d_xg_lo[NROW*DDIM];
__device__ __align__(256) __nv_bfloat16 d_qkvw_hi[(size_t)ENUM*DDIM*QKVP];
__device__ __align__(256) __nv_bfloat16 d_qkvw_lo[(size_t)ENUM*DDIM*QKVP];
__device__ __align__(256) __nv_bfloat16 d_gw_hi[DDIM*VDIM];
__device__ __align__(256) __nv_bfloat16 d_gw_lo[DDIM*VDIM];
__device__ __align__(256) __nv_bfloat16 d_ow_hi[VDIM*DDIM];
__device__ __align__(256) __nv_bfloat16 d_ow_lo[VDIM*DDIM];
__device__ __align__(256) __nv_bfloat16 d_hid_hi[SLEN*DDIM];
__device__ __align__(256) __nv_bfloat16 d_hid_lo[SLEN*DDIM];
__device__ __align__(256) __nv_bfloat16 d_pre_hi[SLEN*VDIM];
__device__ __align__(256) __nv_bfloat16 d_pre_lo[SLEN*VDIM];

// ---------------- PTX helpers -------------------------------------------------
__device__ __forceinline__ void cpa16(uint32_t d, const void* s) {
    asm volatile("cp.async.cg.shared.global [%0], [%1], 16;" :: "r"(d), "l"(s));
}
__device__ __forceinline__ void ldm_x4(uint32_t* r, uint32_t a) {
    asm volatile("ldmatrix.sync.aligned.m8n8.x4.shared.b16 {%0,%1,%2,%3}, [%4];"
                 : "=r"(r[0]), "=r"(r[1]), "=r"(r[2]), "=r"(r[3]) : "r"(a));
}
__device__ __forceinline__ void ldm_x4t(uint32_t* r, uint32_t a) {
    asm volatile("ldmatrix.sync.aligned.m8n8.x4.trans.shared.b16 {%0,%1,%2,%3}, [%4];"
                 : "=r"(r[0]), "=r"(r[1]), "=r"(r[2]), "=r"(r[3]) : "r"(a));
}
__device__ __forceinline__ void mma_bf16(float* c, const uint32_t* a, const uint32_t* b) {
    asm volatile(
        "mma.sync.aligned.m16n8k16.row.col.f32.bf16.bf16.f32 "
        "{%0,%1,%2,%3},{%4,%5,%6,%7},{%8,%9},{%0,%1,%2,%3};"
        : "+f"(c[0]), "+f"(c[1]), "+f"(c[2]), "+f"(c[3])
        : "r"(a[0]), "r"(a[1]), "r"(a[2]), "r"(a[3]), "r"(b[0]), "r"(b[1]));
}

// ---------------- hi/lo split conversion --------------------------------------
__device__ __forceinline__ void split4(float4 v, __nv_bfloat162* hi, __nv_bfloat162* lo) {
    __nv_bfloat16 h0 = __float2bfloat16(v.x), h1 = __float2bfloat16(v.y);
    __nv_bfloat16 h2 = __float2bfloat16(v.z), h3 = __float2bfloat16(v.w);
    __nv_bfloat16 l0 = __float2bfloat16(v.x - __bfloat162float(h0));
    __nv_bfloat16 l1 = __float2bfloat16(v.y - __bfloat162float(h1));
    __nv_bfloat16 l2 = __float2bfloat16(v.z - __bfloat162float(h2));
    __nv_bfloat16 l3 = __float2bfloat16(v.w - __bfloat162float(h3));
    hi[0] = __halves2bfloat162(h0, h1);
    hi[1] = __halves2bfloat162(h2, h3);
    lo[0] = __halves2bfloat162(l0, l1);
    lo[1] = __halves2bfloat162(l2, l3);
}

// -------------- mega-pack: qkv+bg fused weights + gate/out/hidden splits -----
#define QKV_U (ENUM*DDIM*(QKVP/4))
#define GW_U  (DDIM*VDIM/4)
#define OW_U  (VDIM*DDIM/4)
#define HID_U (SLEN*DDIM/4)
#define TOT_U (QKV_U + GW_U + OW_U + HID_U)

__global__ void pack_w_kernel(const float* __restrict__ q_w, const float* __restrict__ k_w,
                              const float* __restrict__ v_w, const float* __restrict__ b_w,
                              const float* __restrict__ a_w, const float* __restrict__ g_w,
                              const float* __restrict__ o_w, const float* __restrict__ hidden) {
    long long u = (long long)blockIdx.x * 256 + threadIdx.x;
    if (u >= TOT_U) return;
    if (u < QKV_U) {
        long long per_e = (long long)DDIM * (QKVP / 4);
        int e = (int)(u / per_e);
        long long r = u - (long long)e * per_e;
        int d = (int)(r / (QKVP / 4));
        int c4 = (int)(r - (long long)d * (QKVP / 4));
        int n = c4 * 4;
        float4 src;
        if (n < KDIM) {
            src = *(const float4*)(q_w + (size_t)d * KDIM + n);
        } else if (n < 2 * KDIM) {
            src = *(const float4*)(k_w + ((size_t)e * DDIM + d) * KDIM + (n - KDIM));
        } else if (n < QKVO) {
            src = *(const float4*)(v_w + ((size_t)e * DDIM + d) * VDIM + (n - 2 * KDIM));
        } else {
            float vals[4];
#pragma unroll
            for (int j = 0; j < 4; j++) {
                int c = n + j;
                if (c < QKVO + HNUM)
                    vals[j] = b_w[((size_t)e * DDIM + d) * HNUM + (c - QKVO)];
                else if (c < QKVO + 2 * HNUM)
                    vals[j] = a_w[((size_t)e * DDIM + d) * HNUM + (c - QKVO - HNUM)];
                else
                    vals[j] = 0.f;
            }
            src = make_float4(vals[0], vals[1], vals[2], vals[3]);
        }
        size_t dst = ((size_t)e * DDIM + d) * QKVP + n;
        __nv_bfloat162 h[2], l[2];
        split4(src, h, l);
        __nv_bfloat162* hp = (__nv_bfloat162*)(d_qkvw_hi + dst);
        __nv_bfloat162* lp = (__nv_bfloat162*)(d_qkvw_lo + dst);
        hp[0] = h[0]; hp[1] = h[1]; lp[0] = l[0]; lp[1] = l[1];
        return;
    }
    u -= QKV_U;
    if (u < GW_U) {
        float4 src = ((const float4*)g_w)[u];
        __nv_bfloat162 h[2], l[2]; split4(src, h, l);
        ((__nv_bfloat162*)d_gw_hi)[2 * u] = h[0]; ((__nv_bfloat162*)d_gw_hi)[2 * u + 1] = h[1];
        ((__nv_bfloat162*)d_gw_lo)[2 * u] = l[0]; ((__nv_bfloat162*)d_gw_lo)[2 * u + 1] = l[1];
        return;
    }
    u -= GW_U;
    if (u < OW_U) {
        float4 src = ((const float4*)o_w)[u];
        __nv_bfloat162 h[2], l[2]; split4(src, h, l);
        ((__nv_bfloat162*)d_ow_hi)[2 * u] = h[0]; ((__nv_bfloat162*)d_ow_hi)[2 * u + 1] = h[1];
        ((__nv_bfloat162*)d_ow_lo)[2 * u] = l[0]; ((__nv_bfloat162*)d_ow_lo)[2 * u + 1] = l[1];
        return;
    }
    u -= OW_U;
    {
        float4 src = ((const float4*)hidden)[u];
        __nv_bfloat162 h[2], l[2]; split4(src, h, l);
        ((__nv_bfloat162*)d_hid_hi)[2 * u] = h[0]; ((__nv_bfloat162*)d_hid_hi)[2 * u + 1] = h[1];
        ((__nv_bfloat162*)d_hid_lo)[2 * u] = l[0]; ((__nv_bfloat162*)d_hid_lo)[2 * u + 1] = l[1];
    }
}

// ---------------- tensor-core split-bf16 GEMM core (3-stage cp.async) ---------
// Inner loop software-pipelined: B frags of ks+1 prefetched under ks's MMAs,
// A frag reloads interleaved with preceding MMA group drain (WAR-safe).
#define LDA 40
#define LDB 136
#define A_SZ (128*LDA)
#define B_SZ (32*LDB)
#define STAGE_H (2*A_SZ + 2*B_SZ)
#define NSTAGE 3
#define GEMM_SMEM (STAGE_H*2*NSTAGE)

template<bool ATOMIC>
__device__ __forceinline__ void gemm_core(
    const __nv_bfloat16* __restrict__ Ahi, const __nv_bfloat16* __restrict__ Alo,
    const __nv_bfloat16* __restrict__ Bhi, const __nv_bfloat16* __restrict__ Blo,
    float* __restrict__ C, int mlim, int N, int K, int lda, int row0, int col0,
    __nv_bfloat16* smbuf) {
    uint32_t sbase = (uint32_t)__cvta_generic_to_shared(smbuf);
    int t = threadIdx.x;

    int arow = t >> 1, akc = (t & 1) * 16;
    int brow = t >> 3, bnc = (t & 7) * 16;
    const __nv_bfloat16* gAh = Ahi + (size_t)(row0 + arow) * lda + akc;
    const __nv_bfloat16* gAl = Alo + (size_t)(row0 + arow) * lda + akc;
    const __nv_bfloat16* gBh = Bhi + (size_t)brow * N + col0 + bnc;
    const __nv_bfloat16* gBl = Blo + (size_t)brow * N + col0 + bnc;
    uint32_t dAh = sbase + (uint32_t)(arow * LDA + akc) * 2;
    uint32_t dAl = dAh + A_SZ * 2;
    uint32_t dBh = sbase + (uint32_t)(2 * A_SZ + brow * LDB + bnc) * 2;
    uint32_t dBl = dBh + B_SZ * 2;

    int lane = t & 31, wid = t >> 5;
    int wm = (wid >> 2) * 64, wn = (wid & 3) * 32;
    int aR = lane & 15, aC = (lane >> 4) * 8;
    uint32_t aOff = (uint32_t)((wm + aR) * LDA + aC) * 2;
    int bgp = lane >> 3, blr = lane & 7;
    int bR = blr + (bgp & 1) * 8, bC = (bgp >> 1) * 8;
    uint32_t bOff = (uint32_t)(bR * LDB + wn + bC) * 2;

    float acc[4][4][4];
#pragma unroll
    for (int mi = 0; mi < 4; mi++)
#pragma unroll
        for (int ni = 0; ni < 4; ni++)
#pragma unroll
            for (int j = 0; j < 4; j++) acc[mi][ni][j] = 0.f;

    int KT = K / 32;

    auto load_stage = [&](int ktl) {
        int k0 = ktl * 32;
        uint32_t so = (uint32_t)((ktl % NSTAGE) * STAGE_H) * 2;
        const __nv_bfloat16* a0 = gAh + k0;
        const __nv_bfloat16* a1 = gAl + k0;
        const __nv_bfloat16* b0 = gBh + (size_t)k0 * N;
        const __nv_bfloat16* b1 = gBl + (size_t)k0 * N;
        cpa16(dAh + so, a0);        cpa16(dAh + so + 16, a0 + 8);
        cpa16(dAl + so, a1);        cpa16(dAl + so + 16, a1 + 8);
        cpa16(dBh + so, b0);        cpa16(dBh + so + 16, b0 + 8);
        cpa16(dBl + so, b1);        cpa16(dBl + so + 16, b1 + 8);
        asm volatile("cp.async.commit_group;");
    };

    load_stage(0);
    if (KT > 1) load_stage(1);

    const uint32_t KBO = (uint32_t)(16 * LDB) * 2;   // ks=1 B offset
    const uint32_t KAO = 32u;                        // ks=1 A offset (16 halfs)

    for (int kt = 0; kt < KT; kt++) {
        if (kt + 1 < KT) {
            asm volatile("cp.async.wait_group 1;");
        } else {
            asm volatile("cp.async.wait_group 0;");
        }
        __syncthreads();
        if (kt + 2 < KT) load_stage(kt + 2);

        uint32_t s0 = sbase + (uint32_t)((kt % NSTAGE) * STAGE_H) * 2;
        uint32_t sAh = s0 + aOff;
        uint32_t sAl = sAh + (uint32_t)A_SZ * 2;
        uint32_t sBh = s0 + (uint32_t)(2 * A_SZ) * 2 + bOff;
        uint32_t sBl = sBh + (uint32_t)B_SZ * 2;

        uint32_t bh0[8], bl0[8], bh1[8], bl1[8], af[16];

        // ks=0 operands + prefetch ks=1 B-hi
        ldm_x4t(bh0 + 0, sBh);          ldm_x4t(bh0 + 4, sBh + 32);
        ldm_x4t(bl0 + 0, sBl);          ldm_x4t(bl0 + 4, sBl + 32);
#pragma unroll
        for (int mi = 0; mi < 4; mi++)
            ldm_x4(af + mi * 4, sAh + (uint32_t)(mi * 16 * LDA) * 2);
        ldm_x4t(bh1 + 0, sBh + KBO);    ldm_x4t(bh1 + 4, sBh + KBO + 32);

        // ks=0: A-hi x B-hi
#pragma unroll
        for (int mi = 0; mi < 4; mi++)
#pragma unroll
            for (int ni = 0; ni < 4; ni++)
                mma_bf16(acc[mi][ni], af + mi * 4, bh0 + (ni >> 1) * 4 + (ni & 1) * 2);
        // prefetch ks=1 B-lo under the bl0 MMA block
        ldm_x4t(bl1 + 0, sBl + KBO);    ldm_x4t(bl1 + 4, sBl + KBO + 32);
        // ks=0: A-hi x B-lo
#pragma unroll
        for (int mi = 0; mi < 4; mi++)
#pragma unroll
            for (int ni = 0; ni < 4; ni++)
                mma_bf16(acc[mi][ni], af + mi * 4, bl0 + (ni >> 1) * 4 + (ni & 1) * 2);
        // reload af = A-lo (ks=0), then A-lo x B-hi
#pragma unroll
        for (int mi = 0; mi < 4; mi++)
            ldm_x4(af + mi * 4, sAl + (uint32_t)(mi * 16 * LDA) * 2);
#pragma unroll
        for (int mi = 0; mi < 4; mi++)
#pragma unroll
            for (int ni = 0; ni < 4; ni++)
                mma_bf16(acc[mi][ni], af + mi * 4, bh0 + (ni >> 1) * 4 + (ni & 1) * 2);

        // ks=1: reload af = A-hi
#pragma unroll
        for (int mi = 0; mi < 4; mi++)
            ldm_x4(af + mi * 4, sAh + KAO + (uint32_t)(mi * 16 * LDA) * 2);
#pragma unroll
        for (int mi = 0; mi < 4; mi++)
#pragma unroll
            for (int ni = 0; ni < 4; ni++)
                mma_bf16(acc[mi][ni], af + mi * 4, bh1 + (ni >> 1) * 4 + (ni & 1) * 2);
#pragma unroll
        for (int mi = 0; mi < 4; mi++)
#pragma unroll
            for (int ni = 0; ni < 4; ni++)
                mma_bf16(acc[mi][ni], af + mi * 4, bl1 + (ni >> 1) * 4 + (ni & 1) * 2);
#pragma unroll
        for (int mi = 0; mi < 4; mi++)
            ldm_x4(af + mi * 4, sAl + KAO + (uint32_t)(mi * 16 * LDA) * 2);
#pragma unroll
        for (int mi = 0; mi < 4; mi++)
#pragma unroll
            for (int ni = 0; ni < 4; ni++)
                mma_bf16(acc[mi][ni], af + mi * 4, bh1 + (ni >> 1) * 4 + (ni & 1) * 2);
    }

    int gr = lane >> 2, gc = (lane & 3) * 2;
#pragma unroll
    for (int mi = 0; mi < 4; mi++) {
        int r = row0 + wm + mi * 16 + gr;
#pragma unroll
        for (int ni = 0; ni < 4; ni++) {
            float* Cp = C + (size_t)r * N + col0 + wn + ni * 8 + gc;
            if (r < mlim) {
                if (ATOMIC) { atomicAdd(Cp, acc[mi][ni][0]); atomicAdd(Cp + 1, acc[mi][ni][1]); }
                else { Cp[0] = acc[mi][ni][0]; Cp[1] = acc[mi][ni][1]; }
            }
            if (r + 8 < mlim) {
                float* Cq = Cp + (size_t)8 * N;
                if (ATOMIC) { atomicAdd(Cq, acc[mi][ni][2]); atomicAdd(Cq + 1, acc[mi][ni][3]); }
                else { Cq[0] = acc[mi][ni][2]; Cq[1] = acc[mi][ni][3]; }
            }
        }
    }
}

// merged qkv (z=0..7) + gate (z=8) GEMM launch
__global__ __launch_bounds__(256, 2)
void gemm_qkv_gate(const __nv_bfloat16* __restrict__ xgh, const __nv_bfloat16* __restrict__ xgl,
                   const __nv_bfloat16* __restrict__ qkvh, const __nv_bfloat16* __restrict__ qkvl,
                   float* __restrict__ qkvpre,
                   const __nv_bfloat16* __restrict__ hih, const __nv_bfloat16* __restrict__ hil,
                   const __nv_bfloat16* __restrict__ gwh, const __nv_bfloat16* __restrict__ gwl,
                   float* __restrict__ gg) {
    extern __shared__ __nv_bfloat16 smbuf[];
    int z = blockIdx.z;
    int row0 = blockIdx.y * 128;
    int col0 = blockIdx.x * 128;
    if (z < ENUM) {
        int mlim = d_m[z];
        if (row0 >= mlim) return;
        gemm_core<false>(xgh + (size_t)z * CAP * DDIM, xgl + (size_t)z * CAP * DDIM,
                         qkvh + (size_t)z * DDIM * QKVP, qkvl + (size_t)z * DDIM * QKVP,
                         qkvpre + (size_t)z * CAP * QKVP, mlim, QKVP, DDIM, DDIM,
                         row0, col0, smbuf);
    } else {
        if (col0 >= VDIM) return;
        gemm_core<false>(hih, hil, gwh, gwl, gg, SLEN, VDIM, DDIM, DDIM, row0, col0, smbuf);
    }
}

// split-K output GEMM: z selects K-half, accumulates via atomics.
__global__ __launch_bounds__(256, 2)
void gemm_out_splitk(const __nv_bfloat16* __restrict__ Ahi, const __nv_bfloat16* __restrict__ Alo,
                     const __nv_bfloat16* __restrict__ Bhi, const __nv_bfloat16* __restrict__ Blo,
                     float* __restrict__ C) {
    extern __shared__ __nv_bfloat16 smbuf[];
    int z = blockIdx.z;            // 0,1
    int row0 = blockIdx.y * 128;
    int col0 = blockIdx.x * 128;
    int kHalf = VDIM / 2;          // 1536
    gemm_core<true>(Ahi + (size_t)z * kHalf, Alo + (size_t)z * kHalf,
                    Bhi + (size_t)z * kHalf * DDIM, Blo + (size_t)z * kHalf * DDIM,
                    C, SLEN, DDIM, kHalf, VDIM, row0, col0, smbuf);
}

__global__ void zero_out_kernel(float4* __restrict__ p, int n4) {
    int i = blockIdx.x * 256 + threadIdx.x;
    if (i < n4) p[i] = make_float4(0.f, 0.f, 0.f, 0.f);
}

// ---------------- router ------------------------------------------------------
__global__ void router_kernel(const float* __restrict__ hidden,
                              const float* __restrict__ gate_w) {
    int s = blockIdx.x;
    int tid = threadIdx.x;
    float acc[ENUM];
#pragma unroll
    for (int e = 0; e < ENUM; e++) acc[e] = 0.f;
    const float* xr = hidden + (size_t)s * DDIM;
    for (int d = tid; d < DDIM; d += 256) {
        float x = xr[d];
        const float* w = gate_w + (size_t)d * ENUM;
#pragma unroll
        for (int e = 0; e < ENUM; e++) acc[e] += x * w[e];
    }
    __shared__ float red[ENUM][256];
#pragma unroll
    for (int e = 0; e < ENUM; e++) red[e][tid] = acc[e];
    __syncthreads();
    for (int st = 128; st > 0; st >>= 1) {
        if (tid < st) {
#pragma unroll
            for (int e = 0; e < ENUM; e++) red[e][tid] += red[e][tid + st];
        }
        __syncthreads();
    }
    if (tid == 0) {
        float l[ENUM], mx = -1e30f;
#pragma unroll
        for (int e = 0; e < ENUM; e++) { l[e] = red[e][0]; mx = fmaxf(mx, l[e]); }
        float p[ENUM], sum = 0.f;
#pragma unroll
        for (int e = 0; e < ENUM; e++) { p[e] = expf(l[e] - mx); sum += p[e]; }
#pragma unroll
        for (int e = 0; e < ENUM; e++) p[e] /= sum;
        int i0 = 0;
#pragma unroll
        for (int e = 1; e < ENUM; e++) if (p[e] > p[i0]) i0 = e;
        int i1 = -1;
#pragma unroll
        for (int e = 0; e < ENUM; e++)
            if (e != i0 && (i1 < 0 || p[e] > p[i1])) i1 = e;
        float r0 = p[i0], r1 = p[i1], rs = r0 + r1;
        d_sel[2 * s] = i0;  d_sel[2 * s + 1] = i1;
        d_rw[2 * s] = r0 / rs;  d_rw[2 * s + 1] = r1 / rs;
    }
}

// -------------- dispatch: parallel warp-per-expert ballot scan ----------------
__global__ void dispatch_kernel() {
    int e = threadIdx.x >> 5;
    int lane = threadIdx.x & 31;
    int cnt = 0;
    for (int i = lane; i < SLEN * 2; i += 32) cnt += (d_sel[i] == e);
#pragma unroll
    for (int o = 16; o; o >>= 1) cnt += __shfl_xor_sync(0xffffffffu, cnt, o);
    int drop = cnt > CAP ? cnt - CAP : 0;
    if (lane == 0) d_m[e] = cnt - drop;
    int base = 0;
    for (int i0 = 0; i0 < SLEN * 2; i0 += 32) {
        int i = i0 + lane;
        bool hit = (d_sel[i] == e);
        unsigned mask = __ballot_sync(0xffffffffu, hit);
        if (hit) {
            int r = base + __popc(mask & ((1u << lane) - 1u));
            if (r >= drop) {
                int j = r - drop;
                d_tok[e * CAP + j] = i >> 1;
                d_pos[i] = e * CAP + j;
            } else {
                d_pos[i] = -1;
            }
        }
        base += __popc(mask);
    }
}

// -------------- gather + hi/lo split of activations --------------------------
__global__ void gather_split_kernel(const float* __restrict__ hidden) {
    int row = blockIdx.x;
    int e = row >> 10, t = row & 1023;
    if (t >= d_m[e]) return;
    const float4* src = (const float4*)(hidden + (size_t)d_tok[row] * DDIM);
    __nv_bfloat162* hi = (__nv_bfloat162*)(d_xg_hi + (size_t)row * DDIM);
    __nv_bfloat162* lo = (__nv_bfloat162*)(d_xg_lo + (size_t)row * DDIM);
    for (int i = threadIdx.x; i < DDIM / 4; i += 256) {
        float4 v = src[i];
        __nv_bfloat162 h[2], l[2];
        split4(v, h, l);
        hi[2 * i] = h[0]; hi[2 * i + 1] = h[1];
        lo[2 * i] = l[0]; lo[2 * i + 1] = l[1];
    }
}

// -------------- beta/g epilogue -----------------------------------------------
__global__ void bg_finish_kernel(const float* __restrict__ A_log,
                                 const float* __restrict__ dt_bias) {
    int idx = blockIdx.x * 256 + threadIdx.x;
    if (idx >= NROW * HNUM) return;
    int row = idx / HNUM, h = idx - row * HNUM;
    int e = row >> 10, t = row & 1023;
    if (t >= d_m[e]) return;
    float bl = d_qkvpre[(size_t)row * QKVP + QKVO + h];
    float al = d_qkvpre[(size_t)row * QKVP + QKVO + HNUM + h];
    d_beta[idx] = 1.f / (1.f + expf(-bl));
    float xx = al + dt_bias[h];
    float sp = xx > 20.f ? xx : log1pf(expf(xx));
    d_g[idx] = -expf(A_log[h]) * sp;
}

// -------------- merged conv launch: y<6 q-norm, y<12 k-norm, else v -----------
__global__ void conv_all_kernel(const float* __restrict__ pre,
                                const float* __restrict__ qcw,
                                const float* __restrict__ kcw,
                                const float* __restrict__ vcw) {
    int row = blockIdx.x;
    int y = blockIdx.y;
    int e = row >> 10, t = row & 1023;
    if (t >= d_m[e]) return;
    int tid = threadIdx.x;

    if (y < 12) {
        int h = (y < 6) ? y : (y - 6);
        int preOff = (y < 6) ? 0 : KDIM;
        float scale = (y < 6) ? 0.0625f : 1.0f;
        const float* cw = (y < 6) ? qcw : kcw;
        float* out = (y < 6) ? d_qn : d_kn;
        int ch = h * DKC + tid;
        float yv = 0.f;
#pragma unroll
        for (int j = 0; j < 4; j++) {
            int tt = t - 3 + j;
            if (tt >= 0) yv += cw[ch * 4 + j] * pre[(size_t)(row - 3 + j) * QKVP + preOff + ch];
        }
        yv = yv / (1.f + expf(-yv));
        __shared__ float red[256];
        red[tid] = yv * yv;
        __syncthreads();
        for (int st = 128; st > 0; st >>= 1) {
            if (tid < st) red[tid] += red[tid + st];
            __syncthreads();
        }
        float inv = rsqrtf(red[0] + 1e-6f) * scale;
        out[(size_t)row * KDIM + ch] = yv * inv;
    } else {
        int ch = (y - 12) * 256 + tid;
        float yv = 0.f;
#pragma unroll
        for (int j = 0; j < 4; j++) {
            int tt = t - 3 + j;
            if (tt >= 0) yv += vcw[ch * 4 + j] * pre[(size_t)(row - 3 + j) * QKVP + 2 * KDIM + ch];
        }
        d_vn[(size_t)row * VDIM + ch] = yv / (1.f + expf(-yv));
    }
}

// -------------- gated delta-rule recurrence (conflict-free strided) -----------
__global__ void recur_kernel() {
    int vc = blockIdx.x;
    int h = blockIdx.y;
    int e = blockIdx.z;
    int m = d_m[e];
    __shared__ float S[32 * 256];
    __shared__ float su[32], sw[32], sd[32];
    int tid = threadIdx.x, warp = tid >> 5, lane = tid & 31;
    int v0 = warp * 4;
    for (int i = lane; i < 4 * 256; i += 32) S[v0 * 256 + i] = 0.f;
    if (lane < 4) { su[v0 + lane] = 0.f; sw[v0 + lane] = 0.f; }
    __syncwarp();
    if (m == 0) return;

    const float* kb = d_kn + (size_t)(e * CAP) * KDIM + h * DKC;
    const float* qb = d_qn + (size_t)(e * CAP) * KDIM + h * DKC;
    const float* vb = d_vn + (size_t)(e * CAP) * VDIM + h * DVC + vc * 32;
    const float* bb = d_beta + (size_t)(e * CAP) * HNUM + h;
    const float* gb = d_g + (size_t)(e * CAP) * HNUM + h;
    float* ob = d_o + (size_t)(e * CAP) * VDIM + h * DVC + vc * 32;

    float kc[8], qc[8];
#pragma unroll
    for (int j = 0; j < 8; j++) { kc[j] = kb[lane + 32 * j]; qc[j] = qb[lane + 32 * j]; }
    float beta = bb[0];
    float gv = gb[0];
    float vv = (lane < 4) ? vb[v0 + lane] : 0.f;

    for (int t = 0; t < m; t++) {
        float eg = expf(gv);
        float qk = 0.f;
#pragma unroll
        for (int j = 0; j < 8; j++) qk += kc[j] * qc[j];
#pragma unroll
        for (int o = 16; o; o >>= 1) qk += __shfl_xor_sync(0xffffffffu, qk, o);

        if (lane < 4) {
            int v = v0 + lane;
            float dd = beta * (vv - eg * su[v]);
            ob[(size_t)t * VDIM + v] = eg * sw[v] + qk * dd;
            sd[v] = dd;
        }
        __syncwarp();

        float kn2[8], qn2[8];
        float beta_n = 0.f, g_n = 0.f, vv_n = 0.f;
        if (t + 1 < m) {
            const float* kr = kb + (size_t)(t + 1) * KDIM;
            const float* qr = qb + (size_t)(t + 1) * KDIM;
#pragma unroll
            for (int j = 0; j < 8; j++) { kn2[j] = kr[lane + 32 * j]; qn2[j] = qr[lane + 32 * j]; }
            beta_n = bb[(size_t)(t + 1) * HNUM];
            g_n = gb[(size_t)(t + 1) * HNUM];
            if (lane < 4) vv_n = vb[(size_t)(t + 1) * VDIM + v0 + lane];
        } else {
#pragma unroll
            for (int j = 0; j < 8; j++) { kn2[j] = 0.f; qn2[j] = 0.f; }
        }

#pragma unroll
        for (int vi = 0; vi < 4; vi++) {
            int v = v0 + vi;
            float dd = sd[v];
            float un = 0.f, wn = 0.f;
            float* Sr = &S[v * 256];
#pragma unroll
            for (int j = 0; j < 8; j++) {
                float s2 = Sr[lane + 32 * j];
                s2 = eg * s2 + kc[j] * dd;
                Sr[lane + 32 * j] = s2;
                un += kn2[j] * s2;
                wn += qn2[j] * s2;
            }
#pragma unroll
            for (int o = 16; o; o >>= 1) {
                un += __shfl_xor_sync(0xffffffffu, un, o);
                wn += __shfl_xor_sync(0xffffffffu, wn, o);
            }
            if (lane == 0) { su[v] = un; sw[v] = wn; }
        }
        __syncwarp();
#pragma unroll
        for (int j = 0; j < 8; j++) { kc[j] = kn2[j]; qc[j] = qn2[j]; }
        beta = beta_n; gv = g_n; vv = vv_n;
    }
}

// -------------- combine + gated RMSNorm + bf16 hi/lo (fused) ------------------
__global__ void combine_kernel(const float* __restrict__ norm_w) {
    int s = blockIdx.x, h = blockIdx.y, tid = threadIdx.x;
    int p0 = d_pos[2 * s], p1 = d_pos[2 * s + 1];
    float r0 = d_rw[2 * s], r1 = d_rw[2 * s + 1];
    float acc[2];
    float ss = 0.f;
#pragma unroll
    for (int i = 0; i < 2; i++) {
        int v = tid + i * 256;
        float a = 0.f;
        if (p0 >= 0) a += r0 * d_o[(size_t)p0 * VDIM + h * DVC + v];
        if (p1 >= 0) a += r1 * d_o[(size_t)p1 * VDIM + h * DVC + v];
        acc[i] = a;
        ss += a * a;
    }
    __shared__ float red[256];
    red[tid] = ss;
    __syncthreads();
    for (int st = 128; st > 0; st >>= 1) {
        if (tid < st) red[tid] += red[tid + st];
        __syncthreads();
    }
    float inv = rsqrtf(red[0] / (float)DVC + 1e-5f);
#pragma unroll
    for (int i = 0; i < 2; i++) {
        int v = tid + i * 256;
        float gg = d_gg[(size_t)s * VDIM + h * DVC + v];
        float sg = gg / (1.f + expf(-gg));
        float val = acc[i] * inv * norm_w[v] * sg;
        __nv_bfloat16 hb = __float2bfloat16(val);
        __nv_bfloat16 lb = __float2bfloat16(val - __bfloat162float(hb));
        size_t idx = (size_t)s * VDIM + h * DVC + v;
        d_pre_hi[idx] = hb;
        d_pre_lo[idx] = lb;
    }
}

// ----------------------------- launch -----------------------------------------
extern "C" void kernel_launch(void* const* d_in, const int* in_sizes, int n_in,
                              void* d_out, int out_size) {
    const float* hidden  = (const float*)d_in[0];
    const float* q_w     = (const float*)d_in[1];
    const float* gate_w  = (const float*)d_in[2];
    const float* k_w     = (const float*)d_in[3];
    const float* v_w     = (const float*)d_in[4];
    const float* b_w     = (const float*)d_in[5];
    const float* a_w     = (const float*)d_in[6];
    const float* A_log   = (const float*)d_in[7];
    const float* dt_bias = (const float*)d_in[8];
    const float* qcw     = (const float*)d_in[9];
    const float* kcw     = (const float*)d_in[10];
    const float* vcw     = (const float*)d_in[11];
    const float* g_w     = (const float*)d_in[12];
    const float* norm_w  = (const float*)d_in[13];
    const float* o_w     = (const float*)d_in[14];

    float* qkvpre = 0; float* gg = 0;
    cudaGetSymbolAddress((void**)&qkvpre, d_qkvpre);
    cudaGetSymbolAddress((void**)&gg, d_gg);

    __nv_bfloat16* xgh = 0; __nv_bfloat16* xgl = 0;
    __nv_bfloat16* qkvh = 0; __nv_bfloat16* qkvl = 0;
    __nv_bfloat16* gwh = 0; __nv_bfloat16* gwl = 0;
    __nv_bfloat16* owh = 0; __nv_bfloat16* owl = 0;
    __nv_bfloat16* hih = 0; __nv_bfloat16* hil = 0;
    __nv_bfloat16* prh = 0; __nv_bfloat16* prl = 0;
    cudaGetSymbolAddress((void**)&xgh, d_xg_hi);
    cudaGetSymbolAddress((void**)&xgl, d_xg_lo);
    cudaGetSymbolAddress((void**)&qkvh, d_qkvw_hi);
    cudaGetSymbolAddress((void**)&qkvl, d_qkvw_lo);
    cudaGetSymbolAddress((void**)&gwh, d_gw_hi);
    cudaGetSymbolAddress((void**)&gwl, d_gw_lo);
    cudaGetSymbolAddress((void**)&owh, d_ow_hi);
    cudaGetSymbolAddress((void**)&owl, d_ow_lo);
    cudaGetSymbolAddress((void**)&hih, d_hid_hi);
    cudaGetSymbolAddress((void**)&hil, d_hid_lo);
    cudaGetSymbolAddress((void**)&prh, d_pre_hi);
    cudaGetSymbolAddress((void**)&prl, d_pre_lo);

    cudaFuncSetAttribute(gemm_qkv_gate, cudaFuncAttributeMaxDynamicSharedMemorySize, GEMM_SMEM);
    cudaFuncSetAttribute(gemm_out_splitk, cudaFuncAttributeMaxDynamicSharedMemorySize, GEMM_SMEM);

    // 1: pack all weights
    pack_w_kernel<<<(int)((TOT_U + 255) / 256), 256>>>(q_w, k_w, v_w, b_w, a_w, g_w, o_w, hidden);
    // 2: zero output (early; independent)
    zero_out_kernel<<<(SLEN * DDIM / 4 + 255) / 256, 256>>>((float4*)d_out, SLEN * DDIM / 4);
    // 3-4: routing
    router_kernel<<<SLEN, 256>>>(hidden, gate_w);
    dispatch_kernel<<<1, 256>>>();
    // 5: gather + activation split
    gather_split_kernel<<<NROW, 256>>>(hidden);
    // 6: merged qkv (z<8) + gate (z=8) projections
    gemm_qkv_gate<<<dim3(QKVP / 128, CAP / 128, ENUM + 1), 256, GEMM_SMEM>>>(
        xgh, xgl, qkvh, qkvl, qkvpre, hih, hil, gwh, gwl, gg);

    bg_finish_kernel<<<(NROW * HNUM + 255) / 256, 256>>>(A_log, dt_bias);

    // 7: merged convs (q norm / k norm / v)
    conv_all_kernel<<<dim3(NROW, 24), 256>>>(qkvpre, qcw, kcw, vcw);

    recur_kernel<<<dim3(DVC / 32, HNUM, ENUM), 256>>>();

    combine_kernel<<<dim3(SLEN, HNUM), 256>>>(norm_w);
    // 8: split-K output GEMM (atomic accumulate into zeroed d_out)
    gemm_out_splitk<<<dim3(DDIM / 128, SLEN / 128, 2), 256, GEMM_SMEM>>>(
        prh, prl, owh, owl, (float*)d_out);
}

// round 13
// speedup vs baseline: 1.3324x; 1.0450x over previous
#include <cuda_runtime.h>
#include <cuda_bf16.h>
#include <stdint.h>
#include <math.h>

#define SLEN 1024
#define DDIM 2048
#define ENUM 8
#define HNUM 6
#define DKC  256
#define DVC  512
#define KDIM 1536   // HNUM*DKC
#define VDIM 3072   // HNUM*DVC
#define QKVO 6144   // q+k+v data cols
#define QKVP 6272   // padded: + 12 beta/g cols + zero pad (49*128)
#define CAP  1024
#define NROW (ENUM*CAP)

// ---------------- scratch (device globals; no allocation in kernel_launch) ----
__device__ int   d_sel[SLEN*2];
__device__ float d_rw [SLEN*2];
__device__ int   d_m  [ENUM];
__device__ int   d_tok[NROW];
__device__ int   d_pos[SLEN*2];
__device__ float d_qkvpre[(size_t)NROW*QKVP];
__device__ float d_qn  [NROW*KDIM];
__device__ float d_kn  [NROW*KDIM];
__device__ float d_vn  [NROW*VDIM];
__device__ float d_beta[NROW*HNUM];
__device__ float d_g   [NROW*HNUM];
__device__ float d_o   [NROW*VDIM];
__device__ float d_gg  [SLEN*VDIM];

// bf16 hi/lo split buffers
__device__ __align__(256) __nv_bfloat16 d_xg_hi[NROW*DDIM];
__device__ __align__(256) __nv_bfloat16 d_xg_lo[NROW*DDIM];
__device__ __align__(256) __nv_bfloat16 d_qkvw_hi[(size_t)ENUM*DDIM*QKVP];
__device__ __align__(256) __nv_bfloat16 d_qkvw_lo[(size_t)ENUM*DDIM*QKVP];
__device__ __align__(256) __nv_bfloat16 d_gw_hi[DDIM*VDIM];
__device__ __align__(256) __nv_bfloat16 d_gw_lo[DDIM*VDIM];
__device__ __align__(256) __nv_bfloat16 d_ow_hi[VDIM*DDIM];
__device__ __align__(256) __nv_bfloat16 d_ow_lo[VDIM*DDIM];
__device__ __align__(256) __nv_bfloat16 d_hid_hi[SLEN*DDIM];
__device__ __align__(256) __nv_bfloat16 d_hid_lo[SLEN*DDIM];
__device__ __align__(256) __nv_bfloat16 d_pre_hi[SLEN*VDIM];
__device__ __align__(256) __nv_bfloat16 d_pre_lo[SLEN*VDIM];

// ---------------- PTX helpers -------------------------------------------------
__device__ __forceinline__ void cpa16(uint32_t d, const void* s) {
    asm volatile("cp.async.cg.shared.global [%0], [%1], 16;" :: "r"(d), "l"(s));
}
__device__ __forceinline__ void ldm_x4(uint32_t* r, uint32_t a) {
    asm volatile("ldmatrix.sync.aligned.m8n8.x4.shared.b16 {%0,%1,%2,%3}, [%4];"
                 : "=r"(r[0]), "=r"(r[1]), "=r"(r[2]), "=r"(r[3]) : "r"(a));
}
__device__ __forceinline__ void ldm_x4t(uint32_t* r, uint32_t a) {
    asm volatile("ldmatrix.sync.aligned.m8n8.x4.trans.shared.b16 {%0,%1,%2,%3}, [%4];"
                 : "=r"(r[0]), "=r"(r[1]), "=r"(r[2]), "=r"(r[3]) : "r"(a));
}
__device__ __forceinline__ void mma_bf16(float* c, const uint32_t* a, const uint32_t* b) {
    asm volatile(
        "mma.sync.aligned.m16n8k16.row.col.f32.bf16.bf16.f32 "
        "{%0,%1,%2,%3},{%4,%5,%6,%7},{%8,%9},{%0,%1,%2,%3};"
        : "+f"(c[0]), "+f"(c[1]), "+f"(c[2]), "+f"(c[3])
        : "r"(a[0]), "r"(a[1]), "r"(a[2]), "r"(a[3]), "r"(b[0]), "r"(b[1]));
}

// ---------------- hi/lo split conversion --------------------------------------
__device__ __forceinline__ void split4(float4 v, __nv_bfloat162* hi, __nv_bfloat162* lo) {
    __nv_bfloat16 h0 = __float2bfloat16(v.x), h1 = __float2bfloat16(v.y);
    __nv_bfloat16 h2 = __float2bfloat16(v.z), h3 = __float2bfloat16(v.w);
    __nv_bfloat16 l0 = __float2bfloat16(v.x - __bfloat162float(h0));
    __nv_bfloat16 l1 = __float2bfloat16(v.y - __bfloat162float(h1));
    __nv_bfloat16 l2 = __float2bfloat16(v.z - __bfloat162float(h2));
    __nv_bfloat16 l3 = __float2bfloat16(v.w - __bfloat162float(h3));
    hi[0] = __halves2bfloat162(h0, h1);
    hi[1] = __halves2bfloat162(h2, h3);
    lo[0] = __halves2bfloat162(l0, l1);
    lo[1] = __halves2bfloat162(l2, l3);
}

// -------------- mega-pack: qkv+bg fused weights + gate/out/hidden splits -----
#define QKV_U (ENUM*DDIM*(QKVP/4))
#define GW_U  (DDIM*VDIM/4)
#define OW_U  (VDIM*DDIM/4)
#define HID_U (SLEN*DDIM/4)
#define TOT_U (QKV_U + GW_U + OW_U + HID_U)

__global__ void pack_w_kernel(const float* __restrict__ q_w, const float* __restrict__ k_w,
                              const float* __restrict__ v_w, const float* __restrict__ b_w,
                              const float* __restrict__ a_w, const float* __restrict__ g_w,
                              const float* __restrict__ o_w, const float* __restrict__ hidden) {
    long long u = (long long)blockIdx.x * 256 + threadIdx.x;
    if (u >= TOT_U) return;
    if (u < QKV_U) {
        long long per_e = (long long)DDIM * (QKVP / 4);
        int e = (int)(u / per_e);
        long long r = u - (long long)e * per_e;
        int d = (int)(r / (QKVP / 4));
        int c4 = (int)(r - (long long)d * (QKVP / 4));
        int n = c4 * 4;
        float4 src;
        if (n < KDIM) {
            src = *(const float4*)(q_w + (size_t)d * KDIM + n);
        } else if (n < 2 * KDIM) {
            src = *(const float4*)(k_w + ((size_t)e * DDIM + d) * KDIM + (n - KDIM));
        } else if (n < QKVO) {
            src = *(const float4*)(v_w + ((size_t)e * DDIM + d) * VDIM + (n - 2 * KDIM));
        } else {
            float vals[4];
#pragma unroll
            for (int j = 0; j < 4; j++) {
                int c = n + j;
                if (c < QKVO + HNUM)
                    vals[j] = b_w[((size_t)e * DDIM + d) * HNUM + (c - QKVO)];
                else if (c < QKVO + 2 * HNUM)
                    vals[j] = a_w[((size_t)e * DDIM + d) * HNUM + (c - QKVO - HNUM)];
                else
                    vals[j] = 0.f;
            }
            src = make_float4(vals[0], vals[1], vals[2], vals[3]);
        }
        size_t dst = ((size_t)e * DDIM + d) * QKVP + n;
        __nv_bfloat162 h[2], l[2];
        split4(src, h, l);
        __nv_bfloat162* hp = (__nv_bfloat162*)(d_qkvw_hi + dst);
        __nv_bfloat162* lp = (__nv_bfloat162*)(d_qkvw_lo + dst);
        hp[0] = h[0]; hp[1] = h[1]; lp[0] = l[0]; lp[1] = l[1];
        return;
    }
    u -= QKV_U;
    if (u < GW_U) {
        float4 src = ((const float4*)g_w)[u];
        __nv_bfloat162 h[2], l[2]; split4(src, h, l);
        ((__nv_bfloat162*)d_gw_hi)[2 * u] = h[0]; ((__nv_bfloat162*)d_gw_hi)[2 * u + 1] = h[1];
        ((__nv_bfloat162*)d_gw_lo)[2 * u] = l[0]; ((__nv_bfloat162*)d_gw_lo)[2 * u + 1] = l[1];
        return;
    }
    u -= GW_U;
    if (u < OW_U) {
        float4 src = ((const float4*)o_w)[u];
        __nv_bfloat162 h[2], l[2]; split4(src, h, l);
        ((__nv_bfloat162*)d_ow_hi)[2 * u] = h[0]; ((__nv_bfloat162*)d_ow_hi)[2 * u + 1] = h[1];
        ((__nv_bfloat162*)d_ow_lo)[2 * u] = l[0]; ((__nv_bfloat162*)d_ow_lo)[2 * u + 1] = l[1];
        return;
    }
    u -= OW_U;
    {
        float4 src = ((const float4*)hidden)[u];
        __nv_bfloat162 h[2], l[2]; split4(src, h, l);
        ((__nv_bfloat162*)d_hid_hi)[2 * u] = h[0]; ((__nv_bfloat162*)d_hid_hi)[2 * u + 1] = h[1];
        ((__nv_bfloat162*)d_hid_lo)[2 * u] = l[0]; ((__nv_bfloat162*)d_hid_lo)[2 * u + 1] = l[1];
    }
}

// ---------------- tensor-core split-bf16 GEMM core ----------------------------
// Swizzled smem (zero padding): stage = 32KB -> 3 stages = 96KB -> 2 CTAs/SM.
// A tile 128x32 halfs, 64B rows: chunk' = chunk ^ ((row>>1)&3)
// B tile 32x128 halfs, 256B rows: chunk' = chunk ^ (row&7)
#define A_BYTES 8192
#define B_BYTES 8192
#define STAGE_BYTES 32768
#define NSTAGE 3
#define GEMM_SMEM (NSTAGE*STAGE_BYTES)

template<bool ATOMIC>
__device__ __forceinline__ void gemm_core(
    const __nv_bfloat16* __restrict__ Ahi, const __nv_bfloat16* __restrict__ Alo,
    const __nv_bfloat16* __restrict__ Bhi, const __nv_bfloat16* __restrict__ Blo,
    float* __restrict__ C, int mlim, int N, int K, int lda, int row0, int col0,
    __nv_bfloat16* smbuf) {
    uint32_t sbase = (uint32_t)__cvta_generic_to_shared(smbuf);
    int t = threadIdx.x;

    // loader mapping
    int arow = t >> 1, ac0 = (t & 1) * 2;            // A: row, 2 chunks of 8 halfs
    int brow = t >> 3, bc0 = (t & 7) * 2;            // B: row, 2 chunks
    uint32_t aswr = ((uint32_t)(arow >> 1)) & 3u;
    uint32_t bswr = (uint32_t)(brow & 7);
    const __nv_bfloat16* gAh = Ahi + (size_t)(row0 + arow) * lda;
    const __nv_bfloat16* gAl = Alo + (size_t)(row0 + arow) * lda;
    const __nv_bfloat16* gBh = Bhi + (size_t)brow * N + col0;
    const __nv_bfloat16* gBl = Blo + (size_t)brow * N + col0;
    uint32_t aoff0 = (uint32_t)(arow * 64) + (((uint32_t)ac0 ^ aswr) * 16);
    uint32_t aoff1 = (uint32_t)(arow * 64) + ((((uint32_t)ac0 + 1u) ^ aswr) * 16);
    uint32_t boff0 = (uint32_t)(brow * 256) + (((uint32_t)bc0 ^ bswr) * 16);
    uint32_t boff1 = (uint32_t)(brow * 256) + ((((uint32_t)bc0 + 1u) ^ bswr) * 16);

    int lane = t & 31, wid = t >> 5;
    int wm = (wid >> 2) * 64, wn = (wid & 3) * 32;
    // A fragment addressing
    int lr = lane & 15;
    uint32_t swA = ((uint32_t)(lr >> 1)) & 3u;
    uint32_t achb = (uint32_t)(lane >> 4);
    uint32_t arowb = (uint32_t)((wm + lr) * 64);
    // B fragment addressing
    int blr = lane & 7, bgp = lane >> 3;
    uint32_t cbB = (uint32_t)((wid & 3) * 4 + (bgp >> 1));
    uint32_t brb = (uint32_t)(blr + (bgp & 1) * 8);

    float acc[4][4][4];
#pragma unroll
    for (int mi = 0; mi < 4; mi++)
#pragma unroll
        for (int ni = 0; ni < 4; ni++)
#pragma unroll
            for (int j = 0; j < 4; j++) acc[mi][ni][j] = 0.f;

    int KT = K / 32;

    auto load_stage = [&](int ktl) {
        int k0 = ktl * 32;
        uint32_t so = sbase + (uint32_t)((ktl % NSTAGE) * STAGE_BYTES);
        cpa16(so + aoff0, gAh + k0 + ac0 * 8);
        cpa16(so + aoff1, gAh + k0 + ac0 * 8 + 8);
        cpa16(so + A_BYTES + aoff0, gAl + k0 + ac0 * 8);
        cpa16(so + A_BYTES + aoff1, gAl + k0 + ac0 * 8 + 8);
        cpa16(so + 2 * A_BYTES + boff0, gBh + (size_t)k0 * N + bc0 * 8);
        cpa16(so + 2 * A_BYTES + boff1, gBh + (size_t)k0 * N + bc0 * 8 + 8);
        cpa16(so + 2 * A_BYTES + B_BYTES + boff0, gBl + (size_t)k0 * N + bc0 * 8);
        cpa16(so + 2 * A_BYTES + B_BYTES + boff1, gBl + (size_t)k0 * N + bc0 * 8 + 8);
        asm volatile("cp.async.commit_group;");
    };

    load_stage(0);
    if (KT > 1) load_stage(1);

    for (int kt = 0; kt < KT; kt++) {
        if (kt + 1 < KT) {
            asm volatile("cp.async.wait_group 1;");
        } else {
            asm volatile("cp.async.wait_group 0;");
        }
        __syncthreads();
        if (kt + 2 < KT) load_stage(kt + 2);

        uint32_t s0 = sbase + (uint32_t)((kt % NSTAGE) * STAGE_BYTES);
        uint32_t sAh = s0;
        uint32_t sAl = s0 + A_BYTES;
        uint32_t sBh = s0 + 2 * A_BYTES;
        uint32_t sBl = s0 + 2 * A_BYTES + B_BYTES;

#pragma unroll
        for (int ks = 0; ks < 2; ks++) {
            // B addresses (swizzled)
            uint32_t rB = brb + (uint32_t)(ks * 16);
            uint32_t bo0 = rB * 256 + ((cbB ^ (uint32_t)blr) * 16);
            uint32_t bo1 = rB * 256 + (((cbB + 2u) ^ (uint32_t)blr) * 16);
            // A addresses (swizzled)
            uint32_t ach = achb + (uint32_t)(ks * 2);
            uint32_t ao = arowb + ((ach ^ swA) * 16);

            uint32_t bh[8], bl2[8], af[16];
            ldm_x4t(bh + 0, sBh + bo0);
            ldm_x4t(bh + 4, sBh + bo1);
            ldm_x4t(bl2 + 0, sBl + bo0);
            ldm_x4t(bl2 + 4, sBl + bo1);
#pragma unroll
            for (int mi = 0; mi < 4; mi++)
                ldm_x4(af + mi * 4, sAh + ao + (uint32_t)(mi * 1024));
#pragma unroll
            for (int mi = 0; mi < 4; mi++)
#pragma unroll
                for (int ni = 0; ni < 4; ni++)
                    mma_bf16(acc[mi][ni], af + mi * 4, bh + (ni >> 1) * 4 + (ni & 1) * 2);
#pragma unroll
            for (int mi = 0; mi < 4; mi++)
#pragma unroll
                for (int ni = 0; ni < 4; ni++)
                    mma_bf16(acc[mi][ni], af + mi * 4, bl2 + (ni >> 1) * 4 + (ni & 1) * 2);
#pragma unroll
            for (int mi = 0; mi < 4; mi++)
                ldm_x4(af + mi * 4, sAl + ao + (uint32_t)(mi * 1024));
#pragma unroll
            for (int mi = 0; mi < 4; mi++)
#pragma unroll
                for (int ni = 0; ni < 4; ni++)
                    mma_bf16(acc[mi][ni], af + mi * 4, bh + (ni >> 1) * 4 + (ni & 1) * 2);
        }
    }

    int gr = lane >> 2, gc = (lane & 3) * 2;
#pragma unroll
    for (int mi = 0; mi < 4; mi++) {
        int r = row0 + wm + mi * 16 + gr;
#pragma unroll
        for (int ni = 0; ni < 4; ni++) {
            float* Cp = C + (size_t)r * N + col0 + wn + ni * 8 + gc;
            if (r < mlim) {
                if (ATOMIC) { atomicAdd(Cp, acc[mi][ni][0]); atomicAdd(Cp + 1, acc[mi][ni][1]); }
                else { Cp[0] = acc[mi][ni][0]; Cp[1] = acc[mi][ni][1]; }
            }
            if (r + 8 < mlim) {
                float* Cq = Cp + (size_t)8 * N;
                if (ATOMIC) { atomicAdd(Cq, acc[mi][ni][2]); atomicAdd(Cq + 1, acc[mi][ni][3]); }
                else { Cq[0] = acc[mi][ni][2]; Cq[1] = acc[mi][ni][3]; }
            }
        }
    }
}

// merged qkv (z=0..7) + gate (z=8) GEMM launch
__global__ __launch_bounds__(256, 2)
void gemm_qkv_gate(const __nv_bfloat16* __restrict__ xgh, const __nv_bfloat16* __restrict__ xgl,
                   const __nv_bfloat16* __restrict__ qkvh, const __nv_bfloat16* __restrict__ qkvl,
                   float* __restrict__ qkvpre,
                   const __nv_bfloat16* __restrict__ hih, const __nv_bfloat16* __restrict__ hil,
                   const __nv_bfloat16* __restrict__ gwh, const __nv_bfloat16* __restrict__ gwl,
                   float* __restrict__ gg) {
    extern __shared__ __nv_bfloat16 smbuf[];
    int z = blockIdx.z;
    int row0 = blockIdx.y * 128;
    int col0 = blockIdx.x * 128;
    if (z < ENUM) {
        int mlim = d_m[z];
        if (row0 >= mlim) return;
        gemm_core<false>(xgh + (size_t)z * CAP * DDIM, xgl + (size_t)z * CAP * DDIM,
                         qkvh + (size_t)z * DDIM * QKVP, qkvl + (size_t)z * DDIM * QKVP,
                         qkvpre + (size_t)z * CAP * QKVP, mlim, QKVP, DDIM, DDIM,
                         row0, col0, smbuf);
    } else {
        if (col0 >= VDIM) return;
        gemm_core<false>(hih, hil, gwh, gwl, gg, SLEN, VDIM, DDIM, DDIM, row0, col0, smbuf);
    }
}

// split-K output GEMM: z selects K-half, accumulates via atomics.
__global__ __launch_bounds__(256, 2)
void gemm_out_splitk(const __nv_bfloat16* __restrict__ Ahi, const __nv_bfloat16* __restrict__ Alo,
                     const __nv_bfloat16* __restrict__ Bhi, const __nv_bfloat16* __restrict__ Blo,
                     float* __restrict__ C) {
    extern __shared__ __nv_bfloat16 smbuf[];
    int z = blockIdx.z;
    int row0 = blockIdx.y * 128;
    int col0 = blockIdx.x * 128;
    int kHalf = VDIM / 2;
    gemm_core<true>(Ahi + (size_t)z * kHalf, Alo + (size_t)z * kHalf,
                    Bhi + (size_t)z * kHalf * DDIM, Blo + (size_t)z * kHalf * DDIM,
                    C, SLEN, DDIM, kHalf, VDIM, row0, col0, smbuf);
}

__global__ void zero_out_kernel(float4* __restrict__ p, int n4) {
    int i = blockIdx.x * 256 + threadIdx.x;
    if (i < n4) p[i] = make_float4(0.f, 0.f, 0.f, 0.f);
}

// ---------------- router ------------------------------------------------------
__global__ void router_kernel(const float* __restrict__ hidden,
                              const float* __restrict__ gate_w) {
    int s = blockIdx.x;
    int tid = threadIdx.x;
    float acc[ENUM];
#pragma unroll
    for (int e = 0; e < ENUM; e++) acc[e] = 0.f;
    const float* xr = hidden + (size_t)s * DDIM;
    for (int d = tid; d < DDIM; d += 256) {
        float x = xr[d];
        const float* w = gate_w + (size_t)d * ENUM;
#pragma unroll
        for (int e = 0; e < ENUM; e++) acc[e] += x * w[e];
    }
    __shared__ float red[ENUM][256];
#pragma unroll
    for (int e = 0; e < ENUM; e++) red[e][tid] = acc[e];
    __syncthreads();
    for (int st = 128; st > 0; st >>= 1) {
        if (tid < st) {
#pragma unroll
            for (int e = 0; e < ENUM; e++) red[e][tid] += red[e][tid + st];
        }
        __syncthreads();
    }
    if (tid == 0) {
        float l[ENUM], mx = -1e30f;
#pragma unroll
        for (int e = 0; e < ENUM; e++) { l[e] = red[e][0]; mx = fmaxf(mx, l[e]); }
        float p[ENUM], sum = 0.f;
#pragma unroll
        for (int e = 0; e < ENUM; e++) { p[e] = expf(l[e] - mx); sum += p[e]; }
#pragma unroll
        for (int e = 0; e < ENUM; e++) p[e] /= sum;
        int i0 = 0;
#pragma unroll
        for (int e = 1; e < ENUM; e++) if (p[e] > p[i0]) i0 = e;
        int i1 = -1;
#pragma unroll
        for (int e = 0; e < ENUM; e++)
            if (e != i0 && (i1 < 0 || p[e] > p[i1])) i1 = e;
        float r0 = p[i0], r1 = p[i1], rs = r0 + r1;
        d_sel[2 * s] = i0;  d_sel[2 * s + 1] = i1;
        d_rw[2 * s] = r0 / rs;  d_rw[2 * s + 1] = r1 / rs;
    }
}

// -------------- dispatch: parallel warp-per-expert ballot scan ----------------
__global__ void dispatch_kernel() {
    int e = threadIdx.x >> 5;
    int lane = threadIdx.x & 31;
    int cnt = 0;
    for (int i = lane; i < SLEN * 2; i += 32) cnt += (d_sel[i] == e);
#pragma unroll
    for (int o = 16; o; o >>= 1) cnt += __shfl_xor_sync(0xffffffffu, cnt, o);
    int drop = cnt > CAP ? cnt - CAP : 0;
    if (lane == 0) d_m[e] = cnt - drop;
    int base = 0;
    for (int i0 = 0; i0 < SLEN * 2; i0 += 32) {
        int i = i0 + lane;
        bool hit = (d_sel[i] == e);
        unsigned mask = __ballot_sync(0xffffffffu, hit);
        if (hit) {
            int r = base + __popc(mask & ((1u << lane) - 1u));
            if (r >= drop) {
                int j = r - drop;
                d_tok[e * CAP + j] = i >> 1;
                d_pos[i] = e * CAP + j;
            } else {
                d_pos[i] = -1;
            }
        }
        base += __popc(mask);
    }
}

// -------------- gather + hi/lo split of activations --------------------------
__global__ void gather_split_kernel(const float* __restrict__ hidden) {
    int row = blockIdx.x;
    int e = row >> 10, t = row & 1023;
    if (t >= d_m[e]) return;
    const float4* src = (const float4*)(hidden + (size_t)d_tok[row] * DDIM);
    __nv_bfloat162* hi = (__nv_bfloat162*)(d_xg_hi + (size_t)row * DDIM);
    __nv_bfloat162* lo = (__nv_bfloat162*)(d_xg_lo + (size_t)row * DDIM);
    for (int i = threadIdx.x; i < DDIM / 4; i += 256) {
        float4 v = src[i];
        __nv_bfloat162 h[2], l[2];
        split4(v, h, l);
        hi[2 * i] = h[0]; hi[2 * i + 1] = h[1];
        lo[2 * i] = l[0]; lo[2 * i + 1] = l[1];
    }
}

// -------------- beta/g epilogue -----------------------------------------------
__global__ void bg_finish_kernel(const float* __restrict__ A_log,
                                 const float* __restrict__ dt_bias) {
    int idx = blockIdx.x * 256 + threadIdx.x;
    if (idx >= NROW * HNUM) return;
    int row = idx / HNUM, h = idx - row * HNUM;
    int e = row >> 10, t = row & 1023;
    if (t >= d_m[e]) return;
    float bl = d_qkvpre[(size_t)row * QKVP + QKVO + h];
    float al = d_qkvpre[(size_t)row * QKVP + QKVO + HNUM + h];
    d_beta[idx] = 1.f / (1.f + expf(-bl));
    float xx = al + dt_bias[h];
    float sp = xx > 20.f ? xx : log1pf(expf(xx));
    d_g[idx] = -expf(A_log[h]) * sp;
}

// -------------- merged conv launch: y<6 q-norm, y<12 k-norm, else v -----------
__global__ void conv_all_kernel(const float* __restrict__ pre,
                                const float* __restrict__ qcw,
                                const float* __restrict__ kcw,
                                const float* __restrict__ vcw) {
    int row = blockIdx.x;
    int y = blockIdx.y;
    int e = row >> 10, t = row & 1023;
    if (t >= d_m[e]) return;
    int tid = threadIdx.x;

    if (y < 12) {
        int h = (y < 6) ? y : (y - 6);
        int preOff = (y < 6) ? 0 : KDIM;
        float scale = (y < 6) ? 0.0625f : 1.0f;
        const float* cw = (y < 6) ? qcw : kcw;
        float* out = (y < 6) ? d_qn : d_kn;
        int ch = h * DKC + tid;
        float yv = 0.f;
#pragma unroll
        for (int j = 0; j < 4; j++) {
            int tt = t - 3 + j;
            if (tt >= 0) yv += cw[ch * 4 + j] * pre[(size_t)(row - 3 + j) * QKVP + preOff + ch];
        }
        yv = yv / (1.f + expf(-yv));
        __shared__ float red[256];
        red[tid] = yv * yv;
        __syncthreads();
        for (int st = 128; st > 0; st >>= 1) {
            if (tid < st) red[tid] += red[tid + st];
            __syncthreads();
        }
        float inv = rsqrtf(red[0] + 1e-6f) * scale;
        out[(size_t)row * KDIM + ch] = yv * inv;
    } else {
        int ch = (y - 12) * 256 + tid;
        float yv = 0.f;
#pragma unroll
        for (int j = 0; j < 4; j++) {
            int tt = t - 3 + j;
            if (tt >= 0) yv += vcw[ch * 4 + j] * pre[(size_t)(row - 3 + j) * QKVP + 2 * KDIM + ch];
        }
        d_vn[(size_t)row * VDIM + ch] = yv / (1.f + expf(-yv));
    }
}

// -------------- gated delta-rule recurrence (conflict-free strided) -----------
__global__ void recur_kernel() {
    int vc = blockIdx.x;
    int h = blockIdx.y;
    int e = blockIdx.z;
    int m = d_m[e];
    __shared__ float S[32 * 256];
    __shared__ float su[32], sw[32], sd[32];
    int tid = threadIdx.x, warp = tid >> 5, lane = tid & 31;
    int v0 = warp * 4;
    for (int i = lane; i < 4 * 256; i += 32) S[v0 * 256 + i] = 0.f;
    if (lane < 4) { su[v0 + lane] = 0.f; sw[v0 + lane] = 0.f; }
    __syncwarp();
    if (m == 0) return;

    const float* kb = d_kn + (size_t)(e * CAP) * KDIM + h * DKC;
    const float* qb = d_qn + (size_t)(e * CAP) * KDIM + h * DKC;
    const float* vb = d_vn + (size_t)(e * CAP) * VDIM + h * DVC + vc * 32;
    const float* bb = d_beta + (size_t)(e * CAP) * HNUM + h;
    const float* gb = d_g + (size_t)(e * CAP) * HNUM + h;
    float* ob = d_o + (size_t)(e * CAP) * VDIM + h * DVC + vc * 32;

    float kc[8], qc[8];
#pragma unroll
    for (int j = 0; j < 8; j++) { kc[j] = kb[lane + 32 * j]; qc[j] = qb[lane + 32 * j]; }
    float beta = bb[0];
    float gv = gb[0];
    float vv = (lane < 4) ? vb[v0 + lane] : 0.f;

    for (int t = 0; t < m; t++) {
        float eg = expf(gv);
        float qk = 0.f;
#pragma unroll
        for (int j = 0; j < 8; j++) qk += kc[j] * qc[j];
#pragma unroll
        for (int o = 16; o; o >>= 1) qk += __shfl_xor_sync(0xffffffffu, qk, o);

        if (lane < 4) {
            int v = v0 + lane;
            float dd = beta * (vv - eg * su[v]);
            ob[(size_t)t * VDIM + v] = eg * sw[v] + qk * dd;
            sd[v] = dd;
        }
        __syncwarp();

        float kn2[8], qn2[8];
        float beta_n = 0.f, g_n = 0.f, vv_n = 0.f;
        if (t + 1 < m) {
            const float* kr = kb + (size_t)(t + 1) * KDIM;
            const float* qr = qb + (size_t)(t + 1) * KDIM;
#pragma unroll
            for (int j = 0; j < 8; j++) { kn2[j] = kr[lane + 32 * j]; qn2[j] = qr[lane + 32 * j]; }
            beta_n = bb[(size_t)(t + 1) * HNUM];
            g_n = gb[(size_t)(t + 1) * HNUM];
            if (lane < 4) vv_n = vb[(size_t)(t + 1) * VDIM + v0 + lane];
        } else {
#pragma unroll
            for (int j = 0; j < 8; j++) { kn2[j] = 0.f; qn2[j] = 0.f; }
        }

#pragma unroll
        for (int vi = 0; vi < 4; vi++) {
            int v = v0 + vi;
            float dd = sd[v];
            float un = 0.f, wn = 0.f;
            float* Sr = &S[v * 256];
#pragma unroll
            for (int j = 0; j < 8; j++) {
                float s2 = Sr[lane + 32 * j];
                s2 = eg * s2 + kc[j] * dd;
                Sr[lane + 32 * j] = s2;
                un += kn2[j] * s2;
                wn += qn2[j] * s2;
            }
#pragma unroll
            for (int o = 16; o; o >>= 1) {
                un += __shfl_xor_sync(0xffffffffu, un, o);
                wn += __shfl_xor_sync(0xffffffffu, wn, o);
            }
            if (lane == 0) { su[v] = un; sw[v] = wn; }
        }
        __syncwarp();
#pragma unroll
        for (int j = 0; j < 8; j++) { kc[j] = kn2[j]; qc[j] = qn2[j]; }
        beta = beta_n; gv = g_n; vv = vv_n;
    }
}

// -------------- combine + gated RMSNorm + bf16 hi/lo (fused) ------------------
__global__ void combine_kernel(const float* __restrict__ norm_w) {
    int s = blockIdx.x, h = blockIdx.y, tid = threadIdx.x;
    int p0 = d_pos[2 * s], p1 = d_pos[2 * s + 1];
    float r0 = d_rw[2 * s], r1 = d_rw[2 * s + 1];
    float acc[2];
    float ss = 0.f;
#pragma unroll
    for (int i = 0; i < 2; i++) {
        int v = tid + i * 256;
        float a = 0.f;
        if (p0 >= 0) a += r0 * d_o[(size_t)p0 * VDIM + h * DVC + v];
        if (p1 >= 0) a += r1 * d_o[(size_t)p1 * VDIM + h * DVC + v];
        acc[i] = a;
        ss += a * a;
    }
    __shared__ float red[256];
    red[tid] = ss;
    __syncthreads();
    for (int st = 128; st > 0; st >>= 1) {
        if (tid < st) red[tid] += red[tid + st];
        __syncthreads();
    }
    float inv = rsqrtf(red[0] / (float)DVC + 1e-5f);
#pragma unroll
    for (int i = 0; i < 2; i++) {
        int v = tid + i * 256;
        float gg = d_gg[(size_t)s * VDIM + h * DVC + v];
        float sg = gg / (1.f + expf(-gg));
        float val = acc[i] * inv * norm_w[v] * sg;
        __nv_bfloat16 hb = __float2bfloat16(val);
        __nv_bfloat16 lb = __float2bfloat16(val - __bfloat162float(hb));
        size_t idx = (size_t)s * VDIM + h * DVC + v;
        d_pre_hi[idx] = hb;
        d_pre_lo[idx] = lb;
    }
}

// ----------------------------- launch -----------------------------------------
extern "C" void kernel_launch(void* const* d_in, const int* in_sizes, int n_in,
                              void* d_out, int out_size) {
    const float* hidden  = (const float*)d_in[0];
    const float* q_w     = (const float*)d_in[1];
    const float* gate_w  = (const float*)d_in[2];
    const float* k_w     = (const float*)d_in[3];
    const float* v_w     = (const float*)d_in[4];
    const float* b_w     = (const float*)d_in[5];
    const float* a_w     = (const float*)d_in[6];
    const float* A_log   = (const float*)d_in[7];
    const float* dt_bias = (const float*)d_in[8];
    const float* qcw     = (const float*)d_in[9];
    const float* kcw     = (const float*)d_in[10];
    const float* vcw     = (const float*)d_in[11];
    const float* g_w     = (const float*)d_in[12];
    const float* norm_w  = (const float*)d_in[13];
    const float* o_w     = (const float*)d_in[14];

    float* qkvpre = 0; float* gg = 0;
    cudaGetSymbolAddress((void**)&qkvpre, d_qkvpre);
    cudaGetSymbolAddress((void**)&gg, d_gg);

    __nv_bfloat16* xgh = 0; __nv_bfloat16* xgl = 0;
    __nv_bfloat16* qkvh = 0; __nv_bfloat16* qkvl = 0;
    __nv_bfloat16* gwh = 0; __nv_bfloat16* gwl = 0;
    __nv_bfloat16* owh = 0; __nv_bfloat16* owl = 0;
    __nv_bfloat16* hih = 0; __nv_bfloat16* hil = 0;
    __nv_bfloat16* prh = 0; __nv_bfloat16* prl = 0;
    cudaGetSymbolAddress((void**)&xgh, d_xg_hi);
    cudaGetSymbolAddress((void**)&xgl, d_xg_lo);
    cudaGetSymbolAddress((void**)&qkvh, d_qkvw_hi);
    cudaGetSymbolAddress((void**)&qkvl, d_qkvw_lo);
    cudaGetSymbolAddress((void**)&gwh, d_gw_hi);
    cudaGetSymbolAddress((void**)&gwl, d_gw_lo);
    cudaGetSymbolAddress((void**)&owh, d_ow_hi);
    cudaGetSymbolAddress((void**)&owl, d_ow_lo);
    cudaGetSymbolAddress((void**)&hih, d_hid_hi);
    cudaGetSymbolAddress((void**)&hil, d_hid_lo);
    cudaGetSymbolAddress((void**)&prh, d_pre_hi);
    cudaGetSymbolAddress((void**)&prl, d_pre_lo);

    cudaFuncSetAttribute(gemm_qkv_gate, cudaFuncAttributeMaxDynamicSharedMemorySize, GEMM_SMEM);
    cudaFuncSetAttribute(gemm_out_splitk, cudaFuncAttributeMaxDynamicSharedMemorySize, GEMM_SMEM);

    // 1: pack all weights
    pack_w_kernel<<<(int)((TOT_U + 255) / 256), 256>>>(q_w, k_w, v_w, b_w, a_w, g_w, o_w, hidden);
    // 2: zero output (early; independent)
    zero_out_kernel<<<(SLEN * DDIM / 4 + 255) / 256, 256>>>((float4*)d_out, SLEN * DDIM / 4);
    // 3-4: routing
    router_kernel<<<SLEN, 256>>>(hidden, gate_w);
    dispatch_kernel<<<1, 256>>>();
    // 5: gather + activation split
    gather_split_kernel<<<NROW, 256>>>(hidden);
    // 6: merged qkv (z<8) + gate (z=8) projections
    gemm_qkv_gate<<<dim3(QKVP / 128, CAP / 128, ENUM + 1), 256, GEMM_SMEM>>>(
        xgh, xgl, qkvh, qkvl, qkvpre, hih, hil, gwh, gwl, gg);

    bg_finish_kernel<<<(NROW * HNUM + 255) / 256, 256>>>(A_log, dt_bias);

    // 7: merged convs (q norm / k norm / v)
    conv_all_kernel<<<dim3(NROW, 24), 256>>>(qkvpre, qcw, kcw, vcw);

    recur_kernel<<<dim3(DVC / 32, HNUM, ENUM), 256>>>();

    combine_kernel<<<dim3(SLEN, HNUM), 256>>>(norm_w);
    // 8: split-K output GEMM (atomic accumulate into zeroed d_out)
    gemm_out_splitk<<<dim3(DDIM / 128, SLEN / 128, 2), 256, GEMM_SMEM>>>(
        prh, prl, owh, owl, (float*)d_out);
}

// round 15
// speedup vs baseline: 1.3341x; 1.0013x over previous
#include <cuda_runtime.h>
#include <cuda_bf16.h>
#include <stdint.h>
#include <math.h>

#define SLEN 1024
#define DDIM 2048
#define ENUM 8
#define HNUM 6
#define DKC  256
#define DVC  512
#define KDIM 1536   // HNUM*DKC
#define VDIM 3072   // HNUM*DVC
#define QKVO 6144   // q+k+v data cols
#define QKVP 6272   // padded: + 12 beta/g cols + zero pad (49*128)
#define CAP  1024
#define NROW (ENUM*CAP)

// ---------------- scratch (device globals; no allocation in kernel_launch) ----
__device__ int   d_sel[SLEN*2];
__device__ float d_rw [SLEN*2];
__device__ int   d_m  [ENUM];
__device__ int   d_tok[NROW];
__device__ int   d_pos[SLEN*2];
__device__ float d_qkvpre[(size_t)NROW*QKVP];
__device__ float d_qn  [NROW*KDIM];
__device__ float d_kn  [NROW*KDIM];
__device__ float d_vn  [NROW*VDIM];
__device__ float d_beta[NROW*HNUM];
__device__ float d_g   [NROW*HNUM];
__device__ float d_o   [NROW*VDIM];
__device__ float d_gg  [SLEN*VDIM];

// bf16 hi/lo split buffers
__device__ __align__(256) __nv_bfloat16 d_xg_hi[NROW*DDIM];
__device__ __align__(256) __nv_bfloat16 d_xg_lo[NROW*DDIM];
__device__ __align__(256) __nv_bfloat16 d_qkvw_hi[(size_t)ENUM*DDIM*QKVP];
__device__ __align__(256) __nv_bfloat16 d_qkvw_lo[(size_t)ENUM*DDIM*QKVP];
__device__ __align__(256) __nv_bfloat16 d_gw_hi[DDIM*VDIM];
__device__ __align__(256) __nv_bfloat16 d_gw_lo[DDIM*VDIM];
__device__ __align__(256) __nv_bfloat16 d_ow_hi[VDIM*DDIM];
__device__ __align__(256) __nv_bfloat16 d_ow_lo[VDIM*DDIM];
__device__ __align__(256) __nv_bfloat16 d_hid_hi[SLEN*DDIM];
__device__ __align__(256) __nv_bfloat16 d_hid_lo[SLEN*DDIM];
__device__ __align__(256) __nv_bfloat16 d_pre_hi[SLEN*VDIM];
__device__ __align__(256) __nv_bfloat16 d_pre_lo[SLEN*VDIM];

// ---------------- PTX helpers -------------------------------------------------
__device__ __forceinline__ void cpa16(uint32_t d, const void* s) {
    asm volatile("cp.async.cg.shared.global [%0], [%1], 16;" :: "r"(d), "l"(s));
}
__device__ __forceinline__ void ldm_x4(uint32_t* r, uint32_t a) {
    asm volatile("ldmatrix.sync.aligned.m8n8.x4.shared.b16 {%0,%1,%2,%3}, [%4];"
                 : "=r"(r[0]), "=r"(r[1]), "=r"(r[2]), "=r"(r[3]) : "r"(a));
}
__device__ __forceinline__ void ldm_x4t(uint32_t* r, uint32_t a) {
    asm volatile("ldmatrix.sync.aligned.m8n8.x4.trans.shared.b16 {%0,%1,%2,%3}, [%4];"
                 : "=r"(r[0]), "=r"(r[1]), "=r"(r[2]), "=r"(r[3]) : "r"(a));
}
__device__ __forceinline__ void mma_bf16(float* c, const uint32_t* a, const uint32_t* b) {
    asm volatile(
        "mma.sync.aligned.m16n8k16.row.col.f32.bf16.bf16.f32 "
        "{%0,%1,%2,%3},{%4,%5,%6,%7},{%8,%9},{%0,%1,%2,%3};"
        : "+f"(c[0]), "+f"(c[1]), "+f"(c[2]), "+f"(c[3])
        : "r"(a[0]), "r"(a[1]), "r"(a[2]), "r"(a[3]), "r"(b[0]), "r"(b[1]));
}

// ---------------- hi/lo split conversion --------------------------------------
__device__ __forceinline__ void split4(float4 v, __nv_bfloat162* hi, __nv_bfloat162* lo) {
    __nv_bfloat16 h0 = __float2bfloat16(v.x), h1 = __float2bfloat16(v.y);
    __nv_bfloat16 h2 = __float2bfloat16(v.z), h3 = __float2bfloat16(v.w);
    __nv_bfloat16 l0 = __float2bfloat16(v.x - __bfloat162float(h0));
    __nv_bfloat16 l1 = __float2bfloat16(v.y - __bfloat162float(h1));
    __nv_bfloat16 l2 = __float2bfloat16(v.z - __bfloat162float(h2));
    __nv_bfloat16 l3 = __float2bfloat16(v.w - __bfloat162float(h3));
    hi[0] = __halves2bfloat162(h0, h1);
    hi[1] = __halves2bfloat162(h2, h3);
    lo[0] = __halves2bfloat162(l0, l1);
    lo[1] = __halves2bfloat162(l2, l3);
}

// -------------- prep: pack weights + zero d_out + router, one launch ----------
#define QKV_U (ENUM*DDIM*(QKVP/4))
#define GW_U  (DDIM*VDIM/4)
#define OW_U  (VDIM*DDIM/4)
#define HID_U (SLEN*DDIM/4)
#define TOT_U (QKV_U + GW_U + OW_U + HID_U)
#define PACK_B (TOT_U/256)
#define ZERO_B ((SLEN*DDIM/4)/256)
#define PREP_B (PACK_B + ZERO_B + SLEN)

__global__ void prep_kernel(const float* __restrict__ q_w, const float* __restrict__ k_w,
                            const float* __restrict__ v_w, const float* __restrict__ b_w,
                            const float* __restrict__ a_w, const float* __restrict__ g_w,
                            const float* __restrict__ o_w, const float* __restrict__ hidden,
                            const float* __restrict__ gate_w, float4* __restrict__ outz) {
    int blk = blockIdx.x;
    int tid = threadIdx.x;
    if (blk < PACK_B) {
        long long u = (long long)blk * 256 + tid;
        if (u < QKV_U) {
            long long per_e = (long long)DDIM * (QKVP / 4);
            int e = (int)(u / per_e);
            long long r = u - (long long)e * per_e;
            int d = (int)(r / (QKVP / 4));
            int c4 = (int)(r - (long long)d * (QKVP / 4));
            int n = c4 * 4;
            float4 src;
            if (n < KDIM) {
                src = *(const float4*)(q_w + (size_t)d * KDIM + n);
            } else if (n < 2 * KDIM) {
                src = *(const float4*)(k_w + ((size_t)e * DDIM + d) * KDIM + (n - KDIM));
            } else if (n < QKVO) {
                src = *(const float4*)(v_w + ((size_t)e * DDIM + d) * VDIM + (n - 2 * KDIM));
            } else {
                float vals[4];
#pragma unroll
                for (int j = 0; j < 4; j++) {
                    int c = n + j;
                    if (c < QKVO + HNUM)
                        vals[j] = b_w[((size_t)e * DDIM + d) * HNUM + (c - QKVO)];
                    else if (c < QKVO + 2 * HNUM)
                        vals[j] = a_w[((size_t)e * DDIM + d) * HNUM + (c - QKVO - HNUM)];
                    else
                        vals[j] = 0.f;
                }
                src = make_float4(vals[0], vals[1], vals[2], vals[3]);
            }
            size_t dst = ((size_t)e * DDIM + d) * QKVP + n;
            __nv_bfloat162 h[2], l[2];
            split4(src, h, l);
            __nv_bfloat162* hp = (__nv_bfloat162*)(d_qkvw_hi + dst);
            __nv_bfloat162* lp = (__nv_bfloat162*)(d_qkvw_lo + dst);
            hp[0] = h[0]; hp[1] = h[1]; lp[0] = l[0]; lp[1] = l[1];
            return;
        }
        u -= QKV_U;
        if (u < GW_U) {
            float4 src = ((const float4*)g_w)[u];
            __nv_bfloat162 h[2], l[2]; split4(src, h, l);
            ((__nv_bfloat162*)d_gw_hi)[2 * u] = h[0]; ((__nv_bfloat162*)d_gw_hi)[2 * u + 1] = h[1];
            ((__nv_bfloat162*)d_gw_lo)[2 * u] = l[0]; ((__nv_bfloat162*)d_gw_lo)[2 * u + 1] = l[1];
            return;
        }
        u -= GW_U;
        if (u < OW_U) {
            float4 src = ((const float4*)o_w)[u];
            __nv_bfloat162 h[2], l[2]; split4(src, h, l);
            ((__nv_bfloat162*)d_ow_hi)[2 * u] = h[0]; ((__nv_bfloat162*)d_ow_hi)[2 * u + 1] = h[1];
            ((__nv_bfloat162*)d_ow_lo)[2 * u] = l[0]; ((__nv_bfloat162*)d_ow_lo)[2 * u + 1] = l[1];
            return;
        }
        u -= OW_U;
        {
            float4 src = ((const float4*)hidden)[u];
            __nv_bfloat162 h[2], l[2]; split4(src, h, l);
            ((__nv_bfloat162*)d_hid_hi)[2 * u] = h[0]; ((__nv_bfloat162*)d_hid_hi)[2 * u + 1] = h[1];
            ((__nv_bfloat162*)d_hid_lo)[2 * u] = l[0]; ((__nv_bfloat162*)d_hid_lo)[2 * u + 1] = l[1];
        }
        return;
    }
    blk -= PACK_B;
    if (blk < ZERO_B) {
        outz[blk * 256 + tid] = make_float4(0.f, 0.f, 0.f, 0.f);
        return;
    }
    // router: one block per token
    int s = blk - ZERO_B;
    float acc[ENUM];
#pragma unroll
    for (int e = 0; e < ENUM; e++) acc[e] = 0.f;
    const float* xr = hidden + (size_t)s * DDIM;
    for (int d = tid; d < DDIM; d += 256) {
        float x = xr[d];
        const float* w = gate_w + (size_t)d * ENUM;
#pragma unroll
        for (int e = 0; e < ENUM; e++) acc[e] += x * w[e];
    }
    __shared__ float red[ENUM][256];
#pragma unroll
    for (int e = 0; e < ENUM; e++) red[e][tid] = acc[e];
    __syncthreads();
    for (int st = 128; st > 0; st >>= 1) {
        if (tid < st) {
#pragma unroll
            for (int e = 0; e < ENUM; e++) red[e][tid] += red[e][tid + st];
        }
        __syncthreads();
    }
    if (tid == 0) {
        float l[ENUM], mx = -1e30f;
#pragma unroll
        for (int e = 0; e < ENUM; e++) { l[e] = red[e][0]; mx = fmaxf(mx, l[e]); }
        float p[ENUM], sum = 0.f;
#pragma unroll
        for (int e = 0; e < ENUM; e++) { p[e] = expf(l[e] - mx); sum += p[e]; }
#pragma unroll
        for (int e = 0; e < ENUM; e++) p[e] /= sum;
        int i0 = 0;
#pragma unroll
        for (int e = 1; e < ENUM; e++) if (p[e] > p[i0]) i0 = e;
        int i1 = -1;
#pragma unroll
        for (int e = 0; e < ENUM; e++)
            if (e != i0 && (i1 < 0 || p[e] > p[i1])) i1 = e;
        float r0 = p[i0], r1 = p[i1], rs = r0 + r1;
        d_sel[2 * s] = i0;  d_sel[2 * s + 1] = i1;
        d_rw[2 * s] = r0 / rs;  d_rw[2 * s + 1] = r1 / rs;
    }
}

// ---------------- tensor-core split-bf16 GEMM core ----------------------------
// Swizzled smem: stage = 32KB -> 3 stages = 96KB -> 2 CTAs/SM.
// Pipeline order (R13-proven): wait_group -> __syncthreads -> load(kt+2)
#define A_BYTES 8192
#define B_BYTES 8192
#define STAGE_BYTES 32768
#define NSTAGE 3
#define GEMM_SMEM (NSTAGE*STAGE_BYTES)

template<bool ATOMIC>
__device__ __forceinline__ void gemm_core(
    const __nv_bfloat16* __restrict__ Ahi, const __nv_bfloat16* __restrict__ Alo,
    const __nv_bfloat16* __restrict__ Bhi, const __nv_bfloat16* __restrict__ Blo,
    float* __restrict__ C, int mlim, int N, int K, int lda, int row0, int col0,
    __nv_bfloat16* smbuf) {
    uint32_t sbase = (uint32_t)__cvta_generic_to_shared(smbuf);
    int t = threadIdx.x;

    int arow = t >> 1, ac0 = (t & 1) * 2;
    int brow = t >> 3, bc0 = (t & 7) * 2;
    uint32_t aswr = ((uint32_t)(arow >> 1)) & 3u;
    uint32_t bswr = (uint32_t)(brow & 7);
    const __nv_bfloat16* gAh = Ahi + (size_t)(row0 + arow) * lda;
    const __nv_bfloat16* gAl = Alo + (size_t)(row0 + arow) * lda;
    const __nv_bfloat16* gBh = Bhi + (size_t)brow * N + col0;
    const __nv_bfloat16* gBl = Blo + (size_t)brow * N + col0;
    uint32_t aoff0 = (uint32_t)(arow * 64) + (((uint32_t)ac0 ^ aswr) * 16);
    uint32_t aoff1 = (uint32_t)(arow * 64) + ((((uint32_t)ac0 + 1u) ^ aswr) * 16);
    uint32_t boff0 = (uint32_t)(brow * 256) + (((uint32_t)bc0 ^ bswr) * 16);
    uint32_t boff1 = (uint32_t)(brow * 256) + ((((uint32_t)bc0 + 1u) ^ bswr) * 16);

    int lane = t & 31, wid = t >> 5;
    int wm = (wid >> 2) * 64, wn = (wid & 3) * 32;
    int lr = lane & 15;
    uint32_t swA = ((uint32_t)(lr >> 1)) & 3u;
    uint32_t achb = (uint32_t)(lane >> 4);
    uint32_t arowb = (uint32_t)((wm + lr) * 64);
    int blr = lane & 7, bgp = lane >> 3;
    uint32_t cbB = (uint32_t)((wid & 3) * 4 + (bgp >> 1));
    uint32_t brb = (uint32_t)(blr + (bgp & 1) * 8);

    float acc[4][4][4];
#pragma unroll
    for (int mi = 0; mi < 4; mi++)
#pragma unroll
        for (int ni = 0; ni < 4; ni++)
#pragma unroll
            for (int j = 0; j < 4; j++) acc[mi][ni][j] = 0.f;

    int KT = K / 32;

    auto load_stage = [&](int ktl) {
        int k0 = ktl * 32;
        uint32_t so = sbase + (uint32_t)((ktl % NSTAGE) * STAGE_BYTES);
        cpa16(so + aoff0, gAh + k0 + ac0 * 8);
        cpa16(so + aoff1, gAh + k0 + ac0 * 8 + 8);
        cpa16(so + A_BYTES + aoff0, gAl + k0 + ac0 * 8);
        cpa16(so + A_BYTES + aoff1, gAl + k0 + ac0 * 8 + 8);
        cpa16(so + 2 * A_BYTES + boff0, gBh + (size_t)k0 * N + bc0 * 8);
        cpa16(so + 2 * A_BYTES + boff1, gBh + (size_t)k0 * N + bc0 * 8 + 8);
        cpa16(so + 2 * A_BYTES + B_BYTES + boff0, gBl + (size_t)k0 * N + bc0 * 8);
        cpa16(so + 2 * A_BYTES + B_BYTES + boff1, gBl + (size_t)k0 * N + bc0 * 8 + 8);
        asm volatile("cp.async.commit_group;");
    };

    load_stage(0);
    if (KT > 1) load_stage(1);

    for (int kt = 0; kt < KT; kt++) {
        if (kt + 1 < KT) {
            asm volatile("cp.async.wait_group 1;");
        } else {
            asm volatile("cp.async.wait_group 0;");
        }
        __syncthreads();
        if (kt + 2 < KT) load_stage(kt + 2);

        uint32_t s0 = sbase + (uint32_t)((kt % NSTAGE) * STAGE_BYTES);
        uint32_t sAh = s0;
        uint32_t sAl = s0 + A_BYTES;
        uint32_t sBh = s0 + 2 * A_BYTES;
        uint32_t sBl = s0 + 2 * A_BYTES + B_BYTES;

#pragma unroll
        for (int ks = 0; ks < 2; ks++) {
            uint32_t rB = brb + (uint32_t)(ks * 16);
            uint32_t bo0 = rB * 256 + ((cbB ^ (uint32_t)blr) * 16);
            uint32_t bo1 = rB * 256 + (((cbB + 2u) ^ (uint32_t)blr) * 16);
            uint32_t ach = achb + (uint32_t)(ks * 2);
            uint32_t ao = arowb + ((ach ^ swA) * 16);

            uint32_t bh[8], bl2[8], af[16];
            ldm_x4t(bh + 0, sBh + bo0);
            ldm_x4t(bh + 4, sBh + bo1);
            ldm_x4t(bl2 + 0, sBl + bo0);
            ldm_x4t(bl2 + 4, sBl + bo1);
#pragma unroll
            for (int mi = 0; mi < 4; mi++)
                ldm_x4(af + mi * 4, sAh + ao + (uint32_t)(mi * 1024));
#pragma unroll
            for (int mi = 0; mi < 4; mi++)
#pragma unroll
                for (int ni = 0; ni < 4; ni++)
                    mma_bf16(acc[mi][ni], af + mi * 4, bh + (ni >> 1) * 4 + (ni & 1) * 2);
#pragma unroll
            for (int mi = 0; mi < 4; mi++)
#pragma unroll
                for (int ni = 0; ni < 4; ni++)
                    mma_bf16(acc[mi][ni], af + mi * 4, bl2 + (ni >> 1) * 4 + (ni & 1) * 2);
#pragma unroll
            for (int mi = 0; mi < 4; mi++)
                ldm_x4(af + mi * 4, sAl + ao + (uint32_t)(mi * 1024));
#pragma unroll
            for (int mi = 0; mi < 4; mi++)
#pragma unroll
                for (int ni = 0; ni < 4; ni++)
                    mma_bf16(acc[mi][ni], af + mi * 4, bh + (ni >> 1) * 4 + (ni & 1) * 2);
        }
    }

    int gr = lane >> 2, gc = (lane & 3) * 2;
#pragma unroll
    for (int mi = 0; mi < 4; mi++) {
        int r = row0 + wm + mi * 16 + gr;
#pragma unroll
        for (int ni = 0; ni < 4; ni++) {
            float* Cp = C + (size_t)r * N + col0 + wn + ni * 8 + gc;
            if (r < mlim) {
                if (ATOMIC) { atomicAdd(Cp, acc[mi][ni][0]); atomicAdd(Cp + 1, acc[mi][ni][1]); }
                else { Cp[0] = acc[mi][ni][0]; Cp[1] = acc[mi][ni][1]; }
            }
            if (r + 8 < mlim) {
                float* Cq = Cp + (size_t)8 * N;
                if (ATOMIC) { atomicAdd(Cq, acc[mi][ni][2]); atomicAdd(Cq + 1, acc[mi][ni][3]); }
                else { Cq[0] = acc[mi][ni][2]; Cq[1] = acc[mi][ni][3]; }
            }
        }
    }
}

// merged qkv (z=0..7) + gate (z=8) GEMM launch
__global__ __launch_bounds__(256, 2)
void gemm_qkv_gate(const __nv_bfloat16* __restrict__ xgh, const __nv_bfloat16* __restrict__ xgl,
                   const __nv_bfloat16* __restrict__ qkvh, const __nv_bfloat16* __restrict__ qkvl,
                   float* __restrict__ qkvpre,
                   const __nv_bfloat16* __restrict__ hih, const __nv_bfloat16* __restrict__ hil,
                   const __nv_bfloat16* __restrict__ gwh, const __nv_bfloat16* __restrict__ gwl,
                   float* __restrict__ gg) {
    extern __shared__ __nv_bfloat16 smbuf[];
    int z = blockIdx.z;
    int row0 = blockIdx.y * 128;
    int col0 = blockIdx.x * 128;
    if (z < ENUM) {
        int mlim = d_m[z];
        if (row0 >= mlim) return;
        gemm_core<false>(xgh + (size_t)z * CAP * DDIM, xgl + (size_t)z * CAP * DDIM,
                         qkvh + (size_t)z * DDIM * QKVP, qkvl + (size_t)z * DDIM * QKVP,
                         qkvpre + (size_t)z * CAP * QKVP, mlim, QKVP, DDIM, DDIM,
                         row0, col0, smbuf);
    } else {
        if (col0 >= VDIM) return;
        gemm_core<false>(hih, hil, gwh, gwl, gg, SLEN, VDIM, DDIM, DDIM, row0, col0, smbuf);
    }
}

// split-K output GEMM: z selects K-half, accumulates via atomics.
__global__ __launch_bounds__(256, 2)
void gemm_out_splitk(const __nv_bfloat16* __restrict__ Ahi, const __nv_bfloat16* __restrict__ Alo,
                     const __nv_bfloat16* __restrict__ Bhi, const __nv_bfloat16* __restrict__ Blo,
                     float* __restrict__ C) {
    extern __shared__ __nv_bfloat16 smbuf[];
    int z = blockIdx.z;
    int row0 = blockIdx.y * 128;
    int col0 = blockIdx.x * 128;
    int kHalf = VDIM / 2;
    gemm_core<true>(Ahi + (size_t)z * kHalf, Alo + (size_t)z * kHalf,
                    Bhi + (size_t)z * kHalf * DDIM, Blo + (size_t)z * kHalf * DDIM,
                    C, SLEN, DDIM, kHalf, VDIM, row0, col0, smbuf);
}

// -------------- dispatch: parallel warp-per-expert ballot scan ----------------
__global__ void dispatch_kernel() {
    int e = threadIdx.x >> 5;
    int lane = threadIdx.x & 31;
    int cnt = 0;
    for (int i = lane; i < SLEN * 2; i += 32) cnt += (d_sel[i] == e);
#pragma unroll
    for (int o = 16; o; o >>= 1) cnt += __shfl_xor_sync(0xffffffffu, cnt, o);
    int drop = cnt > CAP ? cnt - CAP : 0;
    if (lane == 0) d_m[e] = cnt - drop;
    int base = 0;
    for (int i0 = 0; i0 < SLEN * 2; i0 += 32) {
        int i = i0 + lane;
        bool hit = (d_sel[i] == e);
        unsigned mask = __ballot_sync(0xffffffffu, hit);
        if (hit) {
            int r = base + __popc(mask & ((1u << lane) - 1u));
            if (r >= drop) {
                int j = r - drop;
                d_tok[e * CAP + j] = i >> 1;
                d_pos[i] = e * CAP + j;
            } else {
                d_pos[i] = -1;
            }
        }
        base += __popc(mask);
    }
}

// -------------- gather + hi/lo split of activations --------------------------
__global__ void gather_split_kernel(const float* __restrict__ hidden) {
    int row = blockIdx.x;
    int e = row >> 10, t = row & 1023;
    if (t >= d_m[e]) return;
    const float4* src = (const float4*)(hidden + (size_t)d_tok[row] * DDIM);
    __nv_bfloat162* hi = (__nv_bfloat162*)(d_xg_hi + (size_t)row * DDIM);
    __nv_bfloat162* lo = (__nv_bfloat162*)(d_xg_lo + (size_t)row * DDIM);
    for (int i = threadIdx.x; i < DDIM / 4; i += 256) {
        float4 v = src[i];
        __nv_bfloat162 h[2], l[2];
        split4(v, h, l);
        hi[2 * i] = h[0]; hi[2 * i + 1] = h[1];
        lo[2 * i] = l[0]; lo[2 * i + 1] = l[1];
    }
}

// -------------- merged conv + bg launch ----------------------------------------
__global__ void conv_all_kernel(const float* __restrict__ pre,
                                const float* __restrict__ qcw,
                                const float* __restrict__ kcw,
                                const float* __restrict__ vcw,
                                const float* __restrict__ A_log,
                                const float* __restrict__ dt_bias) {
    int row = blockIdx.x;
    int y = blockIdx.y;
    int e = row >> 10, t = row & 1023;
    if (t >= d_m[e]) return;
    int tid = threadIdx.x;

    if (y < 12) {
        int h = (y < 6) ? y : (y - 6);
        int preOff = (y < 6) ? 0 : KDIM;
        float scale = (y < 6) ? 0.0625f : 1.0f;
        const float* cw = (y < 6) ? qcw : kcw;
        float* out = (y < 6) ? d_qn : d_kn;
        int ch = h * DKC + tid;
        float yv = 0.f;
#pragma unroll
        for (int j = 0; j < 4; j++) {
            int tt = t - 3 + j;
            if (tt >= 0) yv += cw[ch * 4 + j] * pre[(size_t)(row - 3 + j) * QKVP + preOff + ch];
        }
        yv = yv / (1.f + expf(-yv));
        __shared__ float red[256];
        red[tid] = yv * yv;
        __syncthreads();
        for (int st = 128; st > 0; st >>= 1) {
            if (tid < st) red[tid] += red[tid + st];
            __syncthreads();
        }
        float inv = rsqrtf(red[0] + 1e-6f) * scale;
        out[(size_t)row * KDIM + ch] = yv * inv;
    } else if (y < 24) {
        int ch = (y - 12) * 256 + tid;
        float yv = 0.f;
#pragma unroll
        for (int j = 0; j < 4; j++) {
            int tt = t - 3 + j;
            if (tt >= 0) yv += vcw[ch * 4 + j] * pre[(size_t)(row - 3 + j) * QKVP + 2 * KDIM + ch];
        }
        d_vn[(size_t)row * VDIM + ch] = yv / (1.f + expf(-yv));
    } else {
        if (tid < HNUM) {
            float bl = pre[(size_t)row * QKVP + QKVO + tid];
            float al = pre[(size_t)row * QKVP + QKVO + HNUM + tid];
            d_beta[row * HNUM + tid] = 1.f / (1.f + expf(-bl));
            float xx = al + dt_bias[tid];
            float sp = xx > 20.f ? xx : log1pf(expf(xx));
            d_g[row * HNUM + tid] = -expf(A_log[tid]) * sp;
        }
    }
}

// -------------- gated delta-rule recurrence (conflict-free strided) -----------
__global__ void recur_kernel() {
    int vc = blockIdx.x;
    int h = blockIdx.y;
    int e = blockIdx.z;
    int m = d_m[e];
    __shared__ float S[32 * 256];
    __shared__ float su[32], sw[32], sd[32];
    int tid = threadIdx.x, warp = tid >> 5, lane = tid & 31;
    int v0 = warp * 4;
    for (int i = lane; i < 4 * 256; i += 32) S[v0 * 256 + i] = 0.f;
    if (lane < 4) { su[v0 + lane] = 0.f; sw[v0 + lane] = 0.f; }
    __syncwarp();
    if (m == 0) return;

    const float* kb = d_kn + (size_t)(e * CAP) * KDIM + h * DKC;
    const float* qb = d_qn + (size_t)(e * CAP) * KDIM + h * DKC;
    const float* vb = d_vn + (size_t)(e * CAP) * VDIM + h * DVC + vc * 32;
    const float* bb = d_beta + (size_t)(e * CAP) * HNUM + h;
    const float* gb = d_g + (size_t)(e * CAP) * HNUM + h;
    float* ob = d_o + (size_t)(e * CAP) * VDIM + h * DVC + vc * 32;

    float kc[8], qc[8];
#pragma unroll
    for (int j = 0; j < 8; j++) { kc[j] = kb[lane + 32 * j]; qc[j] = qb[lane + 32 * j]; }
    float beta = bb[0];
    float gv = gb[0];
    float vv = (lane < 4) ? vb[v0 + lane] : 0.f;

    for (int t = 0; t < m; t++) {
        float eg = expf(gv);
        float qk = 0.f;
#pragma unroll
        for (int j = 0; j < 8; j++) qk += kc[j] * qc[j];
#pragma unroll
        for (int o = 16; o; o >>= 1) qk += __shfl_xor_sync(0xffffffffu, qk, o);

        if (lane < 4) {
            int v = v0 + lane;
            float dd = beta * (vv - eg * su[v]);
            ob[(size_t)t * VDIM + v] = eg * sw[v] + qk * dd;
            sd[v] = dd;
        }
        __syncwarp();

        float kn2[8], qn2[8];
        float beta_n = 0.f, g_n = 0.f, vv_n = 0.f;
        if (t + 1 < m) {
            const float* kr = kb + (size_t)(t + 1) * KDIM;
            const float* qr = qb + (size_t)(t + 1) * KDIM;
#pragma unroll
            for (int j = 0; j < 8; j++) { kn2[j] = kr[lane + 32 * j]; qn2[j] = qr[lane + 32 * j]; }
            beta_n = bb[(size_t)(t + 1) * HNUM];
            g_n = gb[(size_t)(t + 1) * HNUM];
            if (lane < 4) vv_n = vb[(size_t)(t + 1) * VDIM + v0 + lane];
        } else {
#pragma unroll
            for (int j = 0; j < 8; j++) { kn2[j] = 0.f; qn2[j] = 0.f; }
        }

#pragma unroll
        for (int vi = 0; vi < 4; vi++) {
            int v = v0 + vi;
            float dd = sd[v];
            float un = 0.f, wn = 0.f;
            float* Sr = &S[v * 256];
#pragma unroll
            for (int j = 0; j < 8; j++) {
                float s2 = Sr[lane + 32 * j];
                s2 = eg * s2 + kc[j] * dd;
                Sr[lane + 32 * j] = s2;
                un += kn2[j] * s2;
                wn += qn2[j] * s2;
            }
#pragma unroll
            for (int o = 16; o; o >>= 1) {
                un += __shfl_xor_sync(0xffffffffu, un, o);
                wn += __shfl_xor_sync(0xffffffffu, wn, o);
            }
            if (lane == 0) { su[v] = un; sw[v] = wn; }
        }
        __syncwarp();
#pragma unroll
        for (int j = 0; j < 8; j++) { kc[j] = kn2[j]; qc[j] = qn2[j]; }
        beta = beta_n; gv = g_n; vv = vv_n;
    }
}

// -------------- combine + gated RMSNorm + bf16 hi/lo (fused) ------------------
__global__ void combine_kernel(const float* __restrict__ norm_w) {
    int s = blockIdx.x, h = blockIdx.y, tid = threadIdx.x;
    int p0 = d_pos[2 * s], p1 = d_pos[2 * s + 1];
    float r0 = d_rw[2 * s], r1 = d_rw[2 * s + 1];
    float acc[2];
    float ss = 0.f;
#pragma unroll
    for (int i = 0; i < 2; i++) {
        int v = tid + i * 256;
        float a = 0.f;
        if (p0 >= 0) a += r0 * d_o[(size_t)p0 * VDIM + h * DVC + v];
        if (p1 >= 0) a += r1 * d_o[(size_t)p1 * VDIM + h * DVC + v];
        acc[i] = a;
        ss += a * a;
    }
    __shared__ float red[256];
    red[tid] = ss;
    __syncthreads();
    for (int st = 128; st > 0; st >>= 1) {
        if (tid < st) red[tid] += red[tid + st];
        __syncthreads();
    }
    float inv = rsqrtf(red[0] / (float)DVC + 1e-5f);
#pragma unroll
    for (int i = 0; i < 2; i++) {
        int v = tid + i * 256;
        float gg = d_gg[(size_t)s * VDIM + h * DVC + v];
        float sg = gg / (1.f + expf(-gg));
        float val = acc[i] * inv * norm_w[v] * sg;
        __nv_bfloat16 hb = __float2bfloat16(val);
        __nv_bfloat16 lb = __float2bfloat16(val - __bfloat162float(hb));
        size_t idx = (size_t)s * VDIM + h * DVC + v;
        d_pre_hi[idx] = hb;
        d_pre_lo[idx] = lb;
    }
}

// ----------------------------- launch -----------------------------------------
extern "C" void kernel_launch(void* const* d_in, const int* in_sizes, int n_in,
                              void* d_out, int out_size) {
    const float* hidden  = (const float*)d_in[0];
    const float* q_w     = (const float*)d_in[1];
    const float* gate_w  = (const float*)d_in[2];
    const float* k_w     = (const float*)d_in[3];
    const float* v_w     = (const float*)d_in[4];
    const float* b_w     = (const float*)d_in[5];
    const float* a_w     = (const float*)d_in[6];
    const float* A_log   = (const float*)d_in[7];
    const float* dt_bias = (const float*)d_in[8];
    const float* qcw     = (const float*)d_in[9];
    const float* kcw     = (const float*)d_in[10];
    const float* vcw     = (const float*)d_in[11];
    const float* g_w     = (const float*)d_in[12];
    const float* norm_w  = (const float*)d_in[13];
    const float* o_w     = (const float*)d_in[14];

    float* qkvpre = 0; float* gg = 0;
    cudaGetSymbolAddress((void**)&qkvpre, d_qkvpre);
    cudaGetSymbolAddress((void**)&gg, d_gg);

    __nv_bfloat16* xgh = 0; __nv_bfloat16* xgl = 0;
    __nv_bfloat16* qkvh = 0; __nv_bfloat16* qkvl = 0;
    __nv_bfloat16* gwh = 0; __nv_bfloat16* gwl = 0;
    __nv_bfloat16* owh = 0; __nv_bfloat16* owl = 0;
    __nv_bfloat16* hih = 0; __nv_bfloat16* hil = 0;
    __nv_bfloat16* prh = 0; __nv_bfloat16* prl = 0;
    cudaGetSymbolAddress((void**)&xgh, d_xg_hi);
    cudaGetSymbolAddress((void**)&xgl, d_xg_lo);
    cudaGetSymbolAddress((void**)&qkvh, d_qkvw_hi);
    cudaGetSymbolAddress((void**)&qkvl, d_qkvw_lo);
    cudaGetSymbolAddress((void**)&gwh, d_gw_hi);
    cudaGetSymbolAddress((void**)&gwl, d_gw_lo);
    cudaGetSymbolAddress((void**)&owh, d_ow_hi);
    cudaGetSymbolAddress((void**)&owl, d_ow_lo);
    cudaGetSymbolAddress((void**)&hih, d_hid_hi);
    cudaGetSymbolAddress((void**)&hil, d_hid_lo);
    cudaGetSymbolAddress((void**)&prh, d_pre_hi);
    cudaGetSymbolAddress((void**)&prl, d_pre_lo);

    cudaFuncSetAttribute(gemm_qkv_gate, cudaFuncAttributeMaxDynamicSharedMemorySize, GEMM_SMEM);
    cudaFuncSetAttribute(gemm_out_splitk, cudaFuncAttributeMaxDynamicSharedMemorySize, GEMM_SMEM);

    // 1: prep = pack weights + zero d_out + router
    prep_kernel<<<PREP_B, 256>>>(q_w, k_w, v_w, b_w, a_w, g_w, o_w, hidden, gate_w,
                                 (float4*)d_out);
    // 2: dispatch
    dispatch_kernel<<<1, 256>>>();
    // 3: gather + activation split
    gather_split_kernel<<<NROW, 256>>>(hidden);
    // 4: merged qkv (z<8) + gate (z=8) projections  [profiled slot]
    gemm_qkv_gate<<<dim3(QKVP / 128, CAP / 128, ENUM + 1), 256, GEMM_SMEM>>>(
        xgh, xgl, qkvh, qkvl, qkvpre, hih, hil, gwh, gwl, gg);
    // 5: merged convs + bg epilogue
    conv_all_kernel<<<dim3(NROW, 25), 256>>>(qkvpre, qcw, kcw, vcw, A_log, dt_bias);
    // 6: recurrence
    recur_kernel<<<dim3(DVC / 32, HNUM, ENUM), 256>>>();
    // 7: combine + RMSNorm + split
    combine_kernel<<<dim3(SLEN, HNUM), 256>>>(norm_w);
    // 8: split-K output GEMM (atomic accumulate into zeroed d_out)
    gemm_out_splitk<<<dim3(DDIM / 128, SLEN / 128, 2), 256, GEMM_SMEM>>>(
        prh, prl, owh, owl, (float*)d_out);
}

// round 16
// speedup vs baseline: 1.4604x; 1.0947x over previous
#include <cuda_runtime.h>
#include <cuda_bf16.h>
#include <cuda_fp16.h>
#include <stdint.h>
#include <math.h>

#define SLEN 1024
#define DDIM 2048
#define ENUM 8
#define HNUM 6
#define DKC  256
#define DVC  512
#define KDIM 1536   // HNUM*DKC
#define VDIM 3072   // HNUM*DVC
#define QKVO 6144   // q+k+v data cols
#define QKVP 6272   // padded: + 12 beta/g cols + zero pad (49*128)
#define CAP  1024
#define NROW (ENUM*CAP)

// ---------------- scratch (device globals; no allocation in kernel_launch) ----
__device__ int   d_sel[SLEN*2];
__device__ float d_rw [SLEN*2];
__device__ int   d_m  [ENUM];
__device__ int   d_tok[NROW];
__device__ int   d_pos[SLEN*2];
__device__ float d_qkvpre[(size_t)NROW*QKVP];
__device__ float d_qn  [NROW*KDIM];
__device__ float d_kn  [NROW*KDIM];
__device__ float d_vn  [NROW*VDIM];
__device__ float d_beta[NROW*HNUM];
__device__ float d_g   [NROW*HNUM];
__device__ float d_o   [NROW*VDIM];
__device__ float d_gg  [SLEN*VDIM];

// fp16 buffers (qkv+gate GEMM path: A 2-term, B 1-term)
__device__ __align__(256) __half d_xg_hi[NROW*DDIM];
__device__ __align__(256) __half d_xg_lo[NROW*DDIM];
__device__ __align__(256) __half d_qkvw[(size_t)ENUM*DDIM*QKVP];
__device__ __align__(256) __half d_gw[DDIM*VDIM];
__device__ __align__(256) __half d_hid_hi[SLEN*DDIM];
__device__ __align__(256) __half d_hid_lo[SLEN*DDIM];
// bf16 buffers (output GEMM path: 3-term, full accuracy)
__device__ __align__(256) __nv_bfloat16 d_ow_hi[VDIM*DDIM];
__device__ __align__(256) __nv_bfloat16 d_ow_lo[VDIM*DDIM];
__device__ __align__(256) __nv_bfloat16 d_pre_hi[SLEN*VDIM];
__device__ __align__(256) __nv_bfloat16 d_pre_lo[SLEN*VDIM];

// ---------------- PTX helpers -------------------------------------------------
__device__ __forceinline__ void cpa16(uint32_t d, const void* s) {
    asm volatile("cp.async.cg.shared.global [%0], [%1], 16;" :: "r"(d), "l"(s));
}
__device__ __forceinline__ void cpa8(uint32_t d, const void* s) {
    asm volatile("cp.async.ca.shared.global [%0], [%1], 8;" :: "r"(d), "l"(s));
}
__device__ __forceinline__ void ldm_x4(uint32_t* r, uint32_t a) {
    asm volatile("ldmatrix.sync.aligned.m8n8.x4.shared.b16 {%0,%1,%2,%3}, [%4];"
                 : "=r"(r[0]), "=r"(r[1]), "=r"(r[2]), "=r"(r[3]) : "r"(a));
}
__device__ __forceinline__ void ldm_x4t(uint32_t* r, uint32_t a) {
    asm volatile("ldmatrix.sync.aligned.m8n8.x4.trans.shared.b16 {%0,%1,%2,%3}, [%4];"
                 : "=r"(r[0]), "=r"(r[1]), "=r"(r[2]), "=r"(r[3]) : "r"(a));
}
__device__ __forceinline__ void mma_bf16(float* c, const uint32_t* a, const uint32_t* b) {
    asm volatile(
        "mma.sync.aligned.m16n8k16.row.col.f32.bf16.bf16.f32 "
        "{%0,%1,%2,%3},{%4,%5,%6,%7},{%8,%9},{%0,%1,%2,%3};"
        : "+f"(c[0]), "+f"(c[1]), "+f"(c[2]), "+f"(c[3])
        : "r"(a[0]), "r"(a[1]), "r"(a[2]), "r"(a[3]), "r"(b[0]), "r"(b[1]));
}
__device__ __forceinline__ void mma_f16(float* c, const uint32_t* a, const uint32_t* b) {
    asm volatile(
        "mma.sync.aligned.m16n8k16.row.col.f32.f16.f16.f32 "
        "{%0,%1,%2,%3},{%4,%5,%6,%7},{%8,%9},{%0,%1,%2,%3};"
        : "+f"(c[0]), "+f"(c[1]), "+f"(c[2]), "+f"(c[3])
        : "r"(a[0]), "r"(a[1]), "r"(a[2]), "r"(a[3]), "r"(b[0]), "r"(b[1]));
}

// ---------------- split conversions --------------------------------------------
__device__ __forceinline__ void split4b(float4 v, __nv_bfloat162* hi, __nv_bfloat162* lo) {
    __nv_bfloat16 h0 = __float2bfloat16(v.x), h1 = __float2bfloat16(v.y);
    __nv_bfloat16 h2 = __float2bfloat16(v.z), h3 = __float2bfloat16(v.w);
    __nv_bfloat16 l0 = __float2bfloat16(v.x - __bfloat162float(h0));
    __nv_bfloat16 l1 = __float2bfloat16(v.y - __bfloat162float(h1));
    __nv_bfloat16 l2 = __float2bfloat16(v.z - __bfloat162float(h2));
    __nv_bfloat16 l3 = __float2bfloat16(v.w - __bfloat162float(h3));
    hi[0] = __halves2bfloat162(h0, h1);
    hi[1] = __halves2bfloat162(h2, h3);
    lo[0] = __halves2bfloat162(l0, l1);
    lo[1] = __halves2bfloat162(l2, l3);
}
__device__ __forceinline__ void split4h(float4 v, __half2* hi, __half2* lo) {
    __half h0 = __float2half(v.x), h1 = __float2half(v.y);
    __half h2 = __float2half(v.z), h3 = __float2half(v.w);
    __half l0 = __float2half(v.x - __half2float(h0));
    __half l1 = __float2half(v.y - __half2float(h1));
    __half l2 = __float2half(v.z - __half2float(h2));
    __half l3 = __float2half(v.w - __half2float(h3));
    hi[0] = __halves2half2(h0, h1);
    hi[1] = __halves2half2(h2, h3);
    lo[0] = __halves2half2(l0, l1);
    lo[1] = __halves2half2(l2, l3);
}
__device__ __forceinline__ void cvt4h(float4 v, __half2* hi) {
    hi[0] = __halves2half2(__float2half(v.x), __float2half(v.y));
    hi[1] = __halves2half2(__float2half(v.z), __float2half(v.w));
}

// -------------- prep: pack weights + zero d_out + router, one launch ----------
#define QKV_U (ENUM*DDIM*(QKVP/4))
#define GW_U  (DDIM*VDIM/4)
#define OW_U  (VDIM*DDIM/4)
#define HID_U (SLEN*DDIM/4)
#define TOT_U (QKV_U + GW_U + OW_U + HID_U)
#define PACK_B (TOT_U/256)
#define ZERO_B ((SLEN*DDIM/4)/256)
#define PREP_B (PACK_B + ZERO_B + SLEN)

__global__ void prep_kernel(const float* __restrict__ q_w, const float* __restrict__ k_w,
                            const float* __restrict__ v_w, const float* __restrict__ b_w,
                            const float* __restrict__ a_w, const float* __restrict__ g_w,
                            const float* __restrict__ o_w, const float* __restrict__ hidden,
                            const float* __restrict__ gate_w, float4* __restrict__ outz) {
    int blk = blockIdx.x;
    int tid = threadIdx.x;
    if (blk < PACK_B) {
        long long u = (long long)blk * 256 + tid;
        if (u < QKV_U) {
            long long per_e = (long long)DDIM * (QKVP / 4);
            int e = (int)(u / per_e);
            long long r = u - (long long)e * per_e;
            int d = (int)(r / (QKVP / 4));
            int c4 = (int)(r - (long long)d * (QKVP / 4));
            int n = c4 * 4;
            float4 src;
            if (n < KDIM) {
                src = *(const float4*)(q_w + (size_t)d * KDIM + n);
            } else if (n < 2 * KDIM) {
                src = *(const float4*)(k_w + ((size_t)e * DDIM + d) * KDIM + (n - KDIM));
            } else if (n < QKVO) {
                src = *(const float4*)(v_w + ((size_t)e * DDIM + d) * VDIM + (n - 2 * KDIM));
            } else {
                float vals[4];
#pragma unroll
                for (int j = 0; j < 4; j++) {
                    int c = n + j;
                    if (c < QKVO + HNUM)
                        vals[j] = b_w[((size_t)e * DDIM + d) * HNUM + (c - QKVO)];
                    else if (c < QKVO + 2 * HNUM)
                        vals[j] = a_w[((size_t)e * DDIM + d) * HNUM + (c - QKVO - HNUM)];
                    else
                        vals[j] = 0.f;
                }
                src = make_float4(vals[0], vals[1], vals[2], vals[3]);
            }
            size_t dst = ((size_t)e * DDIM + d) * QKVP + n;
            __half2 h[2];
            cvt4h(src, h);
            __half2* hp = (__half2*)(d_qkvw + dst);
            hp[0] = h[0]; hp[1] = h[1];
            return;
        }
        u -= QKV_U;
        if (u < GW_U) {
            float4 src = ((const float4*)g_w)[u];
            __half2 h[2]; cvt4h(src, h);
            ((__half2*)d_gw)[2 * u] = h[0]; ((__half2*)d_gw)[2 * u + 1] = h[1];
            return;
        }
        u -= GW_U;
        if (u < OW_U) {
            float4 src = ((const float4*)o_w)[u];
            __nv_bfloat162 h[2], l[2]; split4b(src, h, l);
            ((__nv_bfloat162*)d_ow_hi)[2 * u] = h[0]; ((__nv_bfloat162*)d_ow_hi)[2 * u + 1] = h[1];
            ((__nv_bfloat162*)d_ow_lo)[2 * u] = l[0]; ((__nv_bfloat162*)d_ow_lo)[2 * u + 1] = l[1];
            return;
        }
        u -= OW_U;
        {
            float4 src = ((const float4*)hidden)[u];
            __half2 h[2], l[2]; split4h(src, h, l);
            ((__half2*)d_hid_hi)[2 * u] = h[0]; ((__half2*)d_hid_hi)[2 * u + 1] = h[1];
            ((__half2*)d_hid_lo)[2 * u] = l[0]; ((__half2*)d_hid_lo)[2 * u + 1] = l[1];
        }
        return;
    }
    blk -= PACK_B;
    if (blk < ZERO_B) {
        outz[blk * 256 + tid] = make_float4(0.f, 0.f, 0.f, 0.f);
        return;
    }
    // router: one block per token
    int s = blk - ZERO_B;
    float acc[ENUM];
#pragma unroll
    for (int e = 0; e < ENUM; e++) acc[e] = 0.f;
    const float* xr = hidden + (size_t)s * DDIM;
    for (int d = tid; d < DDIM; d += 256) {
        float x = xr[d];
        const float* w = gate_w + (size_t)d * ENUM;
#pragma unroll
        for (int e = 0; e < ENUM; e++) acc[e] += x * w[e];
    }
    __shared__ float red[ENUM][256];
#pragma unroll
    for (int e = 0; e < ENUM; e++) red[e][tid] = acc[e];
    __syncthreads();
    for (int st = 128; st > 0; st >>= 1) {
        if (tid < st) {
#pragma unroll
            for (int e = 0; e < ENUM; e++) red[e][tid] += red[e][tid + st];
        }
        __syncthreads();
    }
    if (tid == 0) {
        float l[ENUM], mx = -1e30f;
#pragma unroll
        for (int e = 0; e < ENUM; e++) { l[e] = red[e][0]; mx = fmaxf(mx, l[e]); }
        float p[ENUM], sum = 0.f;
#pragma unroll
        for (int e = 0; e < ENUM; e++) { p[e] = expf(l[e] - mx); sum += p[e]; }
#pragma unroll
        for (int e = 0; e < ENUM; e++) p[e] /= sum;
        int i0 = 0;
#pragma unroll
        for (int e = 1; e < ENUM; e++) if (p[e] > p[i0]) i0 = e;
        int i1 = -1;
#pragma unroll
        for (int e = 0; e < ENUM; e++)
            if (e != i0 && (i1 < 0 || p[e] > p[i1])) i1 = e;
        float r0 = p[i0], r1 = p[i1], rs = r0 + r1;
        d_sel[2 * s] = i0;  d_sel[2 * s + 1] = i1;
        d_rw[2 * s] = r0 / rs;  d_rw[2 * s + 1] = r1 / rs;
    }
}

// ---------------- fp16 2-term GEMM core (qkv + gate) --------------------------
// C = Ah*B + Al*B. Stage = Ah 8KB + Al 8KB + B 8KB = 24KB; 3 stages = 72KB.
#define A2_BYTES 8192
#define STAGE2_BYTES 24576
#define GEMM2_SMEM (3*STAGE2_BYTES)

__device__ __forceinline__ void gemm_core2(
    const __half* __restrict__ Ahi, const __half* __restrict__ Alo,
    const __half* __restrict__ B,
    float* __restrict__ C, int mlim, int N, int K, int lda, int row0, int col0,
    __half* smbuf) {
    uint32_t sbase = (uint32_t)__cvta_generic_to_shared(smbuf);
    int t = threadIdx.x;

    int arow = t >> 1, ac0 = (t & 1) * 2;
    int brow = t >> 3, bc0 = (t & 7) * 2;
    uint32_t aswr = ((uint32_t)(arow >> 1)) & 3u;
    uint32_t bswr = (uint32_t)(brow & 7);
    const __half* gAh = Ahi + (size_t)(row0 + arow) * lda;
    const __half* gAl = Alo + (size_t)(row0 + arow) * lda;
    const __half* gB  = B + (size_t)brow * N + col0;
    uint32_t aoff0 = (uint32_t)(arow * 64) + (((uint32_t)ac0 ^ aswr) * 16);
    uint32_t aoff1 = (uint32_t)(arow * 64) + ((((uint32_t)ac0 + 1u) ^ aswr) * 16);
    uint32_t boff0 = (uint32_t)(brow * 256) + (((uint32_t)bc0 ^ bswr) * 16);
    uint32_t boff1 = (uint32_t)(brow * 256) + ((((uint32_t)bc0 + 1u) ^ bswr) * 16);

    int lane = t & 31, wid = t >> 5;
    int wm = (wid >> 2) * 64, wn = (wid & 3) * 32;
    int lr = lane & 15;
    uint32_t swA = ((uint32_t)(lr >> 1)) & 3u;
    uint32_t achb = (uint32_t)(lane >> 4);
    uint32_t arowb = (uint32_t)((wm + lr) * 64);
    int blr = lane & 7, bgp = lane >> 3;
    uint32_t cbB = (uint32_t)((wid & 3) * 4 + (bgp >> 1));
    uint32_t brb = (uint32_t)(blr + (bgp & 1) * 8);

    float acc[4][4][4];
#pragma unroll
    for (int mi = 0; mi < 4; mi++)
#pragma unroll
        for (int ni = 0; ni < 4; ni++)
#pragma unroll
            for (int j = 0; j < 4; j++) acc[mi][ni][j] = 0.f;

    int KT = K / 32;

    auto load_stage = [&](int ktl) {
        int k0 = ktl * 32;
        uint32_t so = sbase + (uint32_t)((ktl % 3) * STAGE2_BYTES);
        cpa16(so + aoff0, gAh + k0 + ac0 * 8);
        cpa16(so + aoff1, gAh + k0 + ac0 * 8 + 8);
        cpa16(so + A2_BYTES + aoff0, gAl + k0 + ac0 * 8);
        cpa16(so + A2_BYTES + aoff1, gAl + k0 + ac0 * 8 + 8);
        cpa16(so + 2 * A2_BYTES + boff0, gB + (size_t)k0 * N + bc0 * 8);
        cpa16(so + 2 * A2_BYTES + boff1, gB + (size_t)k0 * N + bc0 * 8 + 8);
        asm volatile("cp.async.commit_group;");
    };

    load_stage(0);
    if (KT > 1) load_stage(1);

    for (int kt = 0; kt < KT; kt++) {
        if (kt + 1 < KT) {
            asm volatile("cp.async.wait_group 1;");
        } else {
            asm volatile("cp.async.wait_group 0;");
        }
        __syncthreads();
        if (kt + 2 < KT) load_stage(kt + 2);

        uint32_t s0 = sbase + (uint32_t)((kt % 3) * STAGE2_BYTES);
        uint32_t sAh = s0;
        uint32_t sAl = s0 + A2_BYTES;
        uint32_t sB  = s0 + 2 * A2_BYTES;

#pragma unroll
        for (int ks = 0; ks < 2; ks++) {
            uint32_t rB = brb + (uint32_t)(ks * 16);
            uint32_t bo0 = rB * 256 + ((cbB ^ (uint32_t)blr) * 16);
            uint32_t bo1 = rB * 256 + (((cbB + 2u) ^ (uint32_t)blr) * 16);
            uint32_t ach = achb + (uint32_t)(ks * 2);
            uint32_t ao = arowb + ((ach ^ swA) * 16);

            uint32_t bh[8], af[16];
            ldm_x4t(bh + 0, sB + bo0);
            ldm_x4t(bh + 4, sB + bo1);
#pragma unroll
            for (int mi = 0; mi < 4; mi++)
                ldm_x4(af + mi * 4, sAh + ao + (uint32_t)(mi * 1024));
#pragma unroll
            for (int mi = 0; mi < 4; mi++)
#pragma unroll
                for (int ni = 0; ni < 4; ni++)
                    mma_f16(acc[mi][ni], af + mi * 4, bh + (ni >> 1) * 4 + (ni & 1) * 2);
#pragma unroll
            for (int mi = 0; mi < 4; mi++)
                ldm_x4(af + mi * 4, sAl + ao + (uint32_t)(mi * 1024));
#pragma unroll
            for (int mi = 0; mi < 4; mi++)
#pragma unroll
                for (int ni = 0; ni < 4; ni++)
                    mma_f16(acc[mi][ni], af + mi * 4, bh + (ni >> 1) * 4 + (ni & 1) * 2);
        }
    }

    int gr = lane >> 2, gc = (lane & 3) * 2;
#pragma unroll
    for (int mi = 0; mi < 4; mi++) {
        int r = row0 + wm + mi * 16 + gr;
#pragma unroll
        for (int ni = 0; ni < 4; ni++) {
            float* Cp = C + (size_t)r * N + col0 + wn + ni * 8 + gc;
            if (r < mlim) {
                Cp[0] = acc[mi][ni][0];
                Cp[1] = acc[mi][ni][1];
            }
            if (r + 8 < mlim) {
                float* Cq = Cp + (size_t)8 * N;
                Cq[0] = acc[mi][ni][2];
                Cq[1] = acc[mi][ni][3];
            }
        }
    }
}

// merged qkv (z=0..7) + gate (z=8) GEMM launch (fp16 2-term)
__global__ __launch_bounds__(256, 2)
void gemm_qkv_gate(const __half* __restrict__ xgh, const __half* __restrict__ xgl,
                   const __half* __restrict__ qkvw, float* __restrict__ qkvpre,
                   const __half* __restrict__ hih, const __half* __restrict__ hil,
                   const __half* __restrict__ gw, float* __restrict__ gg) {
    extern __shared__ __half smbuf2[];
    int z = blockIdx.z;
    int row0 = blockIdx.y * 128;
    int col0 = blockIdx.x * 128;
    if (z < ENUM) {
        int mlim = d_m[z];
        if (row0 >= mlim) return;
        gemm_core2(xgh + (size_t)z * CAP * DDIM, xgl + (size_t)z * CAP * DDIM,
                   qkvw + (size_t)z * DDIM * QKVP,
                   qkvpre + (size_t)z * CAP * QKVP, mlim, QKVP, DDIM, DDIM,
                   row0, col0, smbuf2);
    } else {
        if (col0 >= VDIM) return;
        gemm_core2(hih, hil, gw, gg, SLEN, VDIM, DDIM, DDIM, row0, col0, smbuf2);
    }
}

// ---------------- bf16 3-term GEMM core (output GEMM, atomic) ------------------
#define A_BYTES 8192
#define B_BYTES 8192
#define STAGE_BYTES 32768
#define GEMM_SMEM (3*STAGE_BYTES)

__device__ __forceinline__ void gemm_core3(
    const __nv_bfloat16* __restrict__ Ahi, const __nv_bfloat16* __restrict__ Alo,
    const __nv_bfloat16* __restrict__ Bhi, const __nv_bfloat16* __restrict__ Blo,
    float* __restrict__ C, int mlim, int N, int K, int lda, int row0, int col0,
    __nv_bfloat16* smbuf) {
    uint32_t sbase = (uint32_t)__cvta_generic_to_shared(smbuf);
    int t = threadIdx.x;

    int arow = t >> 1, ac0 = (t & 1) * 2;
    int brow = t >> 3, bc0 = (t & 7) * 2;
    uint32_t aswr = ((uint32_t)(arow >> 1)) & 3u;
    uint32_t bswr = (uint32_t)(brow & 7);
    const __nv_bfloat16* gAh = Ahi + (size_t)(row0 + arow) * lda;
    const __nv_bfloat16* gAl = Alo + (size_t)(row0 + arow) * lda;
    const __nv_bfloat16* gBh = Bhi + (size_t)brow * N + col0;
    const __nv_bfloat16* gBl = Blo + (size_t)brow * N + col0;
    uint32_t aoff0 = (uint32_t)(arow * 64) + (((uint32_t)ac0 ^ aswr) * 16);
    uint32_t aoff1 = (uint32_t)(arow * 64) + ((((uint32_t)ac0 + 1u) ^ aswr) * 16);
    uint32_t boff0 = (uint32_t)(brow * 256) + (((uint32_t)bc0 ^ bswr) * 16);
    uint32_t boff1 = (uint32_t)(brow * 256) + ((((uint32_t)bc0 + 1u) ^ bswr) * 16);

    int lane = t & 31, wid = t >> 5;
    int wm = (wid >> 2) * 64, wn = (wid & 3) * 32;
    int lr = lane & 15;
    uint32_t swA = ((uint32_t)(lr >> 1)) & 3u;
    uint32_t achb = (uint32_t)(lane >> 4);
    uint32_t arowb = (uint32_t)((wm + lr) * 64);
    int blr = lane & 7, bgp = lane >> 3;
    uint32_t cbB = (uint32_t)((wid & 3) * 4 + (bgp >> 1));
    uint32_t brb = (uint32_t)(blr + (bgp & 1) * 8);

    float acc[4][4][4];
#pragma unroll
    for (int mi = 0; mi < 4; mi++)
#pragma unroll
        for (int ni = 0; ni < 4; ni++)
#pragma unroll
            for (int j = 0; j < 4; j++) acc[mi][ni][j] = 0.f;

    int KT = K / 32;

    auto load_stage = [&](int ktl) {
        int k0 = ktl * 32;
        uint32_t so = sbase + (uint32_t)((ktl % 3) * STAGE_BYTES);
        cpa16(so + aoff0, gAh + k0 + ac0 * 8);
        cpa16(so + aoff1, gAh + k0 + ac0 * 8 + 8);
        cpa16(so + A_BYTES + aoff0, gAl + k0 + ac0 * 8);
        cpa16(so + A_BYTES + aoff1, gAl + k0 + ac0 * 8 + 8);
        cpa16(so + 2 * A_BYTES + boff0, gBh + (size_t)k0 * N + bc0 * 8);
        cpa16(so + 2 * A_BYTES + boff1, gBh + (size_t)k0 * N + bc0 * 8 + 8);
        cpa16(so + 2 * A_BYTES + B_BYTES + boff0, gBl + (size_t)k0 * N + bc0 * 8);
        cpa16(so + 2 * A_BYTES + B_BYTES + boff1, gBl + (size_t)k0 * N + bc0 * 8 + 8);
        asm volatile("cp.async.commit_group;");
    };

    load_stage(0);
    if (KT > 1) load_stage(1);

    for (int kt = 0; kt < KT; kt++) {
        if (kt + 1 < KT) {
            asm volatile("cp.async.wait_group 1;");
        } else {
            asm volatile("cp.async.wait_group 0;");
        }
        __syncthreads();
        if (kt + 2 < KT) load_stage(kt + 2);

        uint32_t s0 = sbase + (uint32_t)((kt % 3) * STAGE_BYTES);
        uint32_t sAh = s0;
        uint32_t sAl = s0 + A_BYTES;
        uint32_t sBh = s0 + 2 * A_BYTES;
        uint32_t sBl = s0 + 2 * A_BYTES + B_BYTES;

#pragma unroll
        for (int ks = 0; ks < 2; ks++) {
            uint32_t rB = brb + (uint32_t)(ks * 16);
            uint32_t bo0 = rB * 256 + ((cbB ^ (uint32_t)blr) * 16);
            uint32_t bo1 = rB * 256 + (((cbB + 2u) ^ (uint32_t)blr) * 16);
            uint32_t ach = achb + (uint32_t)(ks * 2);
            uint32_t ao = arowb + ((ach ^ swA) * 16);

            uint32_t bh[8], bl2[8], af[16];
            ldm_x4t(bh + 0, sBh + bo0);
            ldm_x4t(bh + 4, sBh + bo1);
            ldm_x4t(bl2 + 0, sBl + bo0);
            ldm_x4t(bl2 + 4, sBl + bo1);
#pragma unroll
            for (int mi = 0; mi < 4; mi++)
                ldm_x4(af + mi * 4, sAh + ao + (uint32_t)(mi * 1024));
#pragma unroll
            for (int mi = 0; mi < 4; mi++)
#pragma unroll
                for (int ni = 0; ni < 4; ni++)
                    mma_bf16(acc[mi][ni], af + mi * 4, bh + (ni >> 1) * 4 + (ni & 1) * 2);
#pragma unroll
            for (int mi = 0; mi < 4; mi++)
#pragma unroll
                for (int ni = 0; ni < 4; ni++)
                    mma_bf16(acc[mi][ni], af + mi * 4, bl2 + (ni >> 1) * 4 + (ni & 1) * 2);
#pragma unroll
            for (int mi = 0; mi < 4; mi++)
                ldm_x4(af + mi * 4, sAl + ao + (uint32_t)(mi * 1024));
#pragma unroll
            for (int mi = 0; mi < 4; mi++)
#pragma unroll
                for (int ni = 0; ni < 4; ni++)
                    mma_bf16(acc[mi][ni], af + mi * 4, bh + (ni >> 1) * 4 + (ni & 1) * 2);
        }
    }

    int gr = lane >> 2, gc = (lane & 3) * 2;
#pragma unroll
    for (int mi = 0; mi < 4; mi++) {
        int r = row0 + wm + mi * 16 + gr;
#pragma unroll
        for (int ni = 0; ni < 4; ni++) {
            float* Cp = C + (size_t)r * N + col0 + wn + ni * 8 + gc;
            if (r < mlim) {
                atomicAdd(Cp, acc[mi][ni][0]);
                atomicAdd(Cp + 1, acc[mi][ni][1]);
            }
            if (r + 8 < mlim) {
                float* Cq = Cp + (size_t)8 * N;
                atomicAdd(Cq, acc[mi][ni][2]);
                atomicAdd(Cq + 1, acc[mi][ni][3]);
            }
        }
    }
}

// split-K output GEMM: z selects K-half, accumulates via atomics.
__global__ __launch_bounds__(256, 2)
void gemm_out_splitk(const __nv_bfloat16* __restrict__ Ahi, const __nv_bfloat16* __restrict__ Alo,
                     const __nv_bfloat16* __restrict__ Bhi, const __nv_bfloat16* __restrict__ Blo,
                     float* __restrict__ C) {
    extern __shared__ __nv_bfloat16 smbuf[];
    int z = blockIdx.z;
    int row0 = blockIdx.y * 128;
    int col0 = blockIdx.x * 128;
    int kHalf = VDIM / 2;
    gemm_core3(Ahi + (size_t)z * kHalf, Alo + (size_t)z * kHalf,
               Bhi + (size_t)z * kHalf * DDIM, Blo + (size_t)z * kHalf * DDIM,
               C, SLEN, DDIM, kHalf, VDIM, row0, col0, smbuf);
}

// -------------- dispatch: parallel warp-per-expert ballot scan ----------------
__global__ void dispatch_kernel() {
    int e = threadIdx.x >> 5;
    int lane = threadIdx.x & 31;
    int cnt = 0;
    for (int i = lane; i < SLEN * 2; i += 32) cnt += (d_sel[i] == e);
#pragma unroll
    for (int o = 16; o; o >>= 1) cnt += __shfl_xor_sync(0xffffffffu, cnt, o);
    int drop = cnt > CAP ? cnt - CAP : 0;
    if (lane == 0) d_m[e] = cnt - drop;
    int base = 0;
    for (int i0 = 0; i0 < SLEN * 2; i0 += 32) {
        int i = i0 + lane;
        bool hit = (d_sel[i] == e);
        unsigned mask = __ballot_sync(0xffffffffu, hit);
        if (hit) {
            int r = base + __popc(mask & ((1u << lane) - 1u));
            if (r >= drop) {
                int j = r - drop;
                d_tok[e * CAP + j] = i >> 1;
                d_pos[i] = e * CAP + j;
            } else {
                d_pos[i] = -1;
            }
        }
        base += __popc(mask);
    }
}

// -------------- gather + fp16 hi/lo split of activations ----------------------
__global__ void gather_split_kernel(const float* __restrict__ hidden) {
    int row = blockIdx.x;
    int e = row >> 10, t = row & 1023;
    if (t >= d_m[e]) return;
    const float4* src = (const float4*)(hidden + (size_t)d_tok[row] * DDIM);
    __half2* hi = (__half2*)(d_xg_hi + (size_t)row * DDIM);
    __half2* lo = (__half2*)(d_xg_lo + (size_t)row * DDIM);
    for (int i = threadIdx.x; i < DDIM / 4; i += 256) {
        float4 v = src[i];
        __half2 h[2], l[2];
        split4h(v, h, l);
        hi[2 * i] = h[0]; hi[2 * i + 1] = h[1];
        lo[2 * i] = l[0]; lo[2 * i + 1] = l[1];
    }
}

// -------------- merged conv + bg launch ----------------------------------------
__global__ void conv_all_kernel(const float* __restrict__ pre,
                                const float* __restrict__ qcw,
                                const float* __restrict__ kcw,
                                const float* __restrict__ vcw,
                                const float* __restrict__ A_log,
                                const float* __restrict__ dt_bias) {
    int row = blockIdx.x;
    int y = blockIdx.y;
    int e = row >> 10, t = row & 1023;
    if (t >= d_m[e]) return;
    int tid = threadIdx.x;

    if (y < 12) {
        int h = (y < 6) ? y : (y - 6);
        int preOff = (y < 6) ? 0 : KDIM;
        float scale = (y < 6) ? 0.0625f : 1.0f;
        const float* cw = (y < 6) ? qcw : kcw;
        float* out = (y < 6) ? d_qn : d_kn;
        int ch = h * DKC + tid;
        float yv = 0.f;
#pragma unroll
        for (int j = 0; j < 4; j++) {
            int tt = t - 3 + j;
            if (tt >= 0) yv += cw[ch * 4 + j] * pre[(size_t)(row - 3 + j) * QKVP + preOff + ch];
        }
        yv = yv / (1.f + expf(-yv));
        __shared__ float red[256];
        red[tid] = yv * yv;
        __syncthreads();
        for (int st = 128; st > 0; st >>= 1) {
            if (tid < st) red[tid] += red[tid + st];
            __syncthreads();
        }
        float inv = rsqrtf(red[0] + 1e-6f) * scale;
        out[(size_t)row * KDIM + ch] = yv * inv;
    } else if (y < 24) {
        int ch = (y - 12) * 256 + tid;
        float yv = 0.f;
#pragma unroll
        for (int j = 0; j < 4; j++) {
            int tt = t - 3 + j;
            if (tt >= 0) yv += vcw[ch * 4 + j] * pre[(size_t)(row - 3 + j) * QKVP + 2 * KDIM + ch];
        }
        d_vn[(size_t)row * VDIM + ch] = yv / (1.f + expf(-yv));
    } else {
        if (tid < HNUM) {
            float bl = pre[(size_t)row * QKVP + QKVO + tid];
            float al = pre[(size_t)row * QKVP + QKVO + HNUM + tid];
            d_beta[row * HNUM + tid] = 1.f / (1.f + expf(-bl));
            float xx = al + dt_bias[tid];
            float sp = xx > 20.f ? xx : log1pf(expf(xx));
            d_g[row * HNUM + tid] = -expf(A_log[tid]) * sp;
        }
    }
}

// -------------- gated delta-rule recurrence (conflict-free strided) -----------
__global__ void recur_kernel() {
    int vc = blockIdx.x;
    int h = blockIdx.y;
    int e = blockIdx.z;
    int m = d_m[e];
    __shared__ float S[32 * 256];
    __shared__ float su[32], sw[32], sd[32];
    int tid = threadIdx.x, warp = tid >> 5, lane = tid & 31;
    int v0 = warp * 4;
    for (int i = lane; i < 4 * 256; i += 32) S[v0 * 256 + i] = 0.f;
    if (lane < 4) { su[v0 + lane] = 0.f; sw[v0 + lane] = 0.f; }
    __syncwarp();
    if (m == 0) return;

    const float* kb = d_kn + (size_t)(e * CAP) * KDIM + h * DKC;
    const float* qb = d_qn + (size_t)(e * CAP) * KDIM + h * DKC;
    const float* vb = d_vn + (size_t)(e * CAP) * VDIM + h * DVC + vc * 32;
    const float* bb = d_beta + (size_t)(e * CAP) * HNUM + h;
    const float* gb = d_g + (size_t)(e * CAP) * HNUM + h;
    float* ob = d_o + (size_t)(e * CAP) * VDIM + h * DVC + vc * 32;

    float kc[8], qc[8];
#pragma unroll
    for (int j = 0; j < 8; j++) { kc[j] = kb[lane + 32 * j]; qc[j] = qb[lane + 32 * j]; }
    float beta = bb[0];
    float gv = gb[0];
    float vv = (lane < 4) ? vb[v0 + lane] : 0.f;

    for (int t = 0; t < m; t++) {
        float eg = expf(gv);
        float qk = 0.f;
#pragma unroll
        for (int j = 0; j < 8; j++) qk += kc[j] * qc[j];
#pragma unroll
        for (int o = 16; o; o >>= 1) qk += __shfl_xor_sync(0xffffffffu, qk, o);

        if (lane < 4) {
            int v = v0 + lane;
            float dd = beta * (vv - eg * su[v]);
            ob[(size_t)t * VDIM + v] = eg * sw[v] + qk * dd;
            sd[v] = dd;
        }
        __syncwarp();

        float kn2[8], qn2[8];
        float beta_n = 0.f, g_n = 0.f, vv_n = 0.f;
        if (t + 1 < m) {
            const float* kr = kb + (size_t)(t + 1) * KDIM;
            const float* qr = qb + (size_t)(t + 1) * KDIM;
#pragma unroll
            for (int j = 0; j < 8; j++) { kn2[j] = kr[lane + 32 * j]; qn2[j] = qr[lane + 32 * j]; }
            beta_n = bb[(size_t)(t + 1) * HNUM];
            g_n = gb[(size_t)(t + 1) * HNUM];
            if (lane < 4) vv_n = vb[(size_t)(t + 1) * VDIM + v0 + lane];
        } else {
#pragma unroll
            for (int j = 0; j < 8; j++) { kn2[j] = 0.f; qn2[j] = 0.f; }
        }

#pragma unroll
        for (int vi = 0; vi < 4; vi++) {
            int v = v0 + vi;
            float dd = sd[v];
            float un = 0.f, wn = 0.f;
            float* Sr = &S[v * 256];
#pragma unroll
            for (int j = 0; j < 8; j++) {
                float s2 = Sr[lane + 32 * j];
                s2 = eg * s2 + kc[j] * dd;
                Sr[lane + 32 * j] = s2;
                un += kn2[j] * s2;
                wn += qn2[j] * s2;
            }
#pragma unroll
            for (int o = 16; o; o >>= 1) {
                un += __shfl_xor_sync(0xffffffffu, un, o);
                wn += __shfl_xor_sync(0xffffffffu, wn, o);
            }
            if (lane == 0) { su[v] = un; sw[v] = wn; }
        }
        __syncwarp();
#pragma unroll
        for (int j = 0; j < 8; j++) { kc[j] = kn2[j]; qc[j] = qn2[j]; }
        beta = beta_n; gv = g_n; vv = vv_n;
    }
}

// -------------- combine + gated RMSNorm + bf16 hi/lo (fused) ------------------
__global__ void combine_kernel(const float* __restrict__ norm_w) {
    int s = blockIdx.x, h = blockIdx.y, tid = threadIdx.x;
    int p0 = d_pos[2 * s], p1 = d_pos[2 * s + 1];
    float r0 = d_rw[2 * s], r1 = d_rw[2 * s + 1];
    float acc[2];
    float ss = 0.f;
#pragma unroll
    for (int i = 0; i < 2; i++) {
        int v = tid + i * 256;
        float a = 0.f;
        if (p0 >= 0) a += r0 * d_o[(size_t)p0 * VDIM + h * DVC + v];
        if (p1 >= 0) a += r1 * d_o[(size_t)p1 * VDIM + h * DVC + v];
        acc[i] = a;
        ss += a * a;
    }
    __shared__ float red[256];
    red[tid] = ss;
    __syncthreads();
    for (int st = 128; st > 0; st >>= 1) {
        if (tid < st) red[tid] += red[tid + st];
        __syncthreads();
    }
    float inv = rsqrtf(red[0] / (float)DVC + 1e-5f);
#pragma unroll
    for (int i = 0; i < 2; i++) {
        int v = tid + i * 256;
        float gg = d_gg[(size_t)s * VDIM + h * DVC + v];
        float sg = gg / (1.f + expf(-gg));
        float val = acc[i] * inv * norm_w[v] * sg;
        __nv_bfloat16 hb = __float2bfloat16(val);
        __nv_bfloat16 lb = __float2bfloat16(val - __bfloat162float(hb));
        size_t idx = (size_t)s * VDIM + h * DVC + v;
        d_pre_hi[idx] = hb;
        d_pre_lo[idx] = lb;
    }
}

// ----------------------------- launch -----------------------------------------
extern "C" void kernel_launch(void* const* d_in, const int* in_sizes, int n_in,
                              void* d_out, int out_size) {
    const float* hidden  = (const float*)d_in[0];
    const float* q_w     = (const float*)d_in[1];
    const float* gate_w  = (const float*)d_in[2];
    const float* k_w     = (const float*)d_in[3];
    const float* v_w     = (const float*)d_in[4];
    const float* b_w     = (const float*)d_in[5];
    const float* a_w     = (const float*)d_in[6];
    const float* A_log   = (const float*)d_in[7];
    const float* dt_bias = (const float*)d_in[8];
    const float* qcw     = (const float*)d_in[9];
    const float* kcw     = (const float*)d_in[10];
    const float* vcw     = (const float*)d_in[11];
    const float* g_w     = (const float*)d_in[12];
    const float* norm_w  = (const float*)d_in[13];
    const float* o_w     = (const float*)d_in[14];

    float* qkvpre = 0; float* gg = 0;
    cudaGetSymbolAddress((void**)&qkvpre, d_qkvpre);
    cudaGetSymbolAddress((void**)&gg, d_gg);

    __half* xgh = 0; __half* xgl = 0; __half* qkvw = 0; __half* gw = 0;
    __half* hih = 0; __half* hil = 0;
    __nv_bfloat16* owh = 0; __nv_bfloat16* owl = 0;
    __nv_bfloat16* prh = 0; __nv_bfloat16* prl = 0;
    cudaGetSymbolAddress((void**)&xgh, d_xg_hi);
    cudaGetSymbolAddress((void**)&xgl, d_xg_lo);
    cudaGetSymbolAddress((void**)&qkvw, d_qkvw);
    cudaGetSymbolAddress((void**)&gw, d_gw);
    cudaGetSymbolAddress((void**)&hih, d_hid_hi);
    cudaGetSymbolAddress((void**)&hil, d_hid_lo);
    cudaGetSymbolAddress((void**)&owh, d_ow_hi);
    cudaGetSymbolAddress((void**)&owl, d_ow_lo);
    cudaGetSymbolAddress((void**)&prh, d_pre_hi);
    cudaGetSymbolAddress((void**)&prl, d_pre_lo);

    cudaFuncSetAttribute(gemm_qkv_gate, cudaFuncAttributeMaxDynamicSharedMemorySize, GEMM2_SMEM);
    cudaFuncSetAttribute(gemm_out_splitk, cudaFuncAttributeMaxDynamicSharedMemorySize, GEMM_SMEM);

    // 1: prep = pack weights + zero d_out + router
    prep_kernel<<<PREP_B, 256>>>(q_w, k_w, v_w, b_w, a_w, g_w, o_w, hidden, gate_w,
                                 (float4*)d_out);
    // 2: dispatch
    dispatch_kernel<<<1, 256>>>();
    // 3: gather + activation split
    gather_split_kernel<<<NROW, 256>>>(hidden);
    // 4: merged qkv (z<8) + gate (z=8) projections (fp16 2-term)
    gemm_qkv_gate<<<dim3(QKVP / 128, CAP / 128, ENUM + 1), 256, GEMM2_SMEM>>>(
        xgh, xgl, qkvw, qkvpre, hih, hil, gw, gg);
    // 5: merged convs + bg epilogue
    conv_all_kernel<<<dim3(NROW, 25), 256>>>(qkvpre, qcw, kcw, vcw, A_log, dt_bias);
    // 6: recurrence
    recur_kernel<<<dim3(DVC / 32, HNUM, ENUM), 256>>>();
    // 7: combine + RMSNorm + bf16 split
    combine_kernel<<<dim3(SLEN, HNUM), 256>>>(norm_w);
    // 8: split-K output GEMM (bf16 3-term, atomic accumulate)
    gemm_out_splitk<<<dim3(DDIM / 128, SLEN / 128, 2), 256, GEMM_SMEM>>>(
        prh, prl, owh, owl, (float*)d_out);
}

// round 17
// speedup vs baseline: 1.4753x; 1.0102x over previous
#include <cuda_runtime.h>
#include <cuda_bf16.h>
#include <cuda_fp16.h>
#include <stdint.h>
#include <math.h>

#define SLEN 1024
#define DDIM 2048
#define ENUM 8
#define HNUM 6
#define DKC  256
#define DVC  512
#define KDIM 1536   // HNUM*DKC
#define VDIM 3072   // HNUM*DVC
#define QKVO 6144   // q+k+v data cols
#define QKVP 6272   // padded: + 12 beta/g cols + zero pad (49*128)
#define CAP  1024
#define NROW (ENUM*CAP)

// ---------------- scratch (device globals; no allocation in kernel_launch) ----
__device__ int   d_sel[SLEN*2];
__device__ float d_rw [SLEN*2];
__device__ int   d_m  [ENUM];
__device__ int   d_tok[NROW];
__device__ int   d_pos[SLEN*2];
__device__ float d_qkvpre[(size_t)NROW*QKVP];
__device__ float d_qn  [NROW*KDIM];
__device__ float d_kn  [NROW*KDIM];
__device__ float d_vn  [NROW*VDIM];
__device__ float d_beta[NROW*HNUM];
__device__ float d_g   [NROW*HNUM];
__device__ float d_o   [NROW*VDIM];
__device__ float d_gg  [SLEN*VDIM];

// fp16 buffers (qkv+gate GEMM path: A 2-term, B 1-term)
__device__ __align__(256) __half d_xg_hi[NROW*DDIM];
__device__ __align__(256) __half d_xg_lo[NROW*DDIM];
__device__ __align__(256) __half d_qkvw[(size_t)ENUM*DDIM*QKVP];
__device__ __align__(256) __half d_gw[DDIM*VDIM];
__device__ __align__(256) __half d_hid_hi[SLEN*DDIM];
__device__ __align__(256) __half d_hid_lo[SLEN*DDIM];
// bf16 buffers (output GEMM path: 3-term, full accuracy)
__device__ __align__(256) __nv_bfloat16 d_ow_hi[VDIM*DDIM];
__device__ __align__(256) __nv_bfloat16 d_ow_lo[VDIM*DDIM];
__device__ __align__(256) __nv_bfloat16 d_pre_hi[SLEN*VDIM];
__device__ __align__(256) __nv_bfloat16 d_pre_lo[SLEN*VDIM];

// ---------------- PTX helpers -------------------------------------------------
__device__ __forceinline__ void cpa16(uint32_t d, const void* s) {
    asm volatile("cp.async.cg.shared.global [%0], [%1], 16;" :: "r"(d), "l"(s));
}
__device__ __forceinline__ void ldm_x4(uint32_t* r, uint32_t a) {
    asm volatile("ldmatrix.sync.aligned.m8n8.x4.shared.b16 {%0,%1,%2,%3}, [%4];"
                 : "=r"(r[0]), "=r"(r[1]), "=r"(r[2]), "=r"(r[3]) : "r"(a));
}
__device__ __forceinline__ void ldm_x4t(uint32_t* r, uint32_t a) {
    asm volatile("ldmatrix.sync.aligned.m8n8.x4.trans.shared.b16 {%0,%1,%2,%3}, [%4];"
                 : "=r"(r[0]), "=r"(r[1]), "=r"(r[2]), "=r"(r[3]) : "r"(a));
}
__device__ __forceinline__ void mma_bf16(float* c, const uint32_t* a, const uint32_t* b) {
    asm volatile(
        "mma.sync.aligned.m16n8k16.row.col.f32.bf16.bf16.f32 "
        "{%0,%1,%2,%3},{%4,%5,%6,%7},{%8,%9},{%0,%1,%2,%3};"
        : "+f"(c[0]), "+f"(c[1]), "+f"(c[2]), "+f"(c[3])
        : "r"(a[0]), "r"(a[1]), "r"(a[2]), "r"(a[3]), "r"(b[0]), "r"(b[1]));
}
__device__ __forceinline__ void mma_f16(float* c, const uint32_t* a, const uint32_t* b) {
    asm volatile(
        "mma.sync.aligned.m16n8k16.row.col.f32.f16.f16.f32 "
        "{%0,%1,%2,%3},{%4,%5,%6,%7},{%8,%9},{%0,%1,%2,%3};"
        : "+f"(c[0]), "+f"(c[1]), "+f"(c[2]), "+f"(c[3])
        : "r"(a[0]), "r"(a[1]), "r"(a[2]), "r"(a[3]), "r"(b[0]), "r"(b[1]));
}

// ---------------- split conversions --------------------------------------------
__device__ __forceinline__ void split4b(float4 v, __nv_bfloat162* hi, __nv_bfloat162* lo) {
    __nv_bfloat16 h0 = __float2bfloat16(v.x), h1 = __float2bfloat16(v.y);
    __nv_bfloat16 h2 = __float2bfloat16(v.z), h3 = __float2bfloat16(v.w);
    __nv_bfloat16 l0 = __float2bfloat16(v.x - __bfloat162float(h0));
    __nv_bfloat16 l1 = __float2bfloat16(v.y - __bfloat162float(h1));
    __nv_bfloat16 l2 = __float2bfloat16(v.z - __bfloat162float(h2));
    __nv_bfloat16 l3 = __float2bfloat16(v.w - __bfloat162float(h3));
    hi[0] = __halves2bfloat162(h0, h1);
    hi[1] = __halves2bfloat162(h2, h3);
    lo[0] = __halves2bfloat162(l0, l1);
    lo[1] = __halves2bfloat162(l2, l3);
}
__device__ __forceinline__ void split4h(float4 v, __half2* hi, __half2* lo) {
    __half h0 = __float2half(v.x), h1 = __float2half(v.y);
    __half h2 = __float2half(v.z), h3 = __float2half(v.w);
    __half l0 = __float2half(v.x - __half2float(h0));
    __half l1 = __float2half(v.y - __half2float(h1));
    __half l2 = __float2half(v.z - __half2float(h2));
    __half l3 = __float2half(v.w - __half2float(h3));
    hi[0] = __halves2half2(h0, h1);
    hi[1] = __halves2half2(h2, h3);
    lo[0] = __halves2half2(l0, l1);
    lo[1] = __halves2half2(l2, l3);
}
__device__ __forceinline__ void cvt4h(float4 v, __half2* hi) {
    hi[0] = __halves2half2(__float2half(v.x), __float2half(v.y));
    hi[1] = __halves2half2(__float2half(v.z), __float2half(v.w));
}

// -------------- prep: pack weights + zero d_out + router, one launch ----------
#define QKV_U (ENUM*DDIM*(QKVP/4))
#define GW_U  (DDIM*VDIM/4)
#define OW_U  (VDIM*DDIM/4)
#define HID_U (SLEN*DDIM/4)
#define TOT_U (QKV_U + GW_U + OW_U + HID_U)
#define PACK_B (TOT_U/256)
#define ZERO_B ((SLEN*DDIM/4)/256)
#define PREP_B (PACK_B + ZERO_B + SLEN)

__global__ void prep_kernel(const float* __restrict__ q_w, const float* __restrict__ k_w,
                            const float* __restrict__ v_w, const float* __restrict__ b_w,
                            const float* __restrict__ a_w, const float* __restrict__ g_w,
                            const float* __restrict__ o_w, const float* __restrict__ hidden,
                            const float* __restrict__ gate_w, float4* __restrict__ outz) {
    int blk = blockIdx.x;
    int tid = threadIdx.x;
    if (blk < PACK_B) {
        long long u = (long long)blk * 256 + tid;
        if (u < QKV_U) {
            long long per_e = (long long)DDIM * (QKVP / 4);
            int e = (int)(u / per_e);
            long long r = u - (long long)e * per_e;
            int d = (int)(r / (QKVP / 4));
            int c4 = (int)(r - (long long)d * (QKVP / 4));
            int n = c4 * 4;
            float4 src;
            if (n < KDIM) {
                src = *(const float4*)(q_w + (size_t)d * KDIM + n);
            } else if (n < 2 * KDIM) {
                src = *(const float4*)(k_w + ((size_t)e * DDIM + d) * KDIM + (n - KDIM));
            } else if (n < QKVO) {
                src = *(const float4*)(v_w + ((size_t)e * DDIM + d) * VDIM + (n - 2 * KDIM));
            } else {
                float vals[4];
#pragma unroll
                for (int j = 0; j < 4; j++) {
                    int c = n + j;
                    if (c < QKVO + HNUM)
                        vals[j] = b_w[((size_t)e * DDIM + d) * HNUM + (c - QKVO)];
                    else if (c < QKVO + 2 * HNUM)
                        vals[j] = a_w[((size_t)e * DDIM + d) * HNUM + (c - QKVO - HNUM)];
                    else
                        vals[j] = 0.f;
                }
                src = make_float4(vals[0], vals[1], vals[2], vals[3]);
            }
            size_t dst = ((size_t)e * DDIM + d) * QKVP + n;
            __half2 h[2];
            cvt4h(src, h);
            __half2* hp = (__half2*)(d_qkvw + dst);
            hp[0] = h[0]; hp[1] = h[1];
            return;
        }
        u -= QKV_U;
        if (u < GW_U) {
            float4 src = ((const float4*)g_w)[u];
            __half2 h[2]; cvt4h(src, h);
            ((__half2*)d_gw)[2 * u] = h[0]; ((__half2*)d_gw)[2 * u + 1] = h[1];
            return;
        }
        u -= GW_U;
        if (u < OW_U) {
            float4 src = ((const float4*)o_w)[u];
            __nv_bfloat162 h[2], l[2]; split4b(src, h, l);
            ((__nv_bfloat162*)d_ow_hi)[2 * u] = h[0]; ((__nv_bfloat162*)d_ow_hi)[2 * u + 1] = h[1];
            ((__nv_bfloat162*)d_ow_lo)[2 * u] = l[0]; ((__nv_bfloat162*)d_ow_lo)[2 * u + 1] = l[1];
            return;
        }
        u -= OW_U;
        {
            float4 src = ((const float4*)hidden)[u];
            __half2 h[2], l[2]; split4h(src, h, l);
            ((__half2*)d_hid_hi)[2 * u] = h[0]; ((__half2*)d_hid_hi)[2 * u + 1] = h[1];
            ((__half2*)d_hid_lo)[2 * u] = l[0]; ((__half2*)d_hid_lo)[2 * u + 1] = l[1];
        }
        return;
    }
    blk -= PACK_B;
    if (blk < ZERO_B) {
        outz[blk * 256 + tid] = make_float4(0.f, 0.f, 0.f, 0.f);
        return;
    }
    // router: one block per token
    int s = blk - ZERO_B;
    float acc[ENUM];
#pragma unroll
    for (int e = 0; e < ENUM; e++) acc[e] = 0.f;
    const float* xr = hidden + (size_t)s * DDIM;
    for (int d = tid; d < DDIM; d += 256) {
        float x = xr[d];
        const float* w = gate_w + (size_t)d * ENUM;
#pragma unroll
        for (int e = 0; e < ENUM; e++) acc[e] += x * w[e];
    }
    __shared__ float red[ENUM][256];
#pragma unroll
    for (int e = 0; e < ENUM; e++) red[e][tid] = acc[e];
    __syncthreads();
    for (int st = 128; st > 0; st >>= 1) {
        if (tid < st) {
#pragma unroll
            for (int e = 0; e < ENUM; e++) red[e][tid] += red[e][tid + st];
        }
        __syncthreads();
    }
    if (tid == 0) {
        float l[ENUM], mx = -1e30f;
#pragma unroll
        for (int e = 0; e < ENUM; e++) { l[e] = red[e][0]; mx = fmaxf(mx, l[e]); }
        float p[ENUM], sum = 0.f;
#pragma unroll
        for (int e = 0; e < ENUM; e++) { p[e] = expf(l[e] - mx); sum += p[e]; }
#pragma unroll
        for (int e = 0; e < ENUM; e++) p[e] /= sum;
        int i0 = 0;
#pragma unroll
        for (int e = 1; e < ENUM; e++) if (p[e] > p[i0]) i0 = e;
        int i1 = -1;
#pragma unroll
        for (int e = 0; e < ENUM; e++)
            if (e != i0 && (i1 < 0 || p[e] > p[i1])) i1 = e;
        float r0 = p[i0], r1 = p[i1], rs = r0 + r1;
        d_sel[2 * s] = i0;  d_sel[2 * s + 1] = i1;
        d_rw[2 * s] = r0 / rs;  d_rw[2 * s + 1] = r1 / rs;
    }
}

// ---------------- fp16 2-term GEMM core (qkv + gate, 4-stage) ------------------
#define A2_BYTES 8192
#define STAGE2_BYTES 24576
#define NST2 4
#define GEMM2_SMEM (NST2*STAGE2_BYTES)

__device__ __forceinline__ void gemm_core2(
    const __half* __restrict__ Ahi, const __half* __restrict__ Alo,
    const __half* __restrict__ B,
    float* __restrict__ C, int mlim, int N, int K, int lda, int row0, int col0,
    __half* smbuf) {
    uint32_t sbase = (uint32_t)__cvta_generic_to_shared(smbuf);
    int t = threadIdx.x;

    int arow = t >> 1, ac0 = (t & 1) * 2;
    int brow = t >> 3, bc0 = (t & 7) * 2;
    uint32_t aswr = ((uint32_t)(arow >> 1)) & 3u;
    uint32_t bswr = (uint32_t)(brow & 7);
    const __half* gAh = Ahi + (size_t)(row0 + arow) * lda;
    const __half* gAl = Alo + (size_t)(row0 + arow) * lda;
    const __half* gB  = B + (size_t)brow * N + col0;
    uint32_t aoff0 = (uint32_t)(arow * 64) + (((uint32_t)ac0 ^ aswr) * 16);
    uint32_t aoff1 = (uint32_t)(arow * 64) + ((((uint32_t)ac0 + 1u) ^ aswr) * 16);
    uint32_t boff0 = (uint32_t)(brow * 256) + (((uint32_t)bc0 ^ bswr) * 16);
    uint32_t boff1 = (uint32_t)(brow * 256) + ((((uint32_t)bc0 + 1u) ^ bswr) * 16);

    int lane = t & 31, wid = t >> 5;
    int wm = (wid >> 2) * 64, wn = (wid & 3) * 32;
    int lr = lane & 15;
    uint32_t swA = ((uint32_t)(lr >> 1)) & 3u;
    uint32_t achb = (uint32_t)(lane >> 4);
    uint32_t arowb = (uint32_t)((wm + lr) * 64);
    int blr = lane & 7, bgp = lane >> 3;
    uint32_t cbB = (uint32_t)((wid & 3) * 4 + (bgp >> 1));
    uint32_t brb = (uint32_t)(blr + (bgp & 1) * 8);

    float acc[4][4][4];
#pragma unroll
    for (int mi = 0; mi < 4; mi++)
#pragma unroll
        for (int ni = 0; ni < 4; ni++)
#pragma unroll
            for (int j = 0; j < 4; j++) acc[mi][ni][j] = 0.f;

    int KT = K / 32;

    auto load_stage = [&](int ktl) {
        int k0 = ktl * 32;
        uint32_t so = sbase + (uint32_t)((ktl % NST2) * STAGE2_BYTES);
        cpa16(so + aoff0, gAh + k0 + ac0 * 8);
        cpa16(so + aoff1, gAh + k0 + ac0 * 8 + 8);
        cpa16(so + A2_BYTES + aoff0, gAl + k0 + ac0 * 8);
        cpa16(so + A2_BYTES + aoff1, gAl + k0 + ac0 * 8 + 8);
        cpa16(so + 2 * A2_BYTES + boff0, gB + (size_t)k0 * N + bc0 * 8);
        cpa16(so + 2 * A2_BYTES + boff1, gB + (size_t)k0 * N + bc0 * 8 + 8);
        asm volatile("cp.async.commit_group;");
    };

    load_stage(0);
    if (KT > 1) load_stage(1);
    if (KT > 2) load_stage(2);

    for (int kt = 0; kt < KT; kt++) {
        if (kt + 2 < KT) {
            asm volatile("cp.async.wait_group 2;");
        } else if (kt + 1 < KT) {
            asm volatile("cp.async.wait_group 1;");
        } else {
            asm volatile("cp.async.wait_group 0;");
        }
        __syncthreads();
        if (kt + 3 < KT) load_stage(kt + 3);

        uint32_t s0 = sbase + (uint32_t)((kt % NST2) * STAGE2_BYTES);
        uint32_t sAh = s0;
        uint32_t sAl = s0 + A2_BYTES;
        uint32_t sB  = s0 + 2 * A2_BYTES;

#pragma unroll
        for (int ks = 0; ks < 2; ks++) {
            uint32_t rB = brb + (uint32_t)(ks * 16);
            uint32_t bo0 = rB * 256 + ((cbB ^ (uint32_t)blr) * 16);
            uint32_t bo1 = rB * 256 + (((cbB + 2u) ^ (uint32_t)blr) * 16);
            uint32_t ach = achb + (uint32_t)(ks * 2);
            uint32_t ao = arowb + ((ach ^ swA) * 16);

            uint32_t bh[8], af[16];
            ldm_x4t(bh + 0, sB + bo0);
            ldm_x4t(bh + 4, sB + bo1);
#pragma unroll
            for (int mi = 0; mi < 4; mi++)
                ldm_x4(af + mi * 4, sAh + ao + (uint32_t)(mi * 1024));
#pragma unroll
            for (int mi = 0; mi < 4; mi++)
#pragma unroll
                for (int ni = 0; ni < 4; ni++)
                    mma_f16(acc[mi][ni], af + mi * 4, bh + (ni >> 1) * 4 + (ni & 1) * 2);
#pragma unroll
            for (int mi = 0; mi < 4; mi++)
                ldm_x4(af + mi * 4, sAl + ao + (uint32_t)(mi * 1024));
#pragma unroll
            for (int mi = 0; mi < 4; mi++)
#pragma unroll
                for (int ni = 0; ni < 4; ni++)
                    mma_f16(acc[mi][ni], af + mi * 4, bh + (ni >> 1) * 4 + (ni & 1) * 2);
        }
    }

    int gr = lane >> 2, gc = (lane & 3) * 2;
#pragma unroll
    for (int mi = 0; mi < 4; mi++) {
        int r = row0 + wm + mi * 16 + gr;
#pragma unroll
        for (int ni = 0; ni < 4; ni++) {
            float* Cp = C + (size_t)r * N + col0 + wn + ni * 8 + gc;
            if (r < mlim) {
                Cp[0] = acc[mi][ni][0];
                Cp[1] = acc[mi][ni][1];
            }
            if (r + 8 < mlim) {
                float* Cq = Cp + (size_t)8 * N;
                Cq[0] = acc[mi][ni][2];
                Cq[1] = acc[mi][ni][3];
            }
        }
    }
}

// merged qkv (z=0..7) + gate (z=8) GEMM launch (fp16 2-term)
__global__ __launch_bounds__(256, 2)
void gemm_qkv_gate(const __half* __restrict__ xgh, const __half* __restrict__ xgl,
                   const __half* __restrict__ qkvw, float* __restrict__ qkvpre,
                   const __half* __restrict__ hih, const __half* __restrict__ hil,
                   const __half* __restrict__ gw, float* __restrict__ gg) {
    extern __shared__ __half smbuf2[];
    int z = blockIdx.z;
    int row0 = blockIdx.y * 128;
    int col0 = blockIdx.x * 128;
    if (z < ENUM) {
        int mlim = d_m[z];
        if (row0 >= mlim) return;
        gemm_core2(xgh + (size_t)z * CAP * DDIM, xgl + (size_t)z * CAP * DDIM,
                   qkvw + (size_t)z * DDIM * QKVP,
                   qkvpre + (size_t)z * CAP * QKVP, mlim, QKVP, DDIM, DDIM,
                   row0, col0, smbuf2);
    } else {
        if (col0 >= VDIM) return;
        gemm_core2(hih, hil, gw, gg, SLEN, VDIM, DDIM, DDIM, row0, col0, smbuf2);
    }
}

// ---------------- bf16 3-term GEMM core (output GEMM, atomic) ------------------
#define A_BYTES 8192
#define B_BYTES 8192
#define STAGE_BYTES 32768
#define GEMM_SMEM (3*STAGE_BYTES)

__device__ __forceinline__ void gemm_core3(
    const __nv_bfloat16* __restrict__ Ahi, const __nv_bfloat16* __restrict__ Alo,
    const __nv_bfloat16* __restrict__ Bhi, const __nv_bfloat16* __restrict__ Blo,
    float* __restrict__ C, int mlim, int N, int K, int lda, int row0, int col0,
    __nv_bfloat16* smbuf) {
    uint32_t sbase = (uint32_t)__cvta_generic_to_shared(smbuf);
    int t = threadIdx.x;

    int arow = t >> 1, ac0 = (t & 1) * 2;
    int brow = t >> 3, bc0 = (t & 7) * 2;
    uint32_t aswr = ((uint32_t)(arow >> 1)) & 3u;
    uint32_t bswr = (uint32_t)(brow & 7);
    const __nv_bfloat16* gAh = Ahi + (size_t)(row0 + arow) * lda;
    const __nv_bfloat16* gAl = Alo + (size_t)(row0 + arow) * lda;
    const __nv_bfloat16* gBh = Bhi + (size_t)brow * N + col0;
    const __nv_bfloat16* gBl = Blo + (size_t)brow * N + col0;
    uint32_t aoff0 = (uint32_t)(arow * 64) + (((uint32_t)ac0 ^ aswr) * 16);
    uint32_t aoff1 = (uint32_t)(arow * 64) + ((((uint32_t)ac0 + 1u) ^ aswr) * 16);
    uint32_t boff0 = (uint32_t)(brow * 256) + (((uint32_t)bc0 ^ bswr) * 16);
    uint32_t boff1 = (uint32_t)(brow * 256) + ((((uint32_t)bc0 + 1u) ^ bswr) * 16);

    int lane = t & 31, wid = t >> 5;
    int wm = (wid >> 2) * 64, wn = (wid & 3) * 32;
    int lr = lane & 15;
    uint32_t swA = ((uint32_t)(lr >> 1)) & 3u;
    uint32_t achb = (uint32_t)(lane >> 4);
    uint32_t arowb = (uint32_t)((wm + lr) * 64);
    int blr = lane & 7, bgp = lane >> 3;
    uint32_t cbB = (uint32_t)((wid & 3) * 4 + (bgp >> 1));
    uint32_t brb = (uint32_t)(blr + (bgp & 1) * 8);

    float acc[4][4][4];
#pragma unroll
    for (int mi = 0; mi < 4; mi++)
#pragma unroll
        for (int ni = 0; ni < 4; ni++)
#pragma unroll
            for (int j = 0; j < 4; j++) acc[mi][ni][j] = 0.f;

    int KT = K / 32;

    auto load_stage = [&](int ktl) {
        int k0 = ktl * 32;
        uint32_t so = sbase + (uint32_t)((ktl % 3) * STAGE_BYTES);
        cpa16(so + aoff0, gAh + k0 + ac0 * 8);
        cpa16(so + aoff1, gAh + k0 + ac0 * 8 + 8);
        cpa16(so + A_BYTES + aoff0, gAl + k0 + ac0 * 8);
        cpa16(so + A_BYTES + aoff1, gAl + k0 + ac0 * 8 + 8);
        cpa16(so + 2 * A_BYTES + boff0, gBh + (size_t)k0 * N + bc0 * 8);
        cpa16(so + 2 * A_BYTES + boff1, gBh + (size_t)k0 * N + bc0 * 8 + 8);
        cpa16(so + 2 * A_BYTES + B_BYTES + boff0, gBl + (size_t)k0 * N + bc0 * 8);
        cpa16(so + 2 * A_BYTES + B_BYTES + boff1, gBl + (size_t)k0 * N + bc0 * 8 + 8);
        asm volatile("cp.async.commit_group;");
    };

    load_stage(0);
    if (KT > 1) load_stage(1);

    for (int kt = 0; kt < KT; kt++) {
        if (kt + 1 < KT) {
            asm volatile("cp.async.wait_group 1;");
        } else {
            asm volatile("cp.async.wait_group 0;");
        }
        __syncthreads();
        if (kt + 2 < KT) load_stage(kt + 2);

        uint32_t s0 = sbase + (uint32_t)((kt % 3) * STAGE_BYTES);
        uint32_t sAh = s0;
        uint32_t sAl = s0 + A_BYTES;
        uint32_t sBh = s0 + 2 * A_BYTES;
        uint32_t sBl = s0 + 2 * A_BYTES + B_BYTES;

#pragma unroll
        for (int ks = 0; ks < 2; ks++) {
            uint32_t rB = brb + (uint32_t)(ks * 16);
            uint32_t bo0 = rB * 256 + ((cbB ^ (uint32_t)blr) * 16);
            uint32_t bo1 = rB * 256 + (((cbB + 2u) ^ (uint32_t)blr) * 16);
            uint32_t ach = achb + (uint32_t)(ks * 2);
            uint32_t ao = arowb + ((ach ^ swA) * 16);

            uint32_t bh[8], bl2[8], af[16];
            ldm_x4t(bh + 0, sBh + bo0);
            ldm_x4t(bh + 4, sBh + bo1);
            ldm_x4t(bl2 + 0, sBl + bo0);
            ldm_x4t(bl2 + 4, sBl + bo1);
#pragma unroll
            for (int mi = 0; mi < 4; mi++)
                ldm_x4(af + mi * 4, sAh + ao + (uint32_t)(mi * 1024));
#pragma unroll
            for (int mi = 0; mi < 4; mi++)
#pragma unroll
                for (int ni = 0; ni < 4; ni++)
                    mma_bf16(acc[mi][ni], af + mi * 4, bh + (ni >> 1) * 4 + (ni & 1) * 2);
#pragma unroll
            for (int mi = 0; mi < 4; mi++)
#pragma unroll
                for (int ni = 0; ni < 4; ni++)
                    mma_bf16(acc[mi][ni], af + mi * 4, bl2 + (ni >> 1) * 4 + (ni & 1) * 2);
#pragma unroll
            for (int mi = 0; mi < 4; mi++)
                ldm_x4(af + mi * 4, sAl + ao + (uint32_t)(mi * 1024));
#pragma unroll
            for (int mi = 0; mi < 4; mi++)
#pragma unroll
                for (int ni = 0; ni < 4; ni++)
                    mma_bf16(acc[mi][ni], af + mi * 4, bh + (ni >> 1) * 4 + (ni & 1) * 2);
        }
    }

    int gr = lane >> 2, gc = (lane & 3) * 2;
#pragma unroll
    for (int mi = 0; mi < 4; mi++) {
        int r = row0 + wm + mi * 16 + gr;
#pragma unroll
        for (int ni = 0; ni < 4; ni++) {
            float* Cp = C + (size_t)r * N + col0 + wn + ni * 8 + gc;
            if (r < mlim) {
                atomicAdd(Cp, acc[mi][ni][0]);
                atomicAdd(Cp + 1, acc[mi][ni][1]);
            }
            if (r + 8 < mlim) {
                float* Cq = Cp + (size_t)8 * N;
                atomicAdd(Cq, acc[mi][ni][2]);
                atomicAdd(Cq + 1, acc[mi][ni][3]);
            }
        }
    }
}

// split-K output GEMM
__global__ __launch_bounds__(256, 2)
void gemm_out_splitk(const __nv_bfloat16* __restrict__ Ahi, const __nv_bfloat16* __restrict__ Alo,
                     const __nv_bfloat16* __restrict__ Bhi, const __nv_bfloat16* __restrict__ Blo,
                     float* __restrict__ C) {
    extern __shared__ __nv_bfloat16 smbuf[];
    int z = blockIdx.z;
    int row0 = blockIdx.y * 128;
    int col0 = blockIdx.x * 128;
    int kHalf = VDIM / 2;
    gemm_core3(Ahi + (size_t)z * kHalf, Alo + (size_t)z * kHalf,
               Bhi + (size_t)z * kHalf * DDIM, Blo + (size_t)z * kHalf * DDIM,
               C, SLEN, DDIM, kHalf, VDIM, row0, col0, smbuf);
}

// -------------- dispatch: parallel warp-per-expert ballot scan ----------------
__global__ void dispatch_kernel() {
    int e = threadIdx.x >> 5;
    int lane = threadIdx.x & 31;
    int cnt = 0;
    for (int i = lane; i < SLEN * 2; i += 32) cnt += (d_sel[i] == e);
#pragma unroll
    for (int o = 16; o; o >>= 1) cnt += __shfl_xor_sync(0xffffffffu, cnt, o);
    int drop = cnt > CAP ? cnt - CAP : 0;
    if (lane == 0) d_m[e] = cnt - drop;
    int base = 0;
    for (int i0 = 0; i0 < SLEN * 2; i0 += 32) {
        int i = i0 + lane;
        bool hit = (d_sel[i] == e);
        unsigned mask = __ballot_sync(0xffffffffu, hit);
        if (hit) {
            int r = base + __popc(mask & ((1u << lane) - 1u));
            if (r >= drop) {
                int j = r - drop;
                d_tok[e * CAP + j] = i >> 1;
                d_pos[i] = e * CAP + j;
            } else {
                d_pos[i] = -1;
            }
        }
        base += __popc(mask);
    }
}

// -------------- gather + fp16 hi/lo split of activations ----------------------
__global__ void gather_split_kernel(const float* __restrict__ hidden) {
    int row = blockIdx.x;
    int e = row >> 10, t = row & 1023;
    if (t >= d_m[e]) return;
    const float4* src = (const float4*)(hidden + (size_t)d_tok[row] * DDIM);
    __half2* hi = (__half2*)(d_xg_hi + (size_t)row * DDIM);
    __half2* lo = (__half2*)(d_xg_lo + (size_t)row * DDIM);
    for (int i = threadIdx.x; i < DDIM / 4; i += 256) {
        float4 v = src[i];
        __half2 h[2], l[2];
        split4h(v, h, l);
        hi[2 * i] = h[0]; hi[2 * i + 1] = h[1];
        lo[2 * i] = l[0]; lo[2 * i + 1] = l[1];
    }
}

// -------------- conv + bg: warp-per-row, shuffle-only norm ---------------------
// grid (NROW/8, 25): y<6 q, y<12 k, y<24 v-chunk, y==24 beta/g
__global__ void conv_all_kernel(const float* __restrict__ pre,
                                const float* __restrict__ qcw,
                                const float* __restrict__ kcw,
                                const float* __restrict__ vcw,
                                const float* __restrict__ A_log,
                                const float* __restrict__ dt_bias) {
    int y = blockIdx.y;
    int warp = threadIdx.x >> 5, lane = threadIdx.x & 31;
    int row = blockIdx.x * 8 + warp;
    int e = row >> 10, t = row & 1023;
    if (t >= d_m[e]) return;

    if (y < 12) {
        int h = (y < 6) ? y : (y - 6);
        int preOff = (y < 6) ? 0 : KDIM;
        float scale = (y < 6) ? 0.0625f : 1.0f;
        const float* cw = (y < 6) ? qcw : kcw;
        float* out = (y < 6) ? d_qn : d_kn;
        int ch0 = h * DKC + lane * 8;
        float cwr[4][8];
#pragma unroll
        for (int c = 0; c < 8; c++) {
            float4 w = *(const float4*)(cw + (size_t)(ch0 + c) * 4);
            cwr[0][c] = w.x; cwr[1][c] = w.y; cwr[2][c] = w.z; cwr[3][c] = w.w;
        }
        float acc[8];
#pragma unroll
        for (int c = 0; c < 8; c++) acc[c] = 0.f;
#pragma unroll
        for (int j = 0; j < 4; j++) {
            int tt = t - 3 + j;
            if (tt >= 0) {
                const float* p = pre + (size_t)(row - 3 + j) * QKVP + preOff + ch0;
                float4 a = *(const float4*)p;
                float4 b = *(const float4*)(p + 4);
                acc[0] += cwr[j][0] * a.x; acc[1] += cwr[j][1] * a.y;
                acc[2] += cwr[j][2] * a.z; acc[3] += cwr[j][3] * a.w;
                acc[4] += cwr[j][4] * b.x; acc[5] += cwr[j][5] * b.y;
                acc[6] += cwr[j][6] * b.z; acc[7] += cwr[j][7] * b.w;
            }
        }
        float ss = 0.f;
#pragma unroll
        for (int c = 0; c < 8; c++) {
            acc[c] = acc[c] / (1.f + expf(-acc[c]));
            ss += acc[c] * acc[c];
        }
#pragma unroll
        for (int o = 16; o; o >>= 1) ss += __shfl_xor_sync(0xffffffffu, ss, o);
        float inv = rsqrtf(ss + 1e-6f) * scale;
        float* op = out + (size_t)row * KDIM + ch0;
        *(float4*)op = make_float4(acc[0] * inv, acc[1] * inv, acc[2] * inv, acc[3] * inv);
        *(float4*)(op + 4) = make_float4(acc[4] * inv, acc[5] * inv, acc[6] * inv, acc[7] * inv);
    } else if (y < 24) {
        int ch0 = (y - 12) * 256 + lane * 8;
        float cwr[4][8];
#pragma unroll
        for (int c = 0; c < 8; c++) {
            float4 w = *(const float4*)(vcw + (size_t)(ch0 + c) * 4);
            cwr[0][c] = w.x; cwr[1][c] = w.y; cwr[2][c] = w.z; cwr[3][c] = w.w;
        }
        float acc[8];
#pragma unroll
        for (int c = 0; c < 8; c++) acc[c] = 0.f;
#pragma unroll
        for (int j = 0; j < 4; j++) {
            int tt = t - 3 + j;
            if (tt >= 0) {
                const float* p = pre + (size_t)(row - 3 + j) * QKVP + 2 * KDIM + ch0;
                float4 a = *(const float4*)p;
                float4 b = *(const float4*)(p + 4);
                acc[0] += cwr[j][0] * a.x; acc[1] += cwr[j][1] * a.y;
                acc[2] += cwr[j][2] * a.z; acc[3] += cwr[j][3] * a.w;
                acc[4] += cwr[j][4] * b.x; acc[5] += cwr[j][5] * b.y;
                acc[6] += cwr[j][6] * b.z; acc[7] += cwr[j][7] * b.w;
            }
        }
        float* op = d_vn + (size_t)row * VDIM + ch0;
        float o0[8];
#pragma unroll
        for (int c = 0; c < 8; c++) o0[c] = acc[c] / (1.f + expf(-acc[c]));
        *(float4*)op = make_float4(o0[0], o0[1], o0[2], o0[3]);
        *(float4*)(op + 4) = make_float4(o0[4], o0[5], o0[6], o0[7]);
    } else {
        if (lane < HNUM) {
            float bl = pre[(size_t)row * QKVP + QKVO + lane];
            float al = pre[(size_t)row * QKVP + QKVO + HNUM + lane];
            d_beta[row * HNUM + lane] = 1.f / (1.f + expf(-bl));
            float xx = al + dt_bias[lane];
            float sp = xx > 20.f ? xx : log1pf(expf(xx));
            d_g[row * HNUM + lane] = -expf(A_log[lane]) * sp;
        }
    }
}

// -------------- gated delta-rule recurrence (conflict-free strided) -----------
__global__ void recur_kernel() {
    int vc = blockIdx.x;
    int h = blockIdx.y;
    int e = blockIdx.z;
    int m = d_m[e];
    __shared__ float S[32 * 256];
    __shared__ float su[32], sw[32], sd[32];
    int tid = threadIdx.x, warp = tid >> 5, lane = tid & 31;
    int v0 = warp * 4;
    for (int i = lane; i < 4 * 256; i += 32) S[v0 * 256 + i] = 0.f;
    if (lane < 4) { su[v0 + lane] = 0.f; sw[v0 + lane] = 0.f; }
    __syncwarp();
    if (m == 0) return;

    const float* kb = d_kn + (size_t)(e * CAP) * KDIM + h * DKC;
    const float* qb = d_qn + (size_t)(e * CAP) * KDIM + h * DKC;
    const float* vb = d_vn + (size_t)(e * CAP) * VDIM + h * DVC + vc * 32;
    const float* bb = d_beta + (size_t)(e * CAP) * HNUM + h;
    const float* gb = d_g + (size_t)(e * CAP) * HNUM + h;
    float* ob = d_o + (size_t)(e * CAP) * VDIM + h * DVC + vc * 32;

    float kc[8], qc[8];
#pragma unroll
    for (int j = 0; j < 8; j++) { kc[j] = kb[lane + 32 * j]; qc[j] = qb[lane + 32 * j]; }
    float beta = bb[0];
    float gv = gb[0];
    float vv = (lane < 4) ? vb[v0 + lane] : 0.f;

    for (int t = 0; t < m; t++) {
        float eg = expf(gv);
        float qk = 0.f;
#pragma unroll
        for (int j = 0; j < 8; j++) qk += kc[j] * qc[j];
#pragma unroll
        for (int o = 16; o; o >>= 1) qk += __shfl_xor_sync(0xffffffffu, qk, o);

        if (lane < 4) {
            int v = v0 + lane;
            float dd = beta * (vv - eg * su[v]);
            ob[(size_t)t * VDIM + v] = eg * sw[v] + qk * dd;
            sd[v] = dd;
        }
        __syncwarp();

        float kn2[8], qn2[8];
        float beta_n = 0.f, g_n = 0.f, vv_n = 0.f;
        if (t + 1 < m) {
            const float* kr = kb + (size_t)(t + 1) * KDIM;
            const float* qr = qb + (size_t)(t + 1) * KDIM;
#pragma unroll
            for (int j = 0; j < 8; j++) { kn2[j] = kr[lane + 32 * j]; qn2[j] = qr[lane + 32 * j]; }
            beta_n = bb[(size_t)(t + 1) * HNUM];
            g_n = gb[(size_t)(t + 1) * HNUM];
            if (lane < 4) vv_n = vb[(size_t)(t + 1) * VDIM + v0 + lane];
        } else {
#pragma unroll
            for (int j = 0; j < 8; j++) { kn2[j] = 0.f; qn2[j] = 0.f; }
        }

#pragma unroll
        for (int vi = 0; vi < 4; vi++) {
            int v = v0 + vi;
            float dd = sd[v];
            float un = 0.f, wn = 0.f;
            float* Sr = &S[v * 256];
#pragma unroll
            for (int j = 0; j < 8; j++) {
                float s2 = Sr[lane + 32 * j];
                s2 = eg * s2 + kc[j] * dd;
                Sr[lane + 32 * j] = s2;
                un += kn2[j] * s2;
                wn += qn2[j] * s2;
            }
#pragma unroll
            for (int o = 16; o; o >>= 1) {
                un += __shfl_xor_sync(0xffffffffu, un, o);
                wn += __shfl_xor_sync(0xffffffffu, wn, o);
            }
            if (lane == 0) { su[v] = un; sw[v] = wn; }
        }
        __syncwarp();
#pragma unroll
        for (int j = 0; j < 8; j++) { kc[j] = kn2[j]; qc[j] = qn2[j]; }
        beta = beta_n; gv = g_n; vv = vv_n;
    }
}

// -------------- combine + gated RMSNorm + bf16 hi/lo (fused) ------------------
__global__ void combine_kernel(const float* __restrict__ norm_w) {
    int s = blockIdx.x, h = blockIdx.y, tid = threadIdx.x;
    int p0 = d_pos[2 * s], p1 = d_pos[2 * s + 1];
    float r0 = d_rw[2 * s], r1 = d_rw[2 * s + 1];
    float acc[2];
    float ss = 0.f;
#pragma unroll
    for (int i = 0; i < 2; i++) {
        int v = tid + i * 256;
        float a = 0.f;
        if (p0 >= 0) a += r0 * d_o[(size_t)p0 * VDIM + h * DVC + v];
        if (p1 >= 0) a += r1 * d_o[(size_t)p1 * VDIM + h * DVC + v];
        acc[i] = a;
        ss += a * a;
    }
    __shared__ float red[256];
    red[tid] = ss;
    __syncthreads();
    for (int st = 128; st > 0; st >>= 1) {
        if (tid < st) red[tid] += red[tid + st];
        __syncthreads();
    }
    float inv = rsqrtf(red[0] / (float)DVC + 1e-5f);
#pragma unroll
    for (int i = 0; i < 2; i++) {
        int v = tid + i * 256;
        float gg = d_gg[(size_t)s * VDIM + h * DVC + v];
        float sg = gg / (1.f + expf(-gg));
        float val = acc[i] * inv * norm_w[v] * sg;
        __nv_bfloat16 hb = __float2bfloat16(val);
        __nv_bfloat16 lb = __float2bfloat16(val - __bfloat162float(hb));
        size_t idx = (size_t)s * VDIM + h * DVC + v;
        d_pre_hi[idx] = hb;
        d_pre_lo[idx] = lb;
    }
}

// ----------------------------- launch -----------------------------------------
extern "C" void kernel_launch(void* const* d_in, const int* in_sizes, int n_in,
                              void* d_out, int out_size) {
    const float* hidden  = (const float*)d_in[0];
    const float* q_w     = (const float*)d_in[1];
    const float* gate_w  = (const float*)d_in[2];
    const float* k_w     = (const float*)d_in[3];
    const float* v_w     = (const float*)d_in[4];
    const float* b_w     = (const float*)d_in[5];
    const float* a_w     = (const float*)d_in[6];
    const float* A_log   = (const float*)d_in[7];
    const float* dt_bias = (const float*)d_in[8];
    const float* qcw     = (const float*)d_in[9];
    const float* kcw     = (const float*)d_in[10];
    const float* vcw     = (const float*)d_in[11];
    const float* g_w     = (const float*)d_in[12];
    const float* norm_w  = (const float*)d_in[13];
    const float* o_w     = (const float*)d_in[14];

    float* qkvpre = 0; float* gg = 0;
    cudaGetSymbolAddress((void**)&qkvpre, d_qkvpre);
    cudaGetSymbolAddress((void**)&gg, d_gg);

    __half* xgh = 0; __half* xgl = 0; __half* qkvw = 0; __half* gw = 0;
    __half* hih = 0; __half* hil = 0;
    __nv_bfloat16* owh = 0; __nv_bfloat16* owl = 0;
    __nv_bfloat16* prh = 0; __nv_bfloat16* prl = 0;
    cudaGetSymbolAddress((void**)&xgh, d_xg_hi);
    cudaGetSymbolAddress((void**)&xgl, d_xg_lo);
    cudaGetSymbolAddress((void**)&qkvw, d_qkvw);
    cudaGetSymbolAddress((void**)&gw, d_gw);
    cudaGetSymbolAddress((void**)&hih, d_hid_hi);
    cudaGetSymbolAddress((void**)&hil, d_hid_lo);
    cudaGetSymbolAddress((void**)&owh, d_ow_hi);
    cudaGetSymbolAddress((void**)&owl, d_ow_lo);
    cudaGetSymbolAddress((void**)&prh, d_pre_hi);
    cudaGetSymbolAddress((void**)&prl, d_pre_lo);

    cudaFuncSetAttribute(gemm_qkv_gate, cudaFuncAttributeMaxDynamicSharedMemorySize, GEMM2_SMEM);
    cudaFuncSetAttribute(gemm_out_splitk, cudaFuncAttributeMaxDynamicSharedMemorySize, GEMM_SMEM);

    // 1: prep = pack weights + zero d_out + router
    prep_kernel<<<PREP_B, 256>>>(q_w, k_w, v_w, b_w, a_w, g_w, o_w, hidden, gate_w,
                                 (float4*)d_out);
    // 2: dispatch
    dispatch_kernel<<<1, 256>>>();
    // 3: gather + activation split
    gather_split_kernel<<<NROW, 256>>>(hidden);
    // 4: merged qkv (z<8) + gate (z=8) projections (fp16 2-term, 4-stage)
    gemm_qkv_gate<<<dim3(QKVP / 128, CAP / 128, ENUM + 1), 256, GEMM2_SMEM>>>(
        xgh, xgl, qkvw, qkvpre, hih, hil, gw, gg);
    // 5: conv + bg (warp-per-row)
    conv_all_kernel<<<dim3(NROW / 8, 25), 256>>>(qkvpre, qcw, kcw, vcw, A_log, dt_bias);
    // 6: recurrence
    recur_kernel<<<dim3(DVC / 32, HNUM, ENUM), 256>>>();
    // 7: combine + RMSNorm + bf16 split
    combine_kernel<<<dim3(SLEN, HNUM), 256>>>(norm_w);
    // 8: split-K output GEMM (bf16 3-term, atomic accumulate)
    gemm_out_splitk<<<dim3(DDIM / 128, SLEN / 128, 2), 256, GEMM_SMEM>>>(
        prh, prl, owh, owl, (float*)d_out);
}